// round 3
// baseline (speedup 1.0000x reference)
#include <cuda_runtime.h>

#define BB 4
#define FC 64
#define CIN1 128
#define NPIX 16384
#define DK 256
#define DV 512

__device__ float g_xup[BB*CIN1*NPIX];
__device__ float g_q[BB*DK*NPIX];
__device__ float g_k[BB*DK*NPIX];
__device__ float g_v[BB*DV*NPIX];
__device__ float g_ctxp[BB*8*8*2048];
__device__ float g_M[BB*8*2048];
__device__ float g_n1[BB*FC*NPIX];
__device__ float g_n2[BB*FC*NPIX];
__device__ float g_xa[BB*FC*NPIX];
__device__ float g_w1t[CIN1*9*FC];
__device__ float g_w2t[FC*9*FC];
__device__ float g_wmod[BB*3*FC];
__device__ float g_rgbpre[BB*3*NPIX];
__device__ float g_rgbup[BB*3*4*NPIX];

// ---------- bilinear 2x upsample (half-pixel, edge clamp) ----------
__global__ void up2_kernel(const float* __restrict__ in, float* __restrict__ out,
                           int C, int Hin, int Win) {
    int Ho = Hin * 2, Wo = Win * 2;
    long total = (long)BB * C * Ho * Wo;
    long i = (long)blockIdx.x * blockDim.x + threadIdx.x;
    if (i >= total) return;
    int ox = (int)(i % Wo); long r = i / Wo;
    int oy = (int)(r % Ho); r /= Ho;
    int c = (int)(r % C); int b = (int)(r / C);
    float sy = oy * 0.5f - 0.25f, sx = ox * 0.5f - 0.25f;
    int y0 = (int)floorf(sy), x0 = (int)floorf(sx);
    float wy = sy - (float)y0, wx = sx - (float)x0;
    int y0c = max(y0, 0), y1c = min(y0 + 1, Hin - 1);
    int x0c = max(x0, 0), x1c = min(x0 + 1, Win - 1);
    const float* p = in + ((long)b * C + c) * Hin * Win;
    float v00 = p[y0c * Win + x0c], v01 = p[y0c * Win + x1c];
    float v10 = p[y1c * Win + x0c], v11 = p[y1c * Win + x1c];
    out[i] = (1.f - wy) * ((1.f - wx) * v00 + wx * v01) + wy * ((1.f - wx) * v10 + wx * v11);
}

// ---------- demodulated conv weights (style = ones), transposed [ci][k][co] ----------
__global__ void weff_kernel(const float* __restrict__ w1, const float* __restrict__ w2) {
    int co = blockIdx.x;
    const float* w; float* wo; int len;
    if (co < 64) { w = w1 + (long)co * CIN1 * 9; wo = g_w1t; len = CIN1 * 9; }
    else { co -= 64; w = w2 + (long)co * FC * 9; wo = g_w2t; len = FC * 9; }
    __shared__ float red[256];
    float s = 0.f;
    for (int i = threadIdx.x; i < len; i += 256) { float v = w[i]; s += v * v; }
    red[threadIdx.x] = s; __syncthreads();
    for (int o = 128; o > 0; o >>= 1) { if (threadIdx.x < o) red[threadIdx.x] += red[threadIdx.x + o]; __syncthreads(); }
    float sc = 2.f * rsqrtf(4.f * red[0] + 1e-8f);
    for (int i = threadIdx.x; i < len; i += 256) wo[(long)i * 64 + co] = w[i] * sc;
}

// ---------- style -> modulated 1x1 rgb weights ----------
__global__ void style_kernel(const float* __restrict__ istyle, const float* __restrict__ sw,
                             const float* __restrict__ sb, const float* __restrict__ rgbw) {
    int f = threadIdx.x, b = blockIdx.x;
    float s = sb[f];
    for (int l = 0; l < 512; l++) s += istyle[b * 512 + l] * sw[f * 512 + l];
    s += 1.f;
    for (int co = 0; co < 3; co++) g_wmod[(b * 3 + co) * 64 + f] = rgbw[co * 64 + f] * s;
}

// ---------- QKV projection GEMM: 64-row slab x 128 pixels per block ----------
__global__ void __launch_bounds__(256) proj_kernel(
    const float* __restrict__ noise, const float* __restrict__ qw,
    const float* __restrict__ kw, const float* __restrict__ vw) {
    __shared__ float Ws[64][68];
    __shared__ float Xs[64][128];
    int nt = blockIdx.x, rt = blockIdx.y, b = blockIdx.z;
    int t = threadIdx.x, n0 = nt * 128;
    const float* wsrc; float* dst; float sc;
    const float SCALE = 0.42044820762685725f; // 32^-0.25
    if (rt < 4)      { wsrc = qw + rt * 64 * 64;       dst = g_q + ((long)b * DK + rt * 64) * NPIX;       sc = SCALE; }
    else if (rt < 8) { wsrc = kw + (rt - 4) * 64 * 64; dst = g_k + ((long)b * DK + (rt - 4) * 64) * NPIX; sc = SCALE; }
    else             { wsrc = vw + (rt - 8) * 64 * 64; dst = g_v + ((long)b * DV + (rt - 8) * 64) * NPIX; sc = 1.f; }
    { int r = t >> 2, q0 = (t & 3) * 16;
      const float4* s4 = (const float4*)(wsrc + r * 64 + q0);
      #pragma unroll
      for (int i = 0; i < 4; i++) *(float4*)&Ws[r][q0 + i * 4] = s4[i]; }
    #pragma unroll
    for (int i = 0; i < 8; i++) { int idx = t + i * 256; int c = idx >> 5, n4 = idx & 31;
      *(float4*)&Xs[c][n4 * 4] = *(const float4*)(noise + ((long)b * FC + c) * NPIX + n0 + n4 * 4); }
    __syncthreads();
    int rg = t >> 4, ng = t & 15;
    float acc[4][8];
    #pragma unroll
    for (int i = 0; i < 4; i++)
      #pragma unroll
      for (int j = 0; j < 8; j++) acc[i][j] = 0.f;
    #pragma unroll 8
    for (int k = 0; k < 64; k++) {
        float4 x0 = *(float4*)&Xs[k][ng * 4];
        float4 x1 = *(float4*)&Xs[k][64 + ng * 4];
        #pragma unroll
        for (int i = 0; i < 4; i++) {
            float w = Ws[rg * 4 + i][k];
            acc[i][0] += w * x0.x; acc[i][1] += w * x0.y; acc[i][2] += w * x0.z; acc[i][3] += w * x0.w;
            acc[i][4] += w * x1.x; acc[i][5] += w * x1.y; acc[i][6] += w * x1.z; acc[i][7] += w * x1.w;
        }
    }
    #pragma unroll
    for (int i = 0; i < 4; i++) {
        long base = (long)(rg * 4 + i) * NPIX + n0;
        *(float4*)(dst + base + ng * 4) = make_float4(acc[i][0] * sc, acc[i][1] * sc, acc[i][2] * sc, acc[i][3] * sc);
        *(float4*)(dst + base + 64 + ng * 4) = make_float4(acc[i][4] * sc, acc[i][5] * sc, acc[i][6] * sc, acc[i][7] * sc);
    }
}

// ---------- softmax over 16384 pixels per k row ----------
__global__ void ksoftmax_kernel() {
    extern __shared__ float buf[];
    __shared__ float red[256];
    int t = threadIdx.x;
    float* p = g_k + (long)blockIdx.x * NPIX;
    float mx = -1e30f;
    for (int i = t; i < NPIX; i += 256) { float v = p[i]; buf[i] = v; mx = fmaxf(mx, v); }
    red[t] = mx; __syncthreads();
    for (int o = 128; o > 0; o >>= 1) { if (t < o) red[t] = fmaxf(red[t], red[t + o]); __syncthreads(); }
    mx = red[0]; __syncthreads();
    float s = 0.f;
    for (int i = t; i < NPIX; i += 256) { float e = __expf(buf[i] - mx); buf[i] = e; s += e; }
    red[t] = s; __syncthreads();
    for (int o = 128; o > 0; o >>= 1) { if (t < o) red[t] += red[t + o]; __syncthreads(); }
    float inv = 1.f / red[0]; __syncthreads();
    for (int i = t; i < NPIX; i += 256) p[i] = buf[i] * inv;
}

// ---------- softmax over d=32 per (b,h,pixel) ----------
__global__ void qsoftmax_kernel() {
    long tid = (long)blockIdx.x * 256 + threadIdx.x;
    int n = (int)(tid % NPIX);
    int h = (int)((tid / NPIX) % 8);
    int b = (int)(tid / ((long)NPIX * 8));
    float* p = g_q + ((long)(b * DK + h * 32)) * NPIX + n;
    float v[32]; float mx = -1e30f;
    #pragma unroll
    for (int d = 0; d < 32; d++) { v[d] = p[(long)d * NPIX]; mx = fmaxf(mx, v[d]); }
    float s = 0.f;
    #pragma unroll
    for (int d = 0; d < 32; d++) { v[d] = __expf(v[d] - mx); s += v[d]; }
    float inv = 1.f / s;
    #pragma unroll
    for (int d = 0; d < 32; d++) p[(long)d * NPIX] = v[d] * inv;
}

// ---------- ctx partial: k[32,2048] @ v[64,2048]^T per (chunk,h,b) ----------
__global__ void __launch_bounds__(128) ctx_kernel() {
    int ch = blockIdx.x, h = blockIdx.y, b = blockIdx.z;
    __shared__ float ks[32][64];
    __shared__ float vs[64][68];
    int t = threadIdx.x;
    int dg = t >> 4, eg = t & 15;
    float acc[4][4];
    #pragma unroll
    for (int i = 0; i < 4; i++)
      #pragma unroll
      for (int j = 0; j < 4; j++) acc[i][j] = 0.f;
    const float* kbase = g_k + ((long)(b * DK + h * 32)) * NPIX + ch * 2048;
    const float* vbase = g_v + ((long)(b * DV + h * 64)) * NPIX + ch * 2048;
    for (int n0 = 0; n0 < 2048; n0 += 64) {
        __syncthreads();
        #pragma unroll
        for (int i = 0; i < 4; i++) { int idx = t + i * 128; int d = idx >> 4, n4 = idx & 15;
            *(float4*)&ks[d][n4 * 4] = *(const float4*)(kbase + (long)d * NPIX + n0 + n4 * 4); }
        #pragma unroll
        for (int i = 0; i < 8; i++) { int idx = t + i * 128; int e = idx >> 4, n4 = idx & 15;
            float4 vv = *(const float4*)(vbase + (long)e * NPIX + n0 + n4 * 4);
            vs[n4 * 4 + 0][e] = vv.x; vs[n4 * 4 + 1][e] = vv.y;
            vs[n4 * 4 + 2][e] = vv.z; vs[n4 * 4 + 3][e] = vv.w; }
        __syncthreads();
        #pragma unroll 8
        for (int n = 0; n < 64; n++) {
            float4 ve = *(float4*)&vs[n][eg * 4];
            #pragma unroll
            for (int i = 0; i < 4; i++) {
                float kd = ks[dg * 4 + i][n];
                acc[i][0] += kd * ve.x; acc[i][1] += kd * ve.y;
                acc[i][2] += kd * ve.z; acc[i][3] += kd * ve.w;
            }
        }
    }
    float* outp = g_ctxp + ((long)(b * 8 + h) * 8 + ch) * 2048;
    #pragma unroll
    for (int i = 0; i < 4; i++)
      #pragma unroll
      for (int j = 0; j < 4; j++)
        outp[(dg * 4 + i) * 64 + eg * 4 + j] = acc[i][j];
}

// ---------- reduce ctx chunks, fold with ow: M[d][c] = sum_e ctx[d][e]*ow[c][h*64+e] ----------
__global__ void __launch_bounds__(256) m_kernel(const float* __restrict__ ow) {
    int h = blockIdx.x & 7, b = blockIdx.x >> 3;
    __shared__ float ctx_s[2048];
    __shared__ float ow_s[64][65];
    int t = threadIdx.x;
    const float* cp = g_ctxp + (long)(b * 8 + h) * 8 * 2048;
    #pragma unroll
    for (int i = 0; i < 8; i++) {
        int idx = t + i * 256;
        float s = 0.f;
        #pragma unroll
        for (int ch = 0; ch < 8; ch++) s += cp[ch * 2048 + idx];
        ctx_s[idx] = s;
    }
    #pragma unroll
    for (int i = 0; i < 16; i++) {
        int idx = t + i * 256;
        int c = idx >> 6, e = idx & 63;
        ow_s[c][e] = ow[(long)c * DV + h * 64 + e];
    }
    __syncthreads();
    float* Mp = g_M + (long)(b * 8 + h) * 2048;
    #pragma unroll
    for (int i = 0; i < 8; i++) {
        int idx = t + i * 256;
        int d = idx >> 6, c = idx & 63;
        float s = 0.f;
        #pragma unroll 16
        for (int e = 0; e < 64; e++) s += ctx_s[d * 64 + e] * ow_s[c][e];
        Mp[idx] = s;
    }
}

// ---------- out projection + residual: nout = noise + ga*(q^T M + ob) ----------
__global__ void __launch_bounds__(256) outproj_kernel(
    const float* __restrict__ noise, const float* __restrict__ ob,
    const float* __restrict__ ga, float* __restrict__ nout) {
    int nt = blockIdx.x, b = blockIdx.y;
    __shared__ float qs[32][132];
    __shared__ float Ms[32][64];
    int t = threadIdx.x;
    int pg = t & 31, cg = t >> 5;
    int n0 = nt * 128;
    float acc[4][8];
    #pragma unroll
    for (int i = 0; i < 4; i++)
      #pragma unroll
      for (int j = 0; j < 8; j++) acc[i][j] = 0.f;
    for (int h = 0; h < 8; h++) {
        __syncthreads();
        #pragma unroll
        for (int i = 0; i < 4; i++) { int idx = t + i * 256; int d = idx >> 5, n4 = idx & 31;
            *(float4*)&qs[d][n4 * 4] =
                *(const float4*)(g_q + ((long)(b * DK + h * 32 + d)) * NPIX + n0 + n4 * 4); }
        #pragma unroll
        for (int i = 0; i < 2; i++) { int idx = t + i * 256; int d = idx >> 4, c4 = idx & 15;
            *(float4*)&Ms[d][c4 * 4] =
                *(const float4*)(g_M + ((long)(b * 8 + h)) * 2048 + d * 64 + c4 * 4); }
        __syncthreads();
        #pragma unroll 4
        for (int d = 0; d < 32; d++) {
            float4 q4 = *(float4*)&qs[d][pg * 4];
            float4 m0 = *(float4*)&Ms[d][cg * 8];
            float4 m1 = *(float4*)&Ms[d][cg * 8 + 4];
            float qv[4] = {q4.x, q4.y, q4.z, q4.w};
            float mv[8] = {m0.x, m0.y, m0.z, m0.w, m1.x, m1.y, m1.z, m1.w};
            #pragma unroll
            for (int i = 0; i < 4; i++)
              #pragma unroll
              for (int j = 0; j < 8; j++) acc[i][j] += qv[i] * mv[j];
        }
    }
    float gav = ga[0];
    #pragma unroll
    for (int j = 0; j < 8; j++) {
        int c = cg * 8 + j;
        float obv = ob[c];
        #pragma unroll
        for (int i = 0; i < 4; i++) {
            long off = ((long)(b * FC + c)) * NPIX + n0 + pg * 4 + i;
            nout[off] = noise[off] + gav * (acc[i][j] + obv);
        }
    }
}

// ---------- per-pixel FF: x += gf*(f2 @ lrelu(f1 @ x + b1) + b2), in place ----------
__global__ void __launch_bounds__(128) ff_kernel(
    const float* __restrict__ f1w, const float* __restrict__ f1b,
    const float* __restrict__ f2w, const float* __restrict__ f2b,
    const float* __restrict__ gf, float* __restrict__ xio) {
    extern __shared__ float sm[];
    float* f1s = sm;               // [128][64]
    float* f2s = sm + 8192;        // [128][68] transposed
    float* b1s = f2s + 128 * 68;
    float* b2s = b1s + 128;
    int t = threadIdx.x;
    for (int i = t; i < 8192; i += 128) f1s[i] = f1w[i];
    for (int i = t; i < 8192; i += 128) { int c = i >> 7, j = i & 127; f2s[j * 68 + c] = f2w[i]; }
    b1s[t] = f1b[t];
    if (t < 64) b2s[t] = f2b[t];
    __syncthreads();
    long base = (long)blockIdx.y * FC * NPIX + blockIdx.x * 128 + t;
    float xv[64], acc[64];
    #pragma unroll
    for (int c = 0; c < 64; c++) { xv[c] = xio[base + (long)c * NPIX]; acc[c] = 0.f; }
    #pragma unroll 2
    for (int j = 0; j < 128; j++) {
        float hv = b1s[j];
        const float4* w1 = (const float4*)(f1s + j * 64);
        #pragma unroll
        for (int c4 = 0; c4 < 16; c4++) {
            float4 w = w1[c4];
            hv += w.x * xv[c4 * 4] + w.y * xv[c4 * 4 + 1] + w.z * xv[c4 * 4 + 2] + w.w * xv[c4 * 4 + 3];
        }
        hv = hv > 0.f ? hv : 0.2f * hv;
        const float4* w2 = (const float4*)(f2s + j * 68);
        #pragma unroll
        for (int c4 = 0; c4 < 16; c4++) {
            float4 w = w2[c4];
            acc[c4 * 4] += w.x * hv; acc[c4 * 4 + 1] += w.y * hv;
            acc[c4 * 4 + 2] += w.z * hv; acc[c4 * 4 + 3] += w.w * hv;
        }
    }
    float g = gf[0];
    #pragma unroll
    for (int c = 0; c < 64; c++) xio[base + (long)c * NPIX] = xv[c] + g * (acc[c] + b2s[c]);
}

// ---------- direct 3x3 conv (same pad) + add + lrelu; weights [ci][k][co] ----------
template<int CIN>
__global__ void __launch_bounds__(256) conv3_kernel(
    const float* __restrict__ in, const float* __restrict__ wt,
    const float* __restrict__ nadd, float* __restrict__ out) {
    __shared__ float ws[8 * 9 * 64];
    __shared__ float ins[8][10][18];
    int t = threadIdx.x;
    int px = t & 127; int tx = px & 15, ty = px >> 4; int cg = t >> 7;
    int bx = blockIdx.x * 16, by = blockIdx.y * 8, b = blockIdx.z;
    float acc[32];
    #pragma unroll
    for (int i = 0; i < 32; i++) acc[i] = 0.f;
    for (int c0 = 0; c0 < CIN; c0 += 8) {
        __syncthreads();
        const float4* wsrc = (const float4*)(wt + (long)c0 * 9 * 64);
        float4* wdst = (float4*)ws;
        for (int i = t; i < 1152; i += 256) wdst[i] = wsrc[i];
        for (int i = t; i < 1440; i += 256) {
            int ci = i / 180, r = i % 180, y = r / 18, xx = r % 18;
            int gy = by + y - 1, gx = bx + xx - 1;
            float v = 0.f;
            if (gy >= 0 && gy < 128 && gx >= 0 && gx < 128)
                v = in[((long)(b * CIN + c0 + ci)) * NPIX + gy * 128 + gx];
            ins[ci][y][xx] = v;
        }
        __syncthreads();
        #pragma unroll
        for (int ci = 0; ci < 8; ci++)
          #pragma unroll
          for (int kk = 0; kk < 9; kk++) {
            float xv = ins[ci][ty + kk / 3][tx + kk % 3];
            const float4* wp = (const float4*)(ws + (ci * 9 + kk) * 64 + cg * 32);
            #pragma unroll
            for (int g = 0; g < 8; g++) {
                float4 w = wp[g];
                acc[g * 4] += w.x * xv; acc[g * 4 + 1] += w.y * xv;
                acc[g * 4 + 2] += w.z * xv; acc[g * 4 + 3] += w.w * xv;
            }
          }
    }
    long poff = (long)(by + ty) * 128 + bx + tx;
    #pragma unroll
    for (int i = 0; i < 32; i++) {
        int co = cg * 32 + i;
        long off = ((long)(b * 64 + co)) * NPIX + poff;
        float v = acc[i] + nadd[off];
        out[off] = v > 0.f ? v : 0.2f * v;
    }
}

// ---------- modulated 1x1 rgb conv + prev_rgb ----------
__global__ void rgb_kernel(const float* __restrict__ xin, const float* __restrict__ prev) {
    int n = blockIdx.x * 256 + threadIdx.x;
    int b = blockIdx.y;
    __shared__ float w[192];
    if (threadIdx.x < 192) w[threadIdx.x] = g_wmod[b * 192 + threadIdx.x];
    __syncthreads();
    float a0 = 0.f, a1 = 0.f, a2 = 0.f;
    for (int c = 0; c < 64; c++) {
        float xv = xin[((long)(b * 64 + c)) * NPIX + n];
        a0 += w[c] * xv; a1 += w[64 + c] * xv; a2 += w[128 + c] * xv;
    }
    g_rgbpre[((long)(b * 3 + 0)) * NPIX + n] = a0 + prev[((long)(b * 3 + 0)) * NPIX + n];
    g_rgbpre[((long)(b * 3 + 1)) * NPIX + n] = a1 + prev[((long)(b * 3 + 1)) * NPIX + n];
    g_rgbpre[((long)(b * 3 + 2)) * NPIX + n] = a2 + prev[((long)(b * 3 + 2)) * NPIX + n];
}

// ---------- normalized [1,2,1] depthwise blur, zero pad ----------
__global__ void blur_kernel(float* __restrict__ out) {
    long i = (long)blockIdx.x * 256 + threadIdx.x;
    int x = (int)(i & 255), y = (int)((i >> 8) & 255);
    long bc = i >> 16;
    const float* p = g_rgbup + bc * 65536;
    float s = 0.f;
    #pragma unroll
    for (int dy = -1; dy <= 1; dy++) {
        int yy = y + dy; if (yy < 0 || yy > 255) continue;
        float wy = (dy == 0) ? 2.f : 1.f;
        #pragma unroll
        for (int dx = -1; dx <= 1; dx++) {
            int xx = x + dx; if (xx < 0 || xx > 255) continue;
            float wx = (dx == 0) ? 2.f : 1.f;
            s += wy * wx * p[yy * 256 + xx];
        }
    }
    out[i] = s * 0.0625f;
}

extern "C" void kernel_launch(void* const* d_in, const int* in_sizes, int n_in,
                              void* d_out, int out_size) {
    const float* x      = (const float*)d_in[0];
    const float* prev   = (const float*)d_in[1];
    const float* istyle = (const float*)d_in[2];
    const float* noise1 = (const float*)d_in[3];
    const float* noise2 = (const float*)d_in[4];
    const float* c1w    = (const float*)d_in[5];
    const float* c2w    = (const float*)d_in[6];
    const float* sw     = (const float*)d_in[7];
    const float* sb     = (const float*)d_in[8];
    const float* rgbw   = (const float*)d_in[9];
    const float* qw     = (const float*)d_in[10];
    const float* kw     = (const float*)d_in[11];
    const float* vw     = (const float*)d_in[12];
    const float* ow     = (const float*)d_in[13];
    const float* ob     = (const float*)d_in[14];
    const float* ga     = (const float*)d_in[15];
    const float* f1w    = (const float*)d_in[16];
    const float* f1b    = (const float*)d_in[17];
    const float* f2w    = (const float*)d_in[18];
    const float* f2b    = (const float*)d_in[19];
    const float* gf     = (const float*)d_in[20];
    float* out = (float*)d_out;
    float* xout = out;
    float* rgbout = out + (long)BB * FC * NPIX;

    cudaFuncSetAttribute(ksoftmax_kernel, cudaFuncAttributeMaxDynamicSharedMemorySize, 65536);
    cudaFuncSetAttribute(ff_kernel, cudaFuncAttributeMaxDynamicSharedMemorySize, 68352);

    float *p_xup, *p_rgbpre, *p_rgbup, *p_n1, *p_n2, *p_xa, *p_w1t, *p_w2t;
    cudaGetSymbolAddress((void**)&p_xup, g_xup);
    cudaGetSymbolAddress((void**)&p_rgbpre, g_rgbpre);
    cudaGetSymbolAddress((void**)&p_rgbup, g_rgbup);
    cudaGetSymbolAddress((void**)&p_n1, g_n1);
    cudaGetSymbolAddress((void**)&p_n2, g_n2);
    cudaGetSymbolAddress((void**)&p_xa, g_xa);
    cudaGetSymbolAddress((void**)&p_w1t, g_w1t);
    cudaGetSymbolAddress((void**)&p_w2t, g_w2t);

    up2_kernel<<<(BB * CIN1 * NPIX) / 256, 256>>>(x, p_xup, CIN1, 64, 64);
    weff_kernel<<<128, 256>>>(c1w, c2w);
    style_kernel<<<BB, 64>>>(istyle, sw, sb, rgbw);

    for (int a = 0; a < 2; a++) {
        const float* noise = a ? noise2 : noise1;
        float* nout = a ? p_n2 : p_n1;
        proj_kernel<<<dim3(128, 16, BB), 256>>>(noise, qw + a * DK * 64, kw + a * DK * 64, vw + a * DV * 64);
        ksoftmax_kernel<<<BB * DK, 256, 65536>>>();
        qsoftmax_kernel<<<(BB * 8 * NPIX) / 256, 256>>>();
        ctx_kernel<<<dim3(8, 8, BB), 128>>>();
        m_kernel<<<BB * 8, 256>>>(ow + a * 64 * DV);
        outproj_kernel<<<dim3(128, BB), 256>>>(noise, ob + a * 64, ga + a, nout);
        ff_kernel<<<dim3(128, BB), 128, 68352>>>(f1w + a * 128 * 64, f1b + a * 128,
                                                 f2w + a * 64 * 128, f2b + a * 64, gf + a, nout);
    }

    conv3_kernel<CIN1><<<dim3(8, 16, BB), 256>>>(p_xup, p_w1t, p_n1, p_xa);
    conv3_kernel<FC><<<dim3(8, 16, BB), 256>>>(p_xa, p_w2t, p_n2, xout);
    rgb_kernel<<<dim3(NPIX / 256, BB), 256>>>(xout, prev);
    up2_kernel<<<(BB * 3 * 4 * NPIX) / 256, 256>>>(p_rgbpre, p_rgbup, 3, 128, 128);
    blur_kernel<<<(BB * 3 * 4 * NPIX) / 256, 256>>>(rgbout);
}

// round 4
// speedup vs baseline: 1.2509x; 1.2509x over previous
#include <cuda_runtime.h>

#define BB 4
#define FC 64
#define CIN1 128
#define NPIX 16384
#define DK 256
#define DV 512

typedef unsigned long long ull;

__device__ __forceinline__ ull pk(float a, float b) {
    ull r; asm("mov.b64 %0, {%1,%2};" : "=l"(r) : "f"(a), "f"(b)); return r;
}
__device__ __forceinline__ float2 upk(ull v) {
    float2 r; asm("mov.b64 {%0,%1}, %2;" : "=f"(r.x), "=f"(r.y) : "l"(v)); return r;
}
__device__ __forceinline__ void fma2(ull& d, ull a, ull b) {
    asm("fma.rn.f32x2 %0, %1, %2, %0;" : "+l"(d) : "l"(a), "l"(b));
}

__device__ float g_xup[BB*CIN1*NPIX];
__device__ float g_q[BB*DK*NPIX];
__device__ float g_k[BB*DK*NPIX];
__device__ float g_v[BB*DV*NPIX];
__device__ float g_ctxp[BB*8*32*2048];
__device__ float g_M[BB*8*2048];
__device__ float g_n1[BB*FC*NPIX];
__device__ float g_n2[BB*FC*NPIX];
__device__ float g_xa[BB*FC*NPIX];
__device__ float g_w1t[CIN1*9*FC];
__device__ float g_w2t[FC*9*FC];
__device__ float g_wmod[BB*3*FC];
__device__ float g_rgbpre[BB*3*NPIX];
__device__ float g_rgbup[BB*3*4*NPIX];

// ---------- bilinear 2x upsample (half-pixel, edge clamp) ----------
__global__ void up2_kernel(const float* __restrict__ in, float* __restrict__ out,
                           int C, int Hin, int Win) {
    int Ho = Hin * 2, Wo = Win * 2;
    long total = (long)BB * C * Ho * Wo;
    long i = (long)blockIdx.x * blockDim.x + threadIdx.x;
    if (i >= total) return;
    int ox = (int)(i % Wo); long r = i / Wo;
    int oy = (int)(r % Ho); r /= Ho;
    int c = (int)(r % C); int b = (int)(r / C);
    float sy = oy * 0.5f - 0.25f, sx = ox * 0.5f - 0.25f;
    int y0 = (int)floorf(sy), x0 = (int)floorf(sx);
    float wy = sy - (float)y0, wx = sx - (float)x0;
    int y0c = max(y0, 0), y1c = min(y0 + 1, Hin - 1);
    int x0c = max(x0, 0), x1c = min(x0 + 1, Win - 1);
    const float* p = in + ((long)b * C + c) * Hin * Win;
    float v00 = p[y0c * Win + x0c], v01 = p[y0c * Win + x1c];
    float v10 = p[y1c * Win + x0c], v11 = p[y1c * Win + x1c];
    out[i] = (1.f - wy) * ((1.f - wx) * v00 + wx * v01) + wy * ((1.f - wx) * v10 + wx * v11);
}

// ---------- demodulated conv weights (style = ones), transposed [ci][k][co] ----------
__global__ void weff_kernel(const float* __restrict__ w1, const float* __restrict__ w2) {
    int co = blockIdx.x;
    const float* w; float* wo; int len;
    if (co < 64) { w = w1 + (long)co * CIN1 * 9; wo = g_w1t; len = CIN1 * 9; }
    else { co -= 64; w = w2 + (long)co * FC * 9; wo = g_w2t; len = FC * 9; }
    __shared__ float red[256];
    float s = 0.f;
    for (int i = threadIdx.x; i < len; i += 256) { float v = w[i]; s += v * v; }
    red[threadIdx.x] = s; __syncthreads();
    for (int o = 128; o > 0; o >>= 1) { if (threadIdx.x < o) red[threadIdx.x] += red[threadIdx.x + o]; __syncthreads(); }
    float sc = 2.f * rsqrtf(4.f * red[0] + 1e-8f);
    for (int i = threadIdx.x; i < len; i += 256) wo[(long)i * 64 + co] = w[i] * sc;
}

// ---------- style -> modulated 1x1 rgb weights ----------
__global__ void style_kernel(const float* __restrict__ istyle, const float* __restrict__ sw,
                             const float* __restrict__ sb, const float* __restrict__ rgbw) {
    int f = threadIdx.x, b = blockIdx.x;
    float s = sb[f];
    for (int l = 0; l < 512; l++) s += istyle[b * 512 + l] * sw[f * 512 + l];
    s += 1.f;
    for (int co = 0; co < 3; co++) g_wmod[(b * 3 + co) * 64 + f] = rgbw[co * 64 + f] * s;
}

// ---------- QKV projection GEMM (f32x2): 64 rows x 128 px per 128-thread block ----------
__global__ void __launch_bounds__(128) proj_kernel(
    const float* __restrict__ noise, const float* __restrict__ qw,
    const float* __restrict__ kw, const float* __restrict__ vw) {
    __shared__ float Ws[64][68];     // transposed [k][row]
    __shared__ float Xs[64][128];
    int nt = blockIdx.x, rt = blockIdx.y, b = blockIdx.z;
    int t = threadIdx.x, n0 = nt * 128;
    const float* wsrc; float* dst; float sc;
    const float SCALE = 0.42044820762685725f; // 32^-0.25
    if (rt < 4)      { wsrc = qw + rt * 64 * 64;       dst = g_q + ((long)b * DK + rt * 64) * NPIX;       sc = SCALE; }
    else if (rt < 8) { wsrc = kw + (rt - 4) * 64 * 64; dst = g_k + ((long)b * DK + (rt - 4) * 64) * NPIX; sc = SCALE; }
    else             { wsrc = vw + (rt - 8) * 64 * 64; dst = g_v + ((long)b * DV + (rt - 8) * 64) * NPIX; sc = 1.f; }
    {   // transpose-load weights
        int r = t >> 1, k0 = (t & 1) * 32;
        const float4* s4 = (const float4*)(wsrc + r * 64 + k0);
        #pragma unroll
        for (int i = 0; i < 8; i++) {
            float4 w = s4[i]; int kk = k0 + i * 4;
            Ws[kk][r] = w.x; Ws[kk + 1][r] = w.y; Ws[kk + 2][r] = w.z; Ws[kk + 3][r] = w.w;
        }
    }
    #pragma unroll
    for (int i = 0; i < 16; i++) { int idx = t + i * 128; int c = idx >> 5, n4 = idx & 31;
      *(float4*)&Xs[c][n4 * 4] = *(const float4*)(noise + ((long)b * FC + c) * NPIX + n0 + n4 * 4); }
    __syncthreads();
    int rp = t >> 4, pg = t & 15;          // rows rp*8..+7, px pg*8..+7
    ull acc[4][8];
    #pragma unroll
    for (int i = 0; i < 4; i++)
      #pragma unroll
      for (int j = 0; j < 8; j++) acc[i][j] = 0ull;
    #pragma unroll 8
    for (int k = 0; k < 64; k++) {
        ulonglong2 wa = *(ulonglong2*)&Ws[k][rp * 8];
        ulonglong2 wb = *(ulonglong2*)&Ws[k][rp * 8 + 4];
        ull a[4] = {wa.x, wa.y, wb.x, wb.y};
        float4 x0 = *(float4*)&Xs[k][pg * 8];
        float4 x1 = *(float4*)&Xs[k][pg * 8 + 4];
        ull xb[8] = {pk(x0.x, x0.x), pk(x0.y, x0.y), pk(x0.z, x0.z), pk(x0.w, x0.w),
                     pk(x1.x, x1.x), pk(x1.y, x1.y), pk(x1.z, x1.z), pk(x1.w, x1.w)};
        #pragma unroll
        for (int i = 0; i < 4; i++)
          #pragma unroll
          for (int j = 0; j < 8; j++) fma2(acc[i][j], a[i], xb[j]);
    }
    #pragma unroll
    for (int i = 0; i < 4; i++) {
        float lo[8], hi[8];
        #pragma unroll
        for (int j = 0; j < 8; j++) { float2 f = upk(acc[i][j]); lo[j] = f.x * sc; hi[j] = f.y * sc; }
        long b0 = (long)(rp * 8 + 2 * i) * NPIX + n0 + pg * 8;
        long b1 = b0 + NPIX;
        *(float4*)(dst + b0) = make_float4(lo[0], lo[1], lo[2], lo[3]);
        *(float4*)(dst + b0 + 4) = make_float4(lo[4], lo[5], lo[6], lo[7]);
        *(float4*)(dst + b1) = make_float4(hi[0], hi[1], hi[2], hi[3]);
        *(float4*)(dst + b1 + 4) = make_float4(hi[4], hi[5], hi[6], hi[7]);
    }
}

// ---------- softmax over 16384 pixels per k row (register resident) ----------
__global__ void __launch_bounds__(256) ksoftmax_kernel() {
    __shared__ float red[256];
    int t = threadIdx.x;
    float* p = g_k + (long)blockIdx.x * NPIX;
    float v[64]; float mx = -1e30f;
    #pragma unroll
    for (int i = 0; i < 64; i++) { v[i] = p[t + i * 256]; mx = fmaxf(mx, v[i]); }
    red[t] = mx; __syncthreads();
    for (int o = 128; o > 0; o >>= 1) { if (t < o) red[t] = fmaxf(red[t], red[t + o]); __syncthreads(); }
    mx = red[0]; __syncthreads();
    float s = 0.f;
    #pragma unroll
    for (int i = 0; i < 64; i++) { v[i] = __expf(v[i] - mx); s += v[i]; }
    red[t] = s; __syncthreads();
    for (int o = 128; o > 0; o >>= 1) { if (t < o) red[t] += red[t + o]; __syncthreads(); }
    float inv = 1.f / red[0];
    #pragma unroll
    for (int i = 0; i < 64; i++) p[t + i * 256] = v[i] * inv;
}

// ---------- softmax over d=32 per (b,h,pixel) ----------
__global__ void qsoftmax_kernel() {
    long tid = (long)blockIdx.x * 256 + threadIdx.x;
    int n = (int)(tid % NPIX);
    int h = (int)((tid / NPIX) % 8);
    int b = (int)(tid / ((long)NPIX * 8));
    float* p = g_q + ((long)(b * DK + h * 32)) * NPIX + n;
    float v[32]; float mx = -1e30f;
    #pragma unroll
    for (int d = 0; d < 32; d++) { v[d] = p[(long)d * NPIX]; mx = fmaxf(mx, v[d]); }
    float s = 0.f;
    #pragma unroll
    for (int d = 0; d < 32; d++) { v[d] = __expf(v[d] - mx); s += v[d]; }
    float inv = 1.f / s;
    #pragma unroll
    for (int d = 0; d < 32; d++) p[(long)d * NPIX] = v[d] * inv;
}

// ---------- ctx partial: k[32,512] @ v[64,512]^T per (chunk,h,b), 32 chunks ----------
__global__ void __launch_bounds__(128) ctx_kernel() {
    int ch = blockIdx.x, h = blockIdx.y, b = blockIdx.z;
    __shared__ float ks[32][64];
    __shared__ float vs[64][68];
    int t = threadIdx.x;
    int dg = t >> 4, eg = t & 15;
    float acc[4][4];
    #pragma unroll
    for (int i = 0; i < 4; i++)
      #pragma unroll
      for (int j = 0; j < 4; j++) acc[i][j] = 0.f;
    const float* kbase = g_k + ((long)(b * DK + h * 32)) * NPIX + ch * 512;
    const float* vbase = g_v + ((long)(b * DV + h * 64)) * NPIX + ch * 512;
    for (int n0 = 0; n0 < 512; n0 += 64) {
        __syncthreads();
        #pragma unroll
        for (int i = 0; i < 4; i++) { int idx = t + i * 128; int d = idx >> 4, n4 = idx & 15;
            *(float4*)&ks[d][n4 * 4] = *(const float4*)(kbase + (long)d * NPIX + n0 + n4 * 4); }
        #pragma unroll
        for (int i = 0; i < 8; i++) { int idx = t + i * 128; int e = idx >> 4, n4 = idx & 15;
            float4 vv = *(const float4*)(vbase + (long)e * NPIX + n0 + n4 * 4);
            vs[n4 * 4 + 0][e] = vv.x; vs[n4 * 4 + 1][e] = vv.y;
            vs[n4 * 4 + 2][e] = vv.z; vs[n4 * 4 + 3][e] = vv.w; }
        __syncthreads();
        #pragma unroll 8
        for (int n = 0; n < 64; n++) {
            float4 ve = *(float4*)&vs[n][eg * 4];
            #pragma unroll
            for (int i = 0; i < 4; i++) {
                float kd = ks[dg * 4 + i][n];
                acc[i][0] += kd * ve.x; acc[i][1] += kd * ve.y;
                acc[i][2] += kd * ve.z; acc[i][3] += kd * ve.w;
            }
        }
    }
    float* outp = g_ctxp + ((long)(b * 8 + h) * 32 + ch) * 2048;
    #pragma unroll
    for (int i = 0; i < 4; i++)
      #pragma unroll
      for (int j = 0; j < 4; j++)
        outp[(dg * 4 + i) * 64 + eg * 4 + j] = acc[i][j];
}

// ---------- reduce ctx chunks, fold with ow: M[d][c] = sum_e ctx[d][e]*ow[c][h*64+e] ----------
__global__ void __launch_bounds__(256) m_kernel(const float* __restrict__ ow) {
    int h = blockIdx.x & 7, b = blockIdx.x >> 3;
    __shared__ float ctx_s[2048];
    __shared__ float ow_s[64][65];
    int t = threadIdx.x;
    const float* cp = g_ctxp + (long)(b * 8 + h) * 32 * 2048;
    #pragma unroll
    for (int i = 0; i < 8; i++) {
        int idx = t + i * 256;
        float s = 0.f;
        #pragma unroll 8
        for (int ch = 0; ch < 32; ch++) s += cp[(long)ch * 2048 + idx];
        ctx_s[idx] = s;
    }
    #pragma unroll
    for (int i = 0; i < 16; i++) {
        int idx = t + i * 256;
        int c = idx >> 6, e = idx & 63;
        ow_s[c][e] = ow[(long)c * DV + h * 64 + e];
    }
    __syncthreads();
    float* Mp = g_M + (long)(b * 8 + h) * 2048;
    #pragma unroll
    for (int i = 0; i < 8; i++) {
        int idx = t + i * 256;
        int d = idx >> 6, c = idx & 63;
        float s = 0.f;
        #pragma unroll 16
        for (int e = 0; e < 64; e++) s += ctx_s[d * 64 + e] * ow_s[c][e];
        Mp[idx] = s;
    }
}

// ---------- out projection + residual (f32x2): nout = noise + ga*(q^T M + ob) ----------
__global__ void __launch_bounds__(256) outproj_kernel(
    const float* __restrict__ noise, const float* __restrict__ ob,
    const float* __restrict__ ga, float* __restrict__ nout) {
    int nt = blockIdx.x, b = blockIdx.y;
    __shared__ float qs[32][132];
    __shared__ float Ms[32][64];
    int t = threadIdx.x;
    int pg = t & 31, cg = t >> 5;
    int n0 = nt * 128;
    ull acc[4][4];          // [px][c-pair]
    #pragma unroll
    for (int i = 0; i < 4; i++)
      #pragma unroll
      for (int j = 0; j < 4; j++) acc[i][j] = 0ull;
    for (int h = 0; h < 8; h++) {
        __syncthreads();
        #pragma unroll
        for (int i = 0; i < 4; i++) { int idx = t + i * 256; int d = idx >> 5, n4 = idx & 31;
            *(float4*)&qs[d][n4 * 4] =
                *(const float4*)(g_q + ((long)(b * DK + h * 32 + d)) * NPIX + n0 + n4 * 4); }
        #pragma unroll
        for (int i = 0; i < 2; i++) { int idx = t + i * 256; int d = idx >> 4, c4 = idx & 15;
            *(float4*)&Ms[d][c4 * 4] =
                *(const float4*)(g_M + ((long)(b * 8 + h)) * 2048 + d * 64 + c4 * 4); }
        __syncthreads();
        #pragma unroll 4
        for (int d = 0; d < 32; d++) {
            float4 q4 = *(float4*)&qs[d][pg * 4];
            ull qb[4] = {pk(q4.x, q4.x), pk(q4.y, q4.y), pk(q4.z, q4.z), pk(q4.w, q4.w)};
            ulonglong2 m01 = *(ulonglong2*)&Ms[d][cg * 8];
            ulonglong2 m23 = *(ulonglong2*)&Ms[d][cg * 8 + 4];
            ull mp[4] = {m01.x, m01.y, m23.x, m23.y};
            #pragma unroll
            for (int p = 0; p < 4; p++)
              #pragma unroll
              for (int cpi = 0; cpi < 4; cpi++) fma2(acc[p][cpi], mp[cpi], qb[p]);
        }
    }
    float gav = ga[0];
    #pragma unroll
    for (int cpi = 0; cpi < 4; cpi++) {
        int c0 = cg * 8 + cpi * 2;
        float ob0 = ob[c0], ob1 = ob[c0 + 1];
        #pragma unroll
        for (int p = 0; p < 4; p++) {
            float2 f = upk(acc[p][cpi]);
            long off0 = ((long)(b * FC + c0)) * NPIX + n0 + pg * 4 + p;
            nout[off0] = noise[off0] + gav * (f.x + ob0);
            long off1 = off0 + NPIX;
            nout[off1] = noise[off1] + gav * (f.y + ob1);
        }
    }
}

// ---------- per-pixel FF (f32x2): x += gf*(f2 @ lrelu(f1 @ x + b1) + b2) ----------
__global__ void __launch_bounds__(128) ff_kernel(
    const float* __restrict__ f1w, const float* __restrict__ f1b,
    const float* __restrict__ f2w, const float* __restrict__ f2b,
    const float* __restrict__ gf, float* __restrict__ xio) {
    __shared__ float f1s[128 * 64];
    __shared__ float f2s[128 * 68];
    __shared__ float b1s[128];
    __shared__ float b2s[64];
    int t = threadIdx.x;
    for (int i = t; i < 8192; i += 128) f1s[i] = f1w[i];
    for (int i = t; i < 8192; i += 128) { int c = i >> 7, j = i & 127; f2s[j * 68 + c] = f2w[i]; }
    b1s[t] = f1b[t];
    if (t < 64) b2s[t] = f2b[t];
    __syncthreads();
    long base = (long)blockIdx.y * FC * NPIX + blockIdx.x * 128 + t;
    ull xp[32], acc[32];
    #pragma unroll
    for (int c2 = 0; c2 < 32; c2++) {
        float a = xio[base + (long)(2 * c2) * NPIX];
        float bq = xio[base + (long)(2 * c2 + 1) * NPIX];
        xp[c2] = pk(a, bq); acc[c2] = 0ull;
    }
    #pragma unroll 2
    for (int j = 0; j < 128; j++) {
        ull d0 = 0ull, d1 = 0ull, d2 = 0ull, d3 = 0ull;
        const ulonglong2* w1p = (const ulonglong2*)(f1s + j * 64);
        #pragma unroll
        for (int i = 0; i < 16; i++) {
            ulonglong2 wv = w1p[i];
            if ((i & 1) == 0) { fma2(d0, wv.x, xp[2 * i]); fma2(d1, wv.y, xp[2 * i + 1]); }
            else              { fma2(d2, wv.x, xp[2 * i]); fma2(d3, wv.y, xp[2 * i + 1]); }
        }
        float2 s0 = upk(d0), s1 = upk(d1), s2 = upk(d2), s3 = upk(d3);
        float hv = b1s[j] + ((s0.x + s0.y) + (s1.x + s1.y)) + ((s2.x + s2.y) + (s3.x + s3.y));
        hv = hv > 0.f ? hv : 0.2f * hv;
        ull hb = pk(hv, hv);
        const ulonglong2* w2p = (const ulonglong2*)(f2s + j * 68);
        #pragma unroll
        for (int i = 0; i < 16; i++) {
            ulonglong2 wv = w2p[i];
            fma2(acc[2 * i], wv.x, hb); fma2(acc[2 * i + 1], wv.y, hb);
        }
    }
    float g = gf[0];
    #pragma unroll
    for (int c2 = 0; c2 < 32; c2++) {
        float2 f = upk(acc[c2]); float2 xv = upk(xp[c2]);
        xio[base + (long)(2 * c2) * NPIX] = xv.x + g * (f.x + b2s[2 * c2]);
        xio[base + (long)(2 * c2 + 1) * NPIX] = xv.y + g * (f.y + b2s[2 * c2 + 1]);
    }
}

// ---------- direct 3x3 conv (f32x2) + add + lrelu; weights [ci][k][co] ----------
template<int CIN>
__global__ void __launch_bounds__(256) conv3_kernel(
    const float* __restrict__ in, const float* __restrict__ wt,
    const float* __restrict__ nadd, float* __restrict__ out) {
    __shared__ float ws[8 * 9 * 64];
    __shared__ float ins[8][18][19];
    int t = threadIdx.x;
    int cg = t >> 6;                      // 4 groups of 16 co
    int pg = t & 63;                      // 8x8 groups of 2x2 px
    int px = (pg & 7) * 2, py = (pg >> 3) * 2;
    int bx = blockIdx.x * 16, by = blockIdx.y * 16, b = blockIdx.z;
    ull acc[4][8];                        // [px 2x2][co-pair]
    #pragma unroll
    for (int i = 0; i < 4; i++)
      #pragma unroll
      for (int j = 0; j < 8; j++) acc[i][j] = 0ull;
    for (int c0 = 0; c0 < CIN; c0 += 8) {
        __syncthreads();
        const float4* wsrc = (const float4*)(wt + (long)c0 * 9 * 64);
        float4* wdst = (float4*)ws;
        for (int i = t; i < 1152; i += 256) wdst[i] = wsrc[i];
        for (int i = t; i < 2592; i += 256) {
            int ci = i / 324, r = i % 324, y = r / 18, xx = r % 18;
            int gy = by + y - 1, gx = bx + xx - 1;
            float v = 0.f;
            if (gy >= 0 && gy < 128 && gx >= 0 && gx < 128)
                v = in[((long)(b * CIN + c0 + ci)) * NPIX + gy * 128 + gx];
            ins[ci][y][xx] = v;
        }
        __syncthreads();
        #pragma unroll
        for (int ci = 0; ci < 8; ci++)
          #pragma unroll
          for (int kk = 0; kk < 9; kk++) {
            int ky = kk / 3, kx = kk % 3;
            float x00 = ins[ci][py + ky][px + kx];
            float x01 = ins[ci][py + ky][px + kx + 1];
            float x10 = ins[ci][py + ky + 1][px + kx];
            float x11 = ins[ci][py + ky + 1][px + kx + 1];
            ull xb[4] = {pk(x00, x00), pk(x01, x01), pk(x10, x10), pk(x11, x11)};
            const ulonglong2* wp = (const ulonglong2*)(ws + (ci * 9 + kk) * 64 + cg * 16);
            ulonglong2 w0 = wp[0], w1 = wp[1], w2 = wp[2], w3 = wp[3];
            ull wpair[8] = {w0.x, w0.y, w1.x, w1.y, w2.x, w2.y, w3.x, w3.y};
            #pragma unroll
            for (int p = 0; p < 4; p++)
              #pragma unroll
              for (int cpi = 0; cpi < 8; cpi++) fma2(acc[p][cpi], wpair[cpi], xb[p]);
          }
    }
    #pragma unroll
    for (int p = 0; p < 4; p++) {
        int gy = by + py + (p >> 1), gx = bx + px + (p & 1);
        long poff = (long)gy * 128 + gx;
        #pragma unroll
        for (int cpi = 0; cpi < 8; cpi++) {
            float2 f = upk(acc[p][cpi]);
            int c0 = cg * 16 + cpi * 2;
            long off0 = ((long)(b * 64 + c0)) * NPIX + poff;
            float v0 = f.x + nadd[off0];
            out[off0] = v0 > 0.f ? v0 : 0.2f * v0;
            long off1 = off0 + NPIX;
            float v1 = f.y + nadd[off1];
            out[off1] = v1 > 0.f ? v1 : 0.2f * v1;
        }
    }
}

// ---------- modulated 1x1 rgb conv + prev_rgb ----------
__global__ void rgb_kernel(const float* __restrict__ xin, const float* __restrict__ prev) {
    int n = blockIdx.x * 256 + threadIdx.x;
    int b = blockIdx.y;
    __shared__ float w[192];
    if (threadIdx.x < 192) w[threadIdx.x] = g_wmod[b * 192 + threadIdx.x];
    __syncthreads();
    float a0 = 0.f, a1 = 0.f, a2 = 0.f;
    for (int c = 0; c < 64; c++) {
        float xv = xin[((long)(b * 64 + c)) * NPIX + n];
        a0 += w[c] * xv; a1 += w[64 + c] * xv; a2 += w[128 + c] * xv;
    }
    g_rgbpre[((long)(b * 3 + 0)) * NPIX + n] = a0 + prev[((long)(b * 3 + 0)) * NPIX + n];
    g_rgbpre[((long)(b * 3 + 1)) * NPIX + n] = a1 + prev[((long)(b * 3 + 1)) * NPIX + n];
    g_rgbpre[((long)(b * 3 + 2)) * NPIX + n] = a2 + prev[((long)(b * 3 + 2)) * NPIX + n];
}

// ---------- normalized [1,2,1] depthwise blur, zero pad ----------
__global__ void blur_kernel(float* __restrict__ out) {
    long i = (long)blockIdx.x * 256 + threadIdx.x;
    int x = (int)(i & 255), y = (int)((i >> 8) & 255);
    long bc = i >> 16;
    const float* p = g_rgbup + bc * 65536;
    float s = 0.f;
    #pragma unroll
    for (int dy = -1; dy <= 1; dy++) {
        int yy = y + dy; if (yy < 0 || yy > 255) continue;
        float wy = (dy == 0) ? 2.f : 1.f;
        #pragma unroll
        for (int dx = -1; dx <= 1; dx++) {
            int xx = x + dx; if (xx < 0 || xx > 255) continue;
            float wx = (dx == 0) ? 2.f : 1.f;
            s += wy * wx * p[yy * 256 + xx];
        }
    }
    out[i] = s * 0.0625f;
}

extern "C" void kernel_launch(void* const* d_in, const int* in_sizes, int n_in,
                              void* d_out, int out_size) {
    const float* x      = (const float*)d_in[0];
    const float* prev   = (const float*)d_in[1];
    const float* istyle = (const float*)d_in[2];
    const float* noise1 = (const float*)d_in[3];
    const float* noise2 = (const float*)d_in[4];
    const float* c1w    = (const float*)d_in[5];
    const float* c2w    = (const float*)d_in[6];
    const float* sw     = (const float*)d_in[7];
    const float* sb     = (const float*)d_in[8];
    const float* rgbw   = (const float*)d_in[9];
    const float* qw     = (const float*)d_in[10];
    const float* kw     = (const float*)d_in[11];
    const float* vw     = (const float*)d_in[12];
    const float* ow     = (const float*)d_in[13];
    const float* ob     = (const float*)d_in[14];
    const float* ga     = (const float*)d_in[15];
    const float* f1w    = (const float*)d_in[16];
    const float* f1b    = (const float*)d_in[17];
    const float* f2w    = (const float*)d_in[18];
    const float* f2b    = (const float*)d_in[19];
    const float* gf     = (const float*)d_in[20];
    float* out = (float*)d_out;
    float* xout = out;
    float* rgbout = out + (long)BB * FC * NPIX;

    float *p_xup, *p_rgbpre, *p_rgbup, *p_n1, *p_n2, *p_xa, *p_w1t, *p_w2t;
    cudaGetSymbolAddress((void**)&p_xup, g_xup);
    cudaGetSymbolAddress((void**)&p_rgbpre, g_rgbpre);
    cudaGetSymbolAddress((void**)&p_rgbup, g_rgbup);
    cudaGetSymbolAddress((void**)&p_n1, g_n1);
    cudaGetSymbolAddress((void**)&p_n2, g_n2);
    cudaGetSymbolAddress((void**)&p_xa, g_xa);
    cudaGetSymbolAddress((void**)&p_w1t, g_w1t);
    cudaGetSymbolAddress((void**)&p_w2t, g_w2t);

    up2_kernel<<<(BB * CIN1 * NPIX) / 256, 256>>>(x, p_xup, CIN1, 64, 64);
    weff_kernel<<<128, 256>>>(c1w, c2w);
    style_kernel<<<BB, 64>>>(istyle, sw, sb, rgbw);

    for (int a = 0; a < 2; a++) {
        const float* noise = a ? noise2 : noise1;
        float* nout = a ? p_n2 : p_n1;
        proj_kernel<<<dim3(128, 16, BB), 128>>>(noise, qw + a * DK * 64, kw + a * DK * 64, vw + a * DV * 64);
        ksoftmax_kernel<<<BB * DK, 256>>>();
        qsoftmax_kernel<<<(BB * 8 * NPIX) / 256, 256>>>();
        ctx_kernel<<<dim3(32, 8, BB), 128>>>();
        m_kernel<<<BB * 8, 256>>>(ow + a * 64 * DV);
        outproj_kernel<<<dim3(128, BB), 256>>>(noise, ob + a * 64, ga + a, nout);
        ff_kernel<<<dim3(128, BB), 128>>>(f1w + a * 128 * 64, f1b + a * 128,
                                          f2w + a * 64 * 128, f2b + a * 64, gf + a, nout);
    }

    conv3_kernel<CIN1><<<dim3(8, 8, BB), 256>>>(p_xup, p_w1t, p_n1, p_xa);
    conv3_kernel<FC><<<dim3(8, 8, BB), 256>>>(p_xa, p_w2t, p_n2, xout);
    rgb_kernel<<<dim3(NPIX / 256, BB), 256>>>(xout, prev);
    up2_kernel<<<(BB * 3 * 4 * NPIX) / 256, 256>>>(p_rgbpre, p_rgbup, 3, 128, 128);
    blur_kernel<<<(BB * 3 * 4 * NPIX) / 256, 256>>>(rgbout);
}

// round 5
// speedup vs baseline: 1.3771x; 1.1009x over previous
#include <cuda_runtime.h>

#define BB 4
#define FC 64
#define CIN1 128
#define NPIX 16384
#define DK 256
#define DV 512

typedef unsigned long long ull;

__device__ __forceinline__ ull pk(float a, float b) {
    ull r; asm("mov.b64 %0, {%1,%2};" : "=l"(r) : "f"(a), "f"(b)); return r;
}
__device__ __forceinline__ float2 upk(ull v) {
    float2 r; asm("mov.b64 {%0,%1}, %2;" : "=f"(r.x), "=f"(r.y) : "l"(v)); return r;
}
__device__ __forceinline__ void fma2(ull& d, ull a, ull b) {
    asm("fma.rn.f32x2 %0, %1, %2, %0;" : "+l"(d) : "l"(a), "l"(b));
}

__device__ float g_xup[BB*CIN1*NPIX];
__device__ float g_q[BB*DK*NPIX];
__device__ float g_k[BB*DK*NPIX];
__device__ float g_v[BB*DV*NPIX];
__device__ float g_kstat[BB*DK*2];
__device__ float g_ctxp[BB*8*32*2048];
__device__ float g_M[BB*8*2048];
__device__ float g_n1[BB*FC*NPIX];
__device__ float g_n2[BB*FC*NPIX];
__device__ float g_xa[BB*FC*NPIX];
__device__ float g_w1t[CIN1*9*FC];
__device__ float g_w2t[FC*9*FC];
__device__ float g_wmod[BB*3*FC];
__device__ float g_rgbpre[BB*3*NPIX];
__device__ float g_rgbup[BB*3*4*NPIX];

// ---------- bilinear 2x upsample (half-pixel, edge clamp) ----------
__global__ void up2_kernel(const float* __restrict__ in, float* __restrict__ out,
                           int C, int Hin, int Win) {
    int Ho = Hin * 2, Wo = Win * 2;
    long total = (long)BB * C * Ho * Wo;
    long i = (long)blockIdx.x * blockDim.x + threadIdx.x;
    if (i >= total) return;
    int ox = (int)(i % Wo); long r = i / Wo;
    int oy = (int)(r % Ho); r /= Ho;
    int c = (int)(r % C); int b = (int)(r / C);
    float sy = oy * 0.5f - 0.25f, sx = ox * 0.5f - 0.25f;
    int y0 = (int)floorf(sy), x0 = (int)floorf(sx);
    float wy = sy - (float)y0, wx = sx - (float)x0;
    int y0c = max(y0, 0), y1c = min(y0 + 1, Hin - 1);
    int x0c = max(x0, 0), x1c = min(x0 + 1, Win - 1);
    const float* p = in + ((long)b * C + c) * Hin * Win;
    float v00 = p[y0c * Win + x0c], v01 = p[y0c * Win + x1c];
    float v10 = p[y1c * Win + x0c], v11 = p[y1c * Win + x1c];
    out[i] = (1.f - wy) * ((1.f - wx) * v00 + wx * v01) + wy * ((1.f - wx) * v10 + wx * v11);
}

// ---------- demodulated conv weights (style = ones), transposed [ci][k][co] ----------
__global__ void weff_kernel(const float* __restrict__ w1, const float* __restrict__ w2) {
    int co = blockIdx.x;
    const float* w; float* wo; int len;
    if (co < 64) { w = w1 + (long)co * CIN1 * 9; wo = g_w1t; len = CIN1 * 9; }
    else { co -= 64; w = w2 + (long)co * FC * 9; wo = g_w2t; len = FC * 9; }
    __shared__ float red[256];
    float s = 0.f;
    for (int i = threadIdx.x; i < len; i += 256) { float v = w[i]; s += v * v; }
    red[threadIdx.x] = s; __syncthreads();
    for (int o = 128; o > 0; o >>= 1) { if (threadIdx.x < o) red[threadIdx.x] += red[threadIdx.x + o]; __syncthreads(); }
    float sc = 2.f * rsqrtf(4.f * red[0] + 1e-8f);
    for (int i = threadIdx.x; i < len; i += 256) wo[(long)i * 64 + co] = w[i] * sc;
}

// ---------- style -> modulated 1x1 rgb weights ----------
__global__ void style_kernel(const float* __restrict__ istyle, const float* __restrict__ sw,
                             const float* __restrict__ sb, const float* __restrict__ rgbw) {
    int f = threadIdx.x, b = blockIdx.x;
    float s = sb[f];
    for (int l = 0; l < 512; l++) s += istyle[b * 512 + l] * sw[f * 512 + l];
    s += 1.f;
    for (int co = 0; co < 3; co++) g_wmod[(b * 3 + co) * 64 + f] = rgbw[co * 64 + f] * s;
}

// ---------- QKV projection GEMM (f32x2, conflict-free Xs) ----------
__global__ void __launch_bounds__(128) proj_kernel(
    const float* __restrict__ noise, const float* __restrict__ qw,
    const float* __restrict__ kw, const float* __restrict__ vw) {
    __shared__ float Ws[64][68];     // transposed [k][row]
    __shared__ float Xs[64][128];
    int nt = blockIdx.x, rt = blockIdx.y, b = blockIdx.z;
    int t = threadIdx.x, n0 = nt * 128;
    const float* wsrc; float* dst; float sc;
    const float SCALE = 0.42044820762685725f; // 32^-0.25
    if (rt < 4)      { wsrc = qw + rt * 64 * 64;       dst = g_q + ((long)b * DK + rt * 64) * NPIX;       sc = SCALE; }
    else if (rt < 8) { wsrc = kw + (rt - 4) * 64 * 64; dst = g_k + ((long)b * DK + (rt - 4) * 64) * NPIX; sc = SCALE; }
    else             { wsrc = vw + (rt - 8) * 64 * 64; dst = g_v + ((long)b * DV + (rt - 8) * 64) * NPIX; sc = 1.f; }
    {   // transpose-load weights
        int r = t >> 1, k0 = (t & 1) * 32;
        const float4* s4 = (const float4*)(wsrc + r * 64 + k0);
        #pragma unroll
        for (int i = 0; i < 8; i++) {
            float4 w = s4[i]; int kk = k0 + i * 4;
            Ws[kk][r] = w.x; Ws[kk + 1][r] = w.y; Ws[kk + 2][r] = w.z; Ws[kk + 3][r] = w.w;
        }
    }
    #pragma unroll
    for (int i = 0; i < 16; i++) { int idx = t + i * 128; int c = idx >> 5, n4 = idx & 31;
      *(float4*)&Xs[c][n4 * 4] = *(const float4*)(noise + ((long)b * FC + c) * NPIX + n0 + n4 * 4); }
    __syncthreads();
    int rp = t >> 4, pg = t & 15;          // rows rp*8..+7, px {pg*4..+3, 64+pg*4..+3}
    ull acc[4][8];
    #pragma unroll
    for (int i = 0; i < 4; i++)
      #pragma unroll
      for (int j = 0; j < 8; j++) acc[i][j] = 0ull;
    #pragma unroll 8
    for (int k = 0; k < 64; k++) {
        ulonglong2 wa = *(ulonglong2*)&Ws[k][rp * 8];
        ulonglong2 wb = *(ulonglong2*)&Ws[k][rp * 8 + 4];
        ull a[4] = {wa.x, wa.y, wb.x, wb.y};
        float4 x0 = *(float4*)&Xs[k][pg * 4];
        float4 x1 = *(float4*)&Xs[k][64 + pg * 4];
        ull xb[8] = {pk(x0.x, x0.x), pk(x0.y, x0.y), pk(x0.z, x0.z), pk(x0.w, x0.w),
                     pk(x1.x, x1.x), pk(x1.y, x1.y), pk(x1.z, x1.z), pk(x1.w, x1.w)};
        #pragma unroll
        for (int i = 0; i < 4; i++)
          #pragma unroll
          for (int j = 0; j < 8; j++) fma2(acc[i][j], a[i], xb[j]);
    }
    #pragma unroll
    for (int i = 0; i < 4; i++) {
        float lo[8], hi[8];
        #pragma unroll
        for (int j = 0; j < 8; j++) { float2 f = upk(acc[i][j]); lo[j] = f.x * sc; hi[j] = f.y * sc; }
        long b0 = (long)(rp * 8 + 2 * i) * NPIX + n0;
        long b1 = b0 + NPIX;
        *(float4*)(dst + b0 + pg * 4) = make_float4(lo[0], lo[1], lo[2], lo[3]);
        *(float4*)(dst + b0 + 64 + pg * 4) = make_float4(lo[4], lo[5], lo[6], lo[7]);
        *(float4*)(dst + b1 + pg * 4) = make_float4(hi[0], hi[1], hi[2], hi[3]);
        *(float4*)(dst + b1 + 64 + pg * 4) = make_float4(hi[4], hi[5], hi[6], hi[7]);
    }
}

// ---------- k softmax stats per row: (max, 1/sum(exp)) ----------
__global__ void __launch_bounds__(256) kstat_kernel() {
    __shared__ float red[256];
    int t = threadIdx.x;
    const float* p = g_k + (long)blockIdx.x * NPIX;
    float v[64]; float mx = -1e30f;
    #pragma unroll
    for (int i = 0; i < 64; i++) { v[i] = p[t + i * 256]; mx = fmaxf(mx, v[i]); }
    red[t] = mx; __syncthreads();
    for (int o = 128; o > 0; o >>= 1) { if (t < o) red[t] = fmaxf(red[t], red[t + o]); __syncthreads(); }
    mx = red[0]; __syncthreads();
    float s = 0.f;
    #pragma unroll
    for (int i = 0; i < 64; i++) s += __expf(v[i] - mx);
    red[t] = s; __syncthreads();
    for (int o = 128; o > 0; o >>= 1) { if (t < o) red[t] += red[t + o]; __syncthreads(); }
    if (t == 0) { g_kstat[blockIdx.x * 2] = mx; g_kstat[blockIdx.x * 2 + 1] = 1.f / red[0]; }
}

// ---------- ctx partial with fused k-softmax: softmax(k)[32,512] @ v[64,512]^T ----------
__global__ void __launch_bounds__(128) ctx_kernel() {
    int ch = blockIdx.x, h = blockIdx.y, b = blockIdx.z;
    __shared__ float ks[32][64];
    __shared__ float vs[64][68];
    __shared__ float smx[32], sinv[32];
    int t = threadIdx.x;
    int dg = t >> 4, eg = t & 15;
    if (t < 32) {
        smx[t] = g_kstat[(b * DK + h * 32 + t) * 2];
        sinv[t] = g_kstat[(b * DK + h * 32 + t) * 2 + 1];
    }
    float acc[4][4];
    #pragma unroll
    for (int i = 0; i < 4; i++)
      #pragma unroll
      for (int j = 0; j < 4; j++) acc[i][j] = 0.f;
    const float* kbase = g_k + ((long)(b * DK + h * 32)) * NPIX + ch * 512;
    const float* vbase = g_v + ((long)(b * DV + h * 64)) * NPIX + ch * 512;
    for (int n0 = 0; n0 < 512; n0 += 64) {
        __syncthreads();
        #pragma unroll
        for (int i = 0; i < 4; i++) { int idx = t + i * 128; int d = idx >> 4, n4 = idx & 15;
            float4 kk = *(const float4*)(kbase + (long)d * NPIX + n0 + n4 * 4);
            float m = smx[d], iv = sinv[d];
            kk.x = __expf(kk.x - m) * iv; kk.y = __expf(kk.y - m) * iv;
            kk.z = __expf(kk.z - m) * iv; kk.w = __expf(kk.w - m) * iv;
            *(float4*)&ks[d][n4 * 4] = kk; }
        #pragma unroll
        for (int i = 0; i < 8; i++) { int idx = t + i * 128; int e = idx >> 4, n4 = idx & 15;
            float4 vv = *(const float4*)(vbase + (long)e * NPIX + n0 + n4 * 4);
            vs[n4 * 4 + 0][e] = vv.x; vs[n4 * 4 + 1][e] = vv.y;
            vs[n4 * 4 + 2][e] = vv.z; vs[n4 * 4 + 3][e] = vv.w; }
        __syncthreads();
        #pragma unroll 8
        for (int n = 0; n < 64; n++) {
            float4 ve = *(float4*)&vs[n][eg * 4];
            #pragma unroll
            for (int i = 0; i < 4; i++) {
                float kd = ks[dg * 4 + i][n];
                acc[i][0] += kd * ve.x; acc[i][1] += kd * ve.y;
                acc[i][2] += kd * ve.z; acc[i][3] += kd * ve.w;
            }
        }
    }
    float* outp = g_ctxp + ((long)(b * 8 + h) * 32 + ch) * 2048;
    #pragma unroll
    for (int i = 0; i < 4; i++)
      #pragma unroll
      for (int j = 0; j < 4; j++)
        outp[(dg * 4 + i) * 64 + eg * 4 + j] = acc[i][j];
}

// ---------- reduce ctx chunks, fold with ow: M[d][c] = sum_e ctx[d][e]*ow[c][h*64+e] ----------
__global__ void __launch_bounds__(256) m_kernel(const float* __restrict__ ow) {
    int h = blockIdx.x & 7, b = blockIdx.x >> 3;
    __shared__ float ctx_s[2048];
    __shared__ float ow_s[64][65];
    int t = threadIdx.x;
    const float* cp = g_ctxp + (long)(b * 8 + h) * 32 * 2048;
    #pragma unroll
    for (int i = 0; i < 8; i++) {
        int idx = t + i * 256;
        float s = 0.f;
        #pragma unroll 8
        for (int ch = 0; ch < 32; ch++) s += cp[(long)ch * 2048 + idx];
        ctx_s[idx] = s;
    }
    #pragma unroll
    for (int i = 0; i < 16; i++) {
        int idx = t + i * 256;
        int c = idx >> 6, e = idx & 63;
        ow_s[c][e] = ow[(long)c * DV + h * 64 + e];
    }
    __syncthreads();
    float* Mp = g_M + (long)(b * 8 + h) * 2048;
    #pragma unroll
    for (int i = 0; i < 8; i++) {
        int idx = t + i * 256;
        int d = idx >> 6, c = idx & 63;
        float s = 0.f;
        #pragma unroll 16
        for (int e = 0; e < 64; e++) s += ctx_s[d * 64 + e] * ow_s[c][e];
        Mp[idx] = s;
    }
}

// ---------- out projection + fused q-softmax + residual ----------
__global__ void __launch_bounds__(256) outproj_kernel(
    const float* __restrict__ noise, const float* __restrict__ ob,
    const float* __restrict__ ga, float* __restrict__ nout) {
    int nt = blockIdx.x, b = blockIdx.y;
    __shared__ float qs[32][132];
    __shared__ float Ms[32][64];
    int t = threadIdx.x;
    int pg = t & 31, cg = t >> 5;
    int n0 = nt * 128;
    ull acc[4][4];          // [px][c-pair]
    #pragma unroll
    for (int i = 0; i < 4; i++)
      #pragma unroll
      for (int j = 0; j < 4; j++) acc[i][j] = 0ull;
    for (int h = 0; h < 8; h++) {
        __syncthreads();
        #pragma unroll
        for (int i = 0; i < 4; i++) { int idx = t + i * 256; int d = idx >> 5, n4 = idx & 31;
            *(float4*)&qs[d][n4 * 4] =
                *(const float4*)(g_q + ((long)(b * DK + h * 32 + d)) * NPIX + n0 + n4 * 4); }
        #pragma unroll
        for (int i = 0; i < 2; i++) { int idx = t + i * 256; int d = idx >> 4, c4 = idx & 15;
            *(float4*)&Ms[d][c4 * 4] =
                *(const float4*)(g_M + ((long)(b * 8 + h)) * 2048 + d * 64 + c4 * 4); }
        __syncthreads();
        if (t < 128) {   // softmax over d=32 for this head, one thread per pixel
            float vv[32]; float mx = -1e30f;
            #pragma unroll
            for (int d = 0; d < 32; d++) { vv[d] = qs[d][t]; mx = fmaxf(mx, vv[d]); }
            float s = 0.f;
            #pragma unroll
            for (int d = 0; d < 32; d++) { vv[d] = __expf(vv[d] - mx); s += vv[d]; }
            float inv = 1.f / s;
            #pragma unroll
            for (int d = 0; d < 32; d++) qs[d][t] = vv[d] * inv;
        }
        __syncthreads();
        #pragma unroll 4
        for (int d = 0; d < 32; d++) {
            float4 q4 = *(float4*)&qs[d][pg * 4];
            ull qb[4] = {pk(q4.x, q4.x), pk(q4.y, q4.y), pk(q4.z, q4.z), pk(q4.w, q4.w)};
            ulonglong2 m01 = *(ulonglong2*)&Ms[d][cg * 8];
            ulonglong2 m23 = *(ulonglong2*)&Ms[d][cg * 8 + 4];
            ull mp[4] = {m01.x, m01.y, m23.x, m23.y};
            #pragma unroll
            for (int p = 0; p < 4; p++)
              #pragma unroll
              for (int cpi = 0; cpi < 4; cpi++) fma2(acc[p][cpi], mp[cpi], qb[p]);
        }
    }
    float gav = ga[0];
    #pragma unroll
    for (int cpi = 0; cpi < 4; cpi++) {
        int c0 = cg * 8 + cpi * 2;
        float ob0 = ob[c0], ob1 = ob[c0 + 1];
        #pragma unroll
        for (int p = 0; p < 4; p++) {
            float2 f = upk(acc[p][cpi]);
            long off0 = ((long)(b * FC + c0)) * NPIX + n0 + pg * 4 + p;
            nout[off0] = noise[off0] + gav * (f.x + ob0);
            long off1 = off0 + NPIX;
            nout[off1] = noise[off1] + gav * (f.y + ob1);
        }
    }
}

// ---------- per-pixel FF (f32x2): x += gf*(f2 @ lrelu(f1 @ x + b1) + b2) ----------
__global__ void __launch_bounds__(128) ff_kernel(
    const float* __restrict__ f1w, const float* __restrict__ f1b,
    const float* __restrict__ f2w, const float* __restrict__ f2b,
    const float* __restrict__ gf, float* __restrict__ xio) {
    __shared__ float f1s[128 * 64];
    __shared__ float f2s[128 * 68];
    __shared__ float b1s[128];
    __shared__ float b2s[64];
    int t = threadIdx.x;
    for (int i = t; i < 8192; i += 128) f1s[i] = f1w[i];
    for (int i = t; i < 8192; i += 128) { int c = i >> 7, j = i & 127; f2s[j * 68 + c] = f2w[i]; }
    b1s[t] = f1b[t];
    if (t < 64) b2s[t] = f2b[t];
    __syncthreads();
    long base = (long)blockIdx.y * FC * NPIX + blockIdx.x * 128 + t;
    ull xp[32], acc[32];
    #pragma unroll
    for (int c2 = 0; c2 < 32; c2++) {
        float a = xio[base + (long)(2 * c2) * NPIX];
        float bq = xio[base + (long)(2 * c2 + 1) * NPIX];
        xp[c2] = pk(a, bq); acc[c2] = 0ull;
    }
    #pragma unroll 2
    for (int j = 0; j < 128; j++) {
        ull d0 = 0ull, d1 = 0ull, d2 = 0ull, d3 = 0ull;
        const ulonglong2* w1p = (const ulonglong2*)(f1s + j * 64);
        #pragma unroll
        for (int i = 0; i < 16; i++) {
            ulonglong2 wv = w1p[i];
            if ((i & 1) == 0) { fma2(d0, wv.x, xp[2 * i]); fma2(d1, wv.y, xp[2 * i + 1]); }
            else              { fma2(d2, wv.x, xp[2 * i]); fma2(d3, wv.y, xp[2 * i + 1]); }
        }
        float2 s0 = upk(d0), s1 = upk(d1), s2 = upk(d2), s3 = upk(d3);
        float hv = b1s[j] + ((s0.x + s0.y) + (s1.x + s1.y)) + ((s2.x + s2.y) + (s3.x + s3.y));
        hv = hv > 0.f ? hv : 0.2f * hv;
        ull hb = pk(hv, hv);
        const ulonglong2* w2p = (const ulonglong2*)(f2s + j * 68);
        #pragma unroll
        for (int i = 0; i < 16; i++) {
            ulonglong2 wv = w2p[i];
            fma2(acc[2 * i], wv.x, hb); fma2(acc[2 * i + 1], wv.y, hb);
        }
    }
    float g = gf[0];
    #pragma unroll
    for (int c2 = 0; c2 < 32; c2++) {
        float2 f = upk(acc[c2]); float2 xv = upk(xp[c2]);
        xio[base + (long)(2 * c2) * NPIX] = xv.x + g * (f.x + b2s[2 * c2]);
        xio[base + (long)(2 * c2 + 1) * NPIX] = xv.y + g * (f.y + b2s[2 * c2 + 1]);
    }
}

// ---------- direct 3x3 conv (f32x2) + add + lrelu; weights [ci][k][co] ----------
template<int CIN>
__global__ void __launch_bounds__(256) conv3_kernel(
    const float* __restrict__ in, const float* __restrict__ wt,
    const float* __restrict__ nadd, float* __restrict__ out) {
    __shared__ float ws[8 * 9 * 64];
    __shared__ float ins[8][18][19];
    int t = threadIdx.x;
    int cg = t >> 6;
    int pg = t & 63;
    int px = (pg & 7) * 2, py = (pg >> 3) * 2;
    int bx = blockIdx.x * 16, by = blockIdx.y * 16, b = blockIdx.z;
    ull acc[4][8];
    #pragma unroll
    for (int i = 0; i < 4; i++)
      #pragma unroll
      for (int j = 0; j < 8; j++) acc[i][j] = 0ull;
    for (int c0 = 0; c0 < CIN; c0 += 8) {
        __syncthreads();
        const float4* wsrc = (const float4*)(wt + (long)c0 * 9 * 64);
        float4* wdst = (float4*)ws;
        for (int i = t; i < 1152; i += 256) wdst[i] = wsrc[i];
        for (int i = t; i < 2592; i += 256) {
            int ci = i / 324, r = i % 324, y = r / 18, xx = r % 18;
            int gy = by + y - 1, gx = bx + xx - 1;
            float v = 0.f;
            if (gy >= 0 && gy < 128 && gx >= 0 && gx < 128)
                v = in[((long)(b * CIN + c0 + ci)) * NPIX + gy * 128 + gx];
            ins[ci][y][xx] = v;
        }
        __syncthreads();
        #pragma unroll
        for (int ci = 0; ci < 8; ci++)
          #pragma unroll
          for (int kk = 0; kk < 9; kk++) {
            int ky = kk / 3, kx = kk % 3;
            float x00 = ins[ci][py + ky][px + kx];
            float x01 = ins[ci][py + ky][px + kx + 1];
            float x10 = ins[ci][py + ky + 1][px + kx];
            float x11 = ins[ci][py + ky + 1][px + kx + 1];
            ull xb[4] = {pk(x00, x00), pk(x01, x01), pk(x10, x10), pk(x11, x11)};
            const ulonglong2* wp = (const ulonglong2*)(ws + (ci * 9 + kk) * 64 + cg * 16);
            ulonglong2 w0 = wp[0], w1 = wp[1], w2 = wp[2], w3 = wp[3];
            ull wpair[8] = {w0.x, w0.y, w1.x, w1.y, w2.x, w2.y, w3.x, w3.y};
            #pragma unroll
            for (int p = 0; p < 4; p++)
              #pragma unroll
              for (int cpi = 0; cpi < 8; cpi++) fma2(acc[p][cpi], wpair[cpi], xb[p]);
          }
    }
    #pragma unroll
    for (int p = 0; p < 4; p++) {
        int gy = by + py + (p >> 1), gx = bx + px + (p & 1);
        long poff = (long)gy * 128 + gx;
        #pragma unroll
        for (int cpi = 0; cpi < 8; cpi++) {
            float2 f = upk(acc[p][cpi]);
            int c0 = cg * 16 + cpi * 2;
            long off0 = ((long)(b * 64 + c0)) * NPIX + poff;
            float v0 = f.x + nadd[off0];
            out[off0] = v0 > 0.f ? v0 : 0.2f * v0;
            long off1 = off0 + NPIX;
            float v1 = f.y + nadd[off1];
            out[off1] = v1 > 0.f ? v1 : 0.2f * v1;
        }
    }
}

// ---------- modulated 1x1 rgb conv + prev_rgb ----------
__global__ void rgb_kernel(const float* __restrict__ xin, const float* __restrict__ prev) {
    int n = blockIdx.x * 256 + threadIdx.x;
    int b = blockIdx.y;
    __shared__ float w[192];
    if (threadIdx.x < 192) w[threadIdx.x] = g_wmod[b * 192 + threadIdx.x];
    __syncthreads();
    float a0 = 0.f, a1 = 0.f, a2 = 0.f;
    for (int c = 0; c < 64; c++) {
        float xv = xin[((long)(b * 64 + c)) * NPIX + n];
        a0 += w[c] * xv; a1 += w[64 + c] * xv; a2 += w[128 + c] * xv;
    }
    g_rgbpre[((long)(b * 3 + 0)) * NPIX + n] = a0 + prev[((long)(b * 3 + 0)) * NPIX + n];
    g_rgbpre[((long)(b * 3 + 1)) * NPIX + n] = a1 + prev[((long)(b * 3 + 1)) * NPIX + n];
    g_rgbpre[((long)(b * 3 + 2)) * NPIX + n] = a2 + prev[((long)(b * 3 + 2)) * NPIX + n];
}

// ---------- normalized [1,2,1] depthwise blur, zero pad ----------
__global__ void blur_kernel(float* __restrict__ out) {
    long i = (long)blockIdx.x * 256 + threadIdx.x;
    int x = (int)(i & 255), y = (int)((i >> 8) & 255);
    long bc = i >> 16;
    const float* p = g_rgbup + bc * 65536;
    float s = 0.f;
    #pragma unroll
    for (int dy = -1; dy <= 1; dy++) {
        int yy = y + dy; if (yy < 0 || yy > 255) continue;
        float wy = (dy == 0) ? 2.f : 1.f;
        #pragma unroll
        for (int dx = -1; dx <= 1; dx++) {
            int xx = x + dx; if (xx < 0 || xx > 255) continue;
            float wx = (dx == 0) ? 2.f : 1.f;
            s += wy * wx * p[yy * 256 + xx];
        }
    }
    out[i] = s * 0.0625f;
}

extern "C" void kernel_launch(void* const* d_in, const int* in_sizes, int n_in,
                              void* d_out, int out_size) {
    const float* x      = (const float*)d_in[0];
    const float* prev   = (const float*)d_in[1];
    const float* istyle = (const float*)d_in[2];
    const float* noise1 = (const float*)d_in[3];
    const float* noise2 = (const float*)d_in[4];
    const float* c1w    = (const float*)d_in[5];
    const float* c2w    = (const float*)d_in[6];
    const float* sw     = (const float*)d_in[7];
    const float* sb     = (const float*)d_in[8];
    const float* rgbw   = (const float*)d_in[9];
    const float* qw     = (const float*)d_in[10];
    const float* kw     = (const float*)d_in[11];
    const float* vw     = (const float*)d_in[12];
    const float* ow     = (const float*)d_in[13];
    const float* ob     = (const float*)d_in[14];
    const float* ga     = (const float*)d_in[15];
    const float* f1w    = (const float*)d_in[16];
    const float* f1b    = (const float*)d_in[17];
    const float* f2w    = (const float*)d_in[18];
    const float* f2b    = (const float*)d_in[19];
    const float* gf     = (const float*)d_in[20];
    float* out = (float*)d_out;
    float* xout = out;
    float* rgbout = out + (long)BB * FC * NPIX;

    float *p_xup, *p_rgbpre, *p_rgbup, *p_n1, *p_n2, *p_xa, *p_w1t, *p_w2t;
    cudaGetSymbolAddress((void**)&p_xup, g_xup);
    cudaGetSymbolAddress((void**)&p_rgbpre, g_rgbpre);
    cudaGetSymbolAddress((void**)&p_rgbup, g_rgbup);
    cudaGetSymbolAddress((void**)&p_n1, g_n1);
    cudaGetSymbolAddress((void**)&p_n2, g_n2);
    cudaGetSymbolAddress((void**)&p_xa, g_xa);
    cudaGetSymbolAddress((void**)&p_w1t, g_w1t);
    cudaGetSymbolAddress((void**)&p_w2t, g_w2t);

    up2_kernel<<<(BB * CIN1 * NPIX) / 256, 256>>>(x, p_xup, CIN1, 64, 64);
    weff_kernel<<<128, 256>>>(c1w, c2w);
    style_kernel<<<BB, 64>>>(istyle, sw, sb, rgbw);

    for (int a = 0; a < 2; a++) {
        const float* noise = a ? noise2 : noise1;
        float* nout = a ? p_n2 : p_n1;
        proj_kernel<<<dim3(128, 16, BB), 128>>>(noise, qw + a * DK * 64, kw + a * DK * 64, vw + a * DV * 64);
        kstat_kernel<<<BB * DK, 256>>>();
        ctx_kernel<<<dim3(32, 8, BB), 128>>>();
        m_kernel<<<BB * 8, 256>>>(ow + a * 64 * DV);
        outproj_kernel<<<dim3(128, BB), 256>>>(noise, ob + a * 64, ga + a, nout);
        ff_kernel<<<dim3(128, BB), 128>>>(f1w + a * 128 * 64, f1b + a * 128,
                                          f2w + a * 64 * 128, f2b + a * 64, gf + a, nout);
    }

    conv3_kernel<CIN1><<<dim3(8, 8, BB), 256>>>(p_xup, p_w1t, p_n1, p_xa);
    conv3_kernel<FC><<<dim3(8, 8, BB), 256>>>(p_xa, p_w2t, p_n2, xout);
    rgb_kernel<<<dim3(NPIX / 256, BB), 256>>>(xout, prev);
    up2_kernel<<<(BB * 3 * 4 * NPIX) / 256, 256>>>(p_rgbpre, p_rgbup, 3, 128, 128);
    blur_kernel<<<(BB * 3 * 4 * NPIX) / 256, 256>>>(rgbout);
}

// round 8
// speedup vs baseline: 1.5504x; 1.1258x over previous
#include <cuda_runtime.h>

#define BB 4
#define FC 64
#define CIN1 128
#define NPIX 16384
#define DK 256
#define DV 512

typedef unsigned long long ull;
typedef unsigned int uint;

__device__ __forceinline__ ull pk(float a, float b) {
    ull r; asm("mov.b64 %0, {%1,%2};" : "=l"(r) : "f"(a), "f"(b)); return r;
}
__device__ __forceinline__ float2 upk(ull v) {
    float2 r; asm("mov.b64 {%0,%1}, %2;" : "=f"(r.x), "=f"(r.y) : "l"(v)); return r;
}
__device__ __forceinline__ void fma2(ull& d, ull a, ull b) {
    asm("fma.rn.f32x2 %0, %1, %2, %0;" : "+l"(d) : "l"(a), "l"(b));
}
__device__ __forceinline__ uint tf32r(float x) {
    uint r; asm("cvt.rna.tf32.f32 %0, %1;" : "=r"(r) : "f"(x)); return r;
}
__device__ __forceinline__ void mma_tf32(float* d, const uint* a, const uint* b) {
    asm volatile("mma.sync.aligned.m16n8k8.row.col.f32.tf32.tf32.f32 "
        "{%0,%1,%2,%3}, {%4,%5,%6,%7}, {%8,%9}, {%0,%1,%2,%3};"
        : "+f"(d[0]), "+f"(d[1]), "+f"(d[2]), "+f"(d[3])
        : "r"(a[0]), "r"(a[1]), "r"(a[2]), "r"(a[3]), "r"(b[0]), "r"(b[1]));
}

__device__ float g_xup[BB*CIN1*NPIX];
__device__ float g_q[BB*DK*NPIX];
__device__ float g_k[BB*DK*NPIX];
__device__ float g_v[BB*DV*NPIX];
__device__ float g_kstat[BB*DK*2];
__device__ float g_ctxp[BB*8*32*2048];
__device__ float g_M[BB*8*2048];
__device__ float g_n1[BB*FC*NPIX];
__device__ float g_n2[BB*FC*NPIX];
__device__ float g_xa[BB*FC*NPIX];
__device__ float g_w1t[(CIN1/8)*9*8*68];
__device__ float g_w2t[(FC/8)*9*8*68];
__device__ float g_wmod[BB*3*FC];
__device__ float g_rgbpre[BB*3*NPIX];
__device__ float g_rgbup[BB*3*4*NPIX];

// ---------- bilinear 2x upsample (half-pixel, edge clamp) ----------
__global__ void up2_kernel(const float* __restrict__ in, float* __restrict__ out,
                           int C, int Hin, int Win) {
    int Ho = Hin * 2, Wo = Win * 2;
    long total = (long)BB * C * Ho * Wo;
    long i = (long)blockIdx.x * blockDim.x + threadIdx.x;
    if (i >= total) return;
    int ox = (int)(i % Wo); long r = i / Wo;
    int oy = (int)(r % Ho); r /= Ho;
    int c = (int)(r % C); int b = (int)(r / C);
    float sy = oy * 0.5f - 0.25f, sx = ox * 0.5f - 0.25f;
    int y0 = (int)floorf(sy), x0 = (int)floorf(sx);
    float wy = sy - (float)y0, wx = sx - (float)x0;
    int y0c = max(y0, 0), y1c = min(y0 + 1, Hin - 1);
    int x0c = max(x0, 0), x1c = min(x0 + 1, Win - 1);
    const float* p = in + ((long)b * C + c) * Hin * Win;
    float v00 = p[y0c * Win + x0c], v01 = p[y0c * Win + x1c];
    float v10 = p[y1c * Win + x0c], v11 = p[y1c * Win + x1c];
    out[i] = (1.f - wy) * ((1.f - wx) * v00 + wx * v01) + wy * ((1.f - wx) * v10 + wx * v11);
}

// ---------- demodulated conv weights (style=ones), layout [cblk][kk][8ci][68co], tf32 ----------
__global__ void weff_kernel(const float* __restrict__ w1, const float* __restrict__ w2) {
    int co = blockIdx.x;
    const float* w; float* wo; int len;
    if (co < 64) { w = w1 + (long)co * CIN1 * 9; wo = g_w1t; len = CIN1 * 9; }
    else { co -= 64; w = w2 + (long)co * FC * 9; wo = g_w2t; len = FC * 9; }
    __shared__ float red[256];
    float s = 0.f;
    for (int i = threadIdx.x; i < len; i += 256) { float v = w[i]; s += v * v; }
    red[threadIdx.x] = s; __syncthreads();
    for (int o = 128; o > 0; o >>= 1) { if (threadIdx.x < o) red[threadIdx.x] += red[threadIdx.x + o]; __syncthreads(); }
    float sc = 2.f * rsqrtf(4.f * red[0] + 1e-8f);
    for (int i = threadIdx.x; i < len; i += 256) {
        int ci = i / 9, kk = i % 9;
        uint rv = tf32r(w[i] * sc);
        wo[(((ci >> 3) * 9 + kk) * 8 + (ci & 7)) * 68 + co] = __uint_as_float(rv);
    }
}

// ---------- style -> modulated 1x1 rgb weights ----------
__global__ void style_kernel(const float* __restrict__ istyle, const float* __restrict__ sw,
                             const float* __restrict__ sb, const float* __restrict__ rgbw) {
    int f = threadIdx.x, b = blockIdx.x;
    float s = sb[f];
    for (int l = 0; l < 512; l++) s += istyle[b * 512 + l] * sw[f * 512 + l];
    s += 1.f;
    for (int co = 0; co < 3; co++) g_wmod[(b * 3 + co) * 64 + f] = rgbw[co * 64 + f] * s;
}

// ---------- QKV projection GEMM via tf32 mma: 64 rows x 128 px per block ----------
__global__ void __launch_bounds__(128) proj_kernel(
    const float* __restrict__ noise, const float* __restrict__ qw,
    const float* __restrict__ kw, const float* __restrict__ vw) {
    __shared__ float Ws[64][68];      // [k][row], tf32-rounded
    __shared__ float Xs[64][136];     // [k][n], tf32-rounded
    int nt = blockIdx.x, rt = blockIdx.y, b = blockIdx.z;
    int t = threadIdx.x, n0 = nt * 128;
    int w = t >> 5, lane = t & 31, g = lane >> 2, tq = lane & 3;
    const float* wsrc; float* dst; float sc;
    const float SCALE = 0.42044820762685725f; // 32^-0.25
    if (rt < 4)      { wsrc = qw + rt * 64 * 64;       dst = g_q + ((long)b * DK + rt * 64) * NPIX;       sc = SCALE; }
    else if (rt < 8) { wsrc = kw + (rt - 4) * 64 * 64; dst = g_k + ((long)b * DK + (rt - 4) * 64) * NPIX; sc = SCALE; }
    else             { wsrc = vw + (rt - 8) * 64 * 64; dst = g_v + ((long)b * DV + (rt - 8) * 64) * NPIX; sc = 1.f; }
    {   // transpose-load weights, tf32 round
        int r = t >> 1, k0 = (t & 1) * 32;
        const float4* s4 = (const float4*)(wsrc + r * 64 + k0);
        #pragma unroll
        for (int i = 0; i < 8; i++) {
            float4 wv = s4[i]; int kk = k0 + i * 4;
            Ws[kk][r]     = __uint_as_float(tf32r(wv.x));
            Ws[kk + 1][r] = __uint_as_float(tf32r(wv.y));
            Ws[kk + 2][r] = __uint_as_float(tf32r(wv.z));
            Ws[kk + 3][r] = __uint_as_float(tf32r(wv.w));
        }
    }
    #pragma unroll
    for (int i = 0; i < 16; i++) { int idx = t + i * 128; int c = idx >> 5, n4 = idx & 31;
      float4 xv = *(const float4*)(noise + ((long)b * FC + c) * NPIX + n0 + n4 * 4);
      float4 rv = make_float4(__uint_as_float(tf32r(xv.x)), __uint_as_float(tf32r(xv.y)),
                              __uint_as_float(tf32r(xv.z)), __uint_as_float(tf32r(xv.w)));
      *(float4*)&Xs[c][n4 * 4] = rv; }
    __syncthreads();
    int wb = w * 16;
    float acc[16][4];
    #pragma unroll
    for (int j = 0; j < 16; j++)
      #pragma unroll
      for (int i = 0; i < 4; i++) acc[j][i] = 0.f;
    #pragma unroll
    for (int ks = 0; ks < 8; ks++) {
        uint a[4];
        a[0] = __float_as_uint(Ws[ks * 8 + tq][wb + g]);
        a[1] = __float_as_uint(Ws[ks * 8 + tq][wb + g + 8]);
        a[2] = __float_as_uint(Ws[ks * 8 + tq + 4][wb + g]);
        a[3] = __float_as_uint(Ws[ks * 8 + tq + 4][wb + g + 8]);
        #pragma unroll
        for (int j = 0; j < 16; j++) {
            uint bfr[2];
            bfr[0] = __float_as_uint(Xs[ks * 8 + tq][j * 8 + g]);
            bfr[1] = __float_as_uint(Xs[ks * 8 + tq + 4][j * 8 + g]);
            mma_tf32(acc[j], a, bfr);
        }
    }
    #pragma unroll
    for (int j = 0; j < 16; j++) {
        int n = n0 + j * 8 + 2 * tq;
        long r0 = (long)(wb + g) * NPIX + n;
        long r1 = (long)(wb + g + 8) * NPIX + n;
        *(float2*)(dst + r0) = make_float2(acc[j][0] * sc, acc[j][1] * sc);
        *(float2*)(dst + r1) = make_float2(acc[j][2] * sc, acc[j][3] * sc);
    }
}

// ---------- k softmax stats per row: (max, 1/sum(exp)) ----------
__global__ void __launch_bounds__(256) kstat_kernel() {
    __shared__ float red[256];
    int t = threadIdx.x;
    const float* p = g_k + (long)blockIdx.x * NPIX;
    float v[64]; float mx = -1e30f;
    #pragma unroll
    for (int i = 0; i < 64; i++) { v[i] = p[t + i * 256]; mx = fmaxf(mx, v[i]); }
    red[t] = mx; __syncthreads();
    for (int o = 128; o > 0; o >>= 1) { if (t < o) red[t] = fmaxf(red[t], red[t + o]); __syncthreads(); }
    mx = red[0]; __syncthreads();
    float s = 0.f;
    #pragma unroll
    for (int i = 0; i < 64; i++) s += __expf(v[i] - mx);
    red[t] = s; __syncthreads();
    for (int o = 128; o > 0; o >>= 1) { if (t < o) red[t] += red[t + o]; __syncthreads(); }
    if (t == 0) { g_kstat[blockIdx.x * 2] = mx; g_kstat[blockIdx.x * 2 + 1] = 1.f / red[0]; }
}

// ---------- ctx partial with fused k-softmax ----------
__global__ void __launch_bounds__(128) ctx_kernel() {
    int ch = blockIdx.x, h = blockIdx.y, b = blockIdx.z;
    __shared__ float ks[32][64];
    __shared__ float vs[64][68];
    __shared__ float smx[32], sinv[32];
    int t = threadIdx.x;
    int dg = t >> 4, eg = t & 15;
    if (t < 32) {
        smx[t] = g_kstat[(b * DK + h * 32 + t) * 2];
        sinv[t] = g_kstat[(b * DK + h * 32 + t) * 2 + 1];
    }
    float acc[4][4];
    #pragma unroll
    for (int i = 0; i < 4; i++)
      #pragma unroll
      for (int j = 0; j < 4; j++) acc[i][j] = 0.f;
    const float* kbase = g_k + ((long)(b * DK + h * 32)) * NPIX + ch * 512;
    const float* vbase = g_v + ((long)(b * DV + h * 64)) * NPIX + ch * 512;
    for (int n0 = 0; n0 < 512; n0 += 64) {
        __syncthreads();
        #pragma unroll
        for (int i = 0; i < 4; i++) { int idx = t + i * 128; int d = idx >> 4, n4 = idx & 15;
            float4 kk = *(const float4*)(kbase + (long)d * NPIX + n0 + n4 * 4);
            float m = smx[d], iv = sinv[d];
            kk.x = __expf(kk.x - m) * iv; kk.y = __expf(kk.y - m) * iv;
            kk.z = __expf(kk.z - m) * iv; kk.w = __expf(kk.w - m) * iv;
            *(float4*)&ks[d][n4 * 4] = kk; }
        #pragma unroll
        for (int i = 0; i < 8; i++) { int idx = t + i * 128; int e = idx >> 4, n4 = idx & 15;
            float4 vv = *(const float4*)(vbase + (long)e * NPIX + n0 + n4 * 4);
            vs[n4 * 4 + 0][e] = vv.x; vs[n4 * 4 + 1][e] = vv.y;
            vs[n4 * 4 + 2][e] = vv.z; vs[n4 * 4 + 3][e] = vv.w; }
        __syncthreads();
        #pragma unroll 8
        for (int n = 0; n < 64; n++) {
            float4 ve = *(float4*)&vs[n][eg * 4];
            #pragma unroll
            for (int i = 0; i < 4; i++) {
                float kd = ks[dg * 4 + i][n];
                acc[i][0] += kd * ve.x; acc[i][1] += kd * ve.y;
                acc[i][2] += kd * ve.z; acc[i][3] += kd * ve.w;
            }
        }
    }
    float* outp = g_ctxp + ((long)(b * 8 + h) * 32 + ch) * 2048;
    #pragma unroll
    for (int i = 0; i < 4; i++)
      #pragma unroll
      for (int j = 0; j < 4; j++)
        outp[(dg * 4 + i) * 64 + eg * 4 + j] = acc[i][j];
}

// ---------- reduce ctx chunks, fold with ow ----------
__global__ void __launch_bounds__(256) m_kernel(const float* __restrict__ ow) {
    int h = blockIdx.x & 7, b = blockIdx.x >> 3;
    __shared__ float ctx_s[2048];
    __shared__ float ow_s[64][65];
    int t = threadIdx.x;
    const float* cp = g_ctxp + (long)(b * 8 + h) * 32 * 2048;
    #pragma unroll
    for (int i = 0; i < 8; i++) {
        int idx = t + i * 256;
        float s = 0.f;
        #pragma unroll 8
        for (int ch = 0; ch < 32; ch++) s += cp[(long)ch * 2048 + idx];
        ctx_s[idx] = s;
    }
    #pragma unroll
    for (int i = 0; i < 16; i++) {
        int idx = t + i * 256;
        int c = idx >> 6, e = idx & 63;
        ow_s[c][e] = ow[(long)c * DV + h * 64 + e];
    }
    __syncthreads();
    float* Mp = g_M + (long)(b * 8 + h) * 2048;
    #pragma unroll
    for (int i = 0; i < 8; i++) {
        int idx = t + i * 256;
        int d = idx >> 6, c = idx & 63;
        float s = 0.f;
        #pragma unroll 16
        for (int e = 0; e < 64; e++) s += ctx_s[d * 64 + e] * ow_s[c][e];
        Mp[idx] = s;
    }
}

// ---------- out projection + fused q-softmax + residual ----------
__global__ void __launch_bounds__(256) outproj_kernel(
    const float* __restrict__ noise, const float* __restrict__ ob,
    const float* __restrict__ ga, float* __restrict__ nout) {
    int nt = blockIdx.x, b = blockIdx.y;
    __shared__ float qs[32][132];
    __shared__ float Ms[32][64];
    int t = threadIdx.x;
    int pg = t & 31, cg = t >> 5;
    int n0 = nt * 128;
    ull acc[4][4];
    #pragma unroll
    for (int i = 0; i < 4; i++)
      #pragma unroll
      for (int j = 0; j < 4; j++) acc[i][j] = 0ull;
    for (int h = 0; h < 8; h++) {
        __syncthreads();
        #pragma unroll
        for (int i = 0; i < 4; i++) { int idx = t + i * 256; int d = idx >> 5, n4 = idx & 31;
            *(float4*)&qs[d][n4 * 4] =
                *(const float4*)(g_q + ((long)(b * DK + h * 32 + d)) * NPIX + n0 + n4 * 4); }
        #pragma unroll
        for (int i = 0; i < 2; i++) { int idx = t + i * 256; int d = idx >> 4, c4 = idx & 15;
            *(float4*)&Ms[d][c4 * 4] =
                *(const float4*)(g_M + ((long)(b * 8 + h)) * 2048 + d * 64 + c4 * 4); }
        __syncthreads();
        if (t < 128) {
            float vv[32]; float mx = -1e30f;
            #pragma unroll
            for (int d = 0; d < 32; d++) { vv[d] = qs[d][t]; mx = fmaxf(mx, vv[d]); }
            float s = 0.f;
            #pragma unroll
            for (int d = 0; d < 32; d++) { vv[d] = __expf(vv[d] - mx); s += vv[d]; }
            float inv = 1.f / s;
            #pragma unroll
            for (int d = 0; d < 32; d++) qs[d][t] = vv[d] * inv;
        }
        __syncthreads();
        #pragma unroll 4
        for (int d = 0; d < 32; d++) {
            float4 q4 = *(float4*)&qs[d][pg * 4];
            ull qb[4] = {pk(q4.x, q4.x), pk(q4.y, q4.y), pk(q4.z, q4.z), pk(q4.w, q4.w)};
            ulonglong2 m01 = *(ulonglong2*)&Ms[d][cg * 8];
            ulonglong2 m23 = *(ulonglong2*)&Ms[d][cg * 8 + 4];
            ull mp[4] = {m01.x, m01.y, m23.x, m23.y};
            #pragma unroll
            for (int p = 0; p < 4; p++)
              #pragma unroll
              for (int cpi = 0; cpi < 4; cpi++) fma2(acc[p][cpi], mp[cpi], qb[p]);
        }
    }
    float gav = ga[0];
    #pragma unroll
    for (int cpi = 0; cpi < 4; cpi++) {
        int c0 = cg * 8 + cpi * 2;
        float ob0 = ob[c0], ob1 = ob[c0 + 1];
        #pragma unroll
        for (int p = 0; p < 4; p++) {
            float2 f = upk(acc[p][cpi]);
            long off0 = ((long)(b * FC + c0)) * NPIX + n0 + pg * 4 + p;
            nout[off0] = noise[off0] + gav * (f.x + ob0);
            long off1 = off0 + NPIX;
            nout[off1] = noise[off1] + gav * (f.y + ob1);
        }
    }
}

// ---------- per-pixel FF (f32x2) ----------
__global__ void __launch_bounds__(128) ff_kernel(
    const float* __restrict__ f1w, const float* __restrict__ f1b,
    const float* __restrict__ f2w, const float* __restrict__ f2b,
    const float* __restrict__ gf, float* __restrict__ xio) {
    __shared__ float f1s[128 * 64];
    __shared__ float f2s[128 * 68];
    __shared__ float b1s[128];
    __shared__ float b2s[64];
    int t = threadIdx.x;
    for (int i = t; i < 8192; i += 128) f1s[i] = f1w[i];
    for (int i = t; i < 8192; i += 128) { int c = i >> 7, j = i & 127; f2s[j * 68 + c] = f2w[i]; }
    b1s[t] = f1b[t];
    if (t < 64) b2s[t] = f2b[t];
    __syncthreads();
    long base = (long)blockIdx.y * FC * NPIX + blockIdx.x * 128 + t;
    ull xp[32], acc[32];
    #pragma unroll
    for (int c2 = 0; c2 < 32; c2++) {
        float a = xio[base + (long)(2 * c2) * NPIX];
        float bq = xio[base + (long)(2 * c2 + 1) * NPIX];
        xp[c2] = pk(a, bq); acc[c2] = 0ull;
    }
    #pragma unroll 2
    for (int j = 0; j < 128; j++) {
        ull d0 = 0ull, d1 = 0ull, d2 = 0ull, d3 = 0ull;
        const ulonglong2* w1p = (const ulonglong2*)(f1s + j * 64);
        #pragma unroll
        for (int i = 0; i < 16; i++) {
            ulonglong2 wv = w1p[i];
            if ((i & 1) == 0) { fma2(d0, wv.x, xp[2 * i]); fma2(d1, wv.y, xp[2 * i + 1]); }
            else              { fma2(d2, wv.x, xp[2 * i]); fma2(d3, wv.y, xp[2 * i + 1]); }
        }
        float2 s0 = upk(d0), s1 = upk(d1), s2 = upk(d2), s3 = upk(d3);
        float hv = b1s[j] + ((s0.x + s0.y) + (s1.x + s1.y)) + ((s2.x + s2.y) + (s3.x + s3.y));
        hv = hv > 0.f ? hv : 0.2f * hv;
        ull hb = pk(hv, hv);
        const ulonglong2* w2p = (const ulonglong2*)(f2s + j * 68);
        #pragma unroll
        for (int i = 0; i < 16; i++) {
            ulonglong2 wv = w2p[i];
            fma2(acc[2 * i], wv.x, hb); fma2(acc[2 * i + 1], wv.y, hb);
        }
    }
    float g = gf[0];
    #pragma unroll
    for (int c2 = 0; c2 < 32; c2++) {
        float2 f = upk(acc[c2]); float2 xv = upk(xp[c2]);
        xio[base + (long)(2 * c2) * NPIX] = xv.x + g * (f.x + b2s[2 * c2]);
        xio[base + (long)(2 * c2 + 1) * NPIX] = xv.y + g * (f.y + b2s[2 * c2 + 1]);
    }
}

// ---------- 3x3 conv via tf32 mma (implicit GEMM) + add + lrelu ----------
template<int CIN>
__global__ void __launch_bounds__(256) conv3_kernel(
    const float* __restrict__ in, const float* __restrict__ wt,
    const float* __restrict__ nadd, float* __restrict__ out) {
    __shared__ float ws[9 * 8 * 68];      // [kk][8ci][68co], tf32
    __shared__ float ins[8][18][20];      // haloed tile, tf32
    int t = threadIdx.x;
    int w = t >> 5, lane = t & 31, g = lane >> 2, tq = lane & 3;
    int mt = w & 3, yh = w >> 2;          // m-tile (16 co), y-half (8 rows of px)
    int wb = mt * 16;
    int bx = blockIdx.x * 16, by = blockIdx.y * 16, b = blockIdx.z;
    float acc[16][4];
    #pragma unroll
    for (int j = 0; j < 16; j++)
      #pragma unroll
      for (int i = 0; i < 4; i++) acc[j][i] = 0.f;
    for (int c0 = 0; c0 < CIN; c0 += 8) {
        __syncthreads();
        {   // copy weight block (already tf32 + padded)
            const float4* wsrc = (const float4*)(wt + (long)(c0 >> 3) * 9 * 544);
            float4* wdst = (float4*)ws;
            for (int i = t; i < 1224; i += 256) wdst[i] = wsrc[i];
        }
        for (int i = t; i < 2592; i += 256) {
            int ci = i / 324, r = i % 324, y = r / 18, xx = r % 18;
            int gy = by + y - 1, gx = bx + xx - 1;
            float v = 0.f;
            if (gy >= 0 && gy < 128 && gx >= 0 && gx < 128)
                v = in[((long)(b * CIN + c0 + ci)) * NPIX + gy * 128 + gx];
            ins[ci][y][xx] = __uint_as_float(tf32r(v));
        }
        __syncthreads();
        #pragma unroll
        for (int kk = 0; kk < 9; kk++) {
            int ky = kk / 3, kx = kk % 3;
            uint a[4];
            a[0] = __float_as_uint(ws[kk * 544 + tq * 68 + wb + g]);
            a[1] = __float_as_uint(ws[kk * 544 + tq * 68 + wb + g + 8]);
            a[2] = __float_as_uint(ws[kk * 544 + (tq + 4) * 68 + wb + g]);
            a[3] = __float_as_uint(ws[kk * 544 + (tq + 4) * 68 + wb + g + 8]);
            #pragma unroll
            for (int j = 0; j < 16; j++) {
                int y = (j >> 1) + yh * 8 + ky;
                int x = (j & 1) * 8 + g + kx;
                uint bfr[2];
                bfr[0] = __float_as_uint(ins[tq][y][x]);
                bfr[1] = __float_as_uint(ins[tq + 4][y][x]);
                mma_tf32(acc[j], a, bfr);
            }
        }
    }
    #pragma unroll
    for (int j = 0; j < 16; j++) {
        int y = (j >> 1) + yh * 8;
        int x = (j & 1) * 8 + 2 * tq;
        long poff = (long)(by + y) * 128 + bx + x;
        long off0 = ((long)(b * 64 + wb + g)) * NPIX + poff;
        long off1 = ((long)(b * 64 + wb + g + 8)) * NPIX + poff;
        float2 n0v = *(const float2*)(nadd + off0);
        float2 n1v = *(const float2*)(nadd + off1);
        float v0 = acc[j][0] + n0v.x, v1 = acc[j][1] + n0v.y;
        float v2 = acc[j][2] + n1v.x, v3 = acc[j][3] + n1v.y;
        v0 = v0 > 0.f ? v0 : 0.2f * v0; v1 = v1 > 0.f ? v1 : 0.2f * v1;
        v2 = v2 > 0.f ? v2 : 0.2f * v2; v3 = v3 > 0.f ? v3 : 0.2f * v3;
        *(float2*)(out + off0) = make_float2(v0, v1);
        *(float2*)(out + off1) = make_float2(v2, v3);
    }
}

// ---------- modulated 1x1 rgb conv + prev_rgb ----------
__global__ void rgb_kernel(const float* __restrict__ xin, const float* __restrict__ prev) {
    int n = blockIdx.x * 256 + threadIdx.x;
    int b = blockIdx.y;
    __shared__ float w[192];
    if (threadIdx.x < 192) w[threadIdx.x] = g_wmod[b * 192 + threadIdx.x];
    __syncthreads();
    float a0 = 0.f, a1 = 0.f, a2 = 0.f;
    for (int c = 0; c < 64; c++) {
        float xv = xin[((long)(b * 64 + c)) * NPIX + n];
        a0 += w[c] * xv; a1 += w[64 + c] * xv; a2 += w[128 + c] * xv;
    }
    g_rgbpre[((long)(b * 3 + 0)) * NPIX + n] = a0 + prev[((long)(b * 3 + 0)) * NPIX + n];
    g_rgbpre[((long)(b * 3 + 1)) * NPIX + n] = a1 + prev[((long)(b * 3 + 1)) * NPIX + n];
    g_rgbpre[((long)(b * 3 + 2)) * NPIX + n] = a2 + prev[((long)(b * 3 + 2)) * NPIX + n];
}

// ---------- normalized [1,2,1] depthwise blur, zero pad ----------
__global__ void blur_kernel(float* __restrict__ out) {
    long i = (long)blockIdx.x * 256 + threadIdx.x;
    int x = (int)(i & 255), y = (int)((i >> 8) & 255);
    long bc = i >> 16;
    const float* p = g_rgbup + bc * 65536;
    float s = 0.f;
    #pragma unroll
    for (int dy = -1; dy <= 1; dy++) {
        int yy = y + dy; if (yy < 0 || yy > 255) continue;
        float wy = (dy == 0) ? 2.f : 1.f;
        #pragma unroll
        for (int dx = -1; dx <= 1; dx++) {
            int xx = x + dx; if (xx < 0 || xx > 255) continue;
            float wx = (dx == 0) ? 2.f : 1.f;
            s += wy * wx * p[yy * 256 + xx];
        }
    }
    out[i] = s * 0.0625f;
}

extern "C" void kernel_launch(void* const* d_in, const int* in_sizes, int n_in,
                              void* d_out, int out_size) {
    const float* x      = (const float*)d_in[0];
    const float* prev   = (const float*)d_in[1];
    const float* istyle = (const float*)d_in[2];
    const float* noise1 = (const float*)d_in[3];
    const float* noise2 = (const float*)d_in[4];
    const float* c1w    = (const float*)d_in[5];
    const float* c2w    = (const float*)d_in[6];
    const float* sw     = (const float*)d_in[7];
    const float* sb     = (const float*)d_in[8];
    const float* rgbw   = (const float*)d_in[9];
    const float* qw     = (const float*)d_in[10];
    const float* kw     = (const float*)d_in[11];
    const float* vw     = (const float*)d_in[12];
    const float* ow     = (const float*)d_in[13];
    const float* ob     = (const float*)d_in[14];
    const float* ga     = (const float*)d_in[15];
    const float* f1w    = (const float*)d_in[16];
    const float* f1b    = (const float*)d_in[17];
    const float* f2w    = (const float*)d_in[18];
    const float* f2b    = (const float*)d_in[19];
    const float* gf     = (const float*)d_in[20];
    float* out = (float*)d_out;
    float* xout = out;
    float* rgbout = out + (long)BB * FC * NPIX;

    float *p_xup, *p_rgbpre, *p_rgbup, *p_n1, *p_n2, *p_xa, *p_w1t, *p_w2t;
    cudaGetSymbolAddress((void**)&p_xup, g_xup);
    cudaGetSymbolAddress((void**)&p_rgbpre, g_rgbpre);
    cudaGetSymbolAddress((void**)&p_rgbup, g_rgbup);
    cudaGetSymbolAddress((void**)&p_n1, g_n1);
    cudaGetSymbolAddress((void**)&p_n2, g_n2);
    cudaGetSymbolAddress((void**)&p_xa, g_xa);
    cudaGetSymbolAddress((void**)&p_w1t, g_w1t);
    cudaGetSymbolAddress((void**)&p_w2t, g_w2t);

    up2_kernel<<<(BB * CIN1 * NPIX) / 256, 256>>>(x, p_xup, CIN1, 64, 64);
    weff_kernel<<<128, 256>>>(c1w, c2w);
    style_kernel<<<BB, 64>>>(istyle, sw, sb, rgbw);

    for (int a = 0; a < 2; a++) {
        const float* noise = a ? noise2 : noise1;
        float* nout = a ? p_n2 : p_n1;
        proj_kernel<<<dim3(128, 16, BB), 128>>>(noise, qw + a * DK * 64, kw + a * DK * 64, vw + a * DV * 64);
        kstat_kernel<<<BB * DK, 256>>>();
        ctx_kernel<<<dim3(32, 8, BB), 128>>>();
        m_kernel<<<BB * 8, 256>>>(ow + a * 64 * DV);
        outproj_kernel<<<dim3(128, BB), 256>>>(noise, ob + a * 64, ga + a, nout);
        ff_kernel<<<dim3(128, BB), 128>>>(f1w + a * 128 * 64, f1b + a * 128,
                                          f2w + a * 64 * 128, f2b + a * 64, gf + a, nout);
    }

    conv3_kernel<CIN1><<<dim3(8, 8, BB), 256>>>(p_xup, p_w1t, p_n1, p_xa);
    conv3_kernel<FC><<<dim3(8, 8, BB), 256>>>(p_xa, p_w2t, p_n2, xout);
    rgb_kernel<<<dim3(NPIX / 256, BB), 256>>>(xout, prev);
    up2_kernel<<<(BB * 3 * 4 * NPIX) / 256, 256>>>(p_rgbpre, p_rgbup, 3, 128, 128);
    blur_kernel<<<(BB * 3 * 4 * NPIX) / 256, 256>>>(rgbout);
}

// round 10
// speedup vs baseline: 1.5905x; 1.0259x over previous
#include <cuda_runtime.h>

#define BB 4
#define FC 64
#define CIN1 128
#define NPIX 16384
#define DK 256
#define DV 512

typedef unsigned long long ull;
typedef unsigned int uint;

__device__ __forceinline__ ull pk(float a, float b) {
    ull r; asm("mov.b64 %0, {%1,%2};" : "=l"(r) : "f"(a), "f"(b)); return r;
}
__device__ __forceinline__ float2 upk(ull v) {
    float2 r; asm("mov.b64 {%0,%1}, %2;" : "=f"(r.x), "=f"(r.y) : "l"(v)); return r;
}
__device__ __forceinline__ void fma2(ull& d, ull a, ull b) {
    asm("fma.rn.f32x2 %0, %1, %2, %0;" : "+l"(d) : "l"(a), "l"(b));
}
__device__ __forceinline__ uint tf32r(float x) {
    uint r; asm("cvt.rna.tf32.f32 %0, %1;" : "=r"(r) : "f"(x)); return r;
}
__device__ __forceinline__ float tf32f(float x) { return __uint_as_float(tf32r(x)); }
__device__ __forceinline__ void mma_tf32(float* d, const uint* a, const uint* b) {
    asm volatile("mma.sync.aligned.m16n8k8.row.col.f32.tf32.tf32.f32 "
        "{%0,%1,%2,%3}, {%4,%5,%6,%7}, {%8,%9}, {%0,%1,%2,%3};"
        : "+f"(d[0]), "+f"(d[1]), "+f"(d[2]), "+f"(d[3])
        : "r"(a[0]), "r"(a[1]), "r"(a[2]), "r"(a[3]), "r"(b[0]), "r"(b[1]));
}

__device__ float g_xup[BB*CIN1*NPIX];
__device__ float g_q[BB*DK*NPIX];
__device__ float g_k[BB*DK*NPIX];
__device__ float g_v[BB*DV*NPIX];
__device__ float g_kstat[BB*DK*2];
__device__ float g_ctxp[BB*8*32*2048];
__device__ float g_M[BB*8*2048];
__device__ float g_n1[BB*FC*NPIX];
__device__ float g_n2[BB*FC*NPIX];
__device__ float g_xa[BB*FC*NPIX];
__device__ float g_w1t[(CIN1/8)*9*8*68];
__device__ float g_w2t[(FC/8)*9*8*68];
__device__ float g_wmod[BB*3*FC];
__device__ float g_rgbpre[BB*3*NPIX];
__device__ float g_rgbup[BB*3*4*NPIX];

// ---------- bilinear 2x upsample (half-pixel, edge clamp) ----------
__global__ void up2_kernel(const float* __restrict__ in, float* __restrict__ out,
                           int C, int Hin, int Win) {
    int Ho = Hin * 2, Wo = Win * 2;
    long total = (long)BB * C * Ho * Wo;
    long i = (long)blockIdx.x * blockDim.x + threadIdx.x;
    if (i >= total) return;
    int ox = (int)(i % Wo); long r = i / Wo;
    int oy = (int)(r % Ho); r /= Ho;
    int c = (int)(r % C); int b = (int)(r / C);
    float sy = oy * 0.5f - 0.25f, sx = ox * 0.5f - 0.25f;
    int y0 = (int)floorf(sy), x0 = (int)floorf(sx);
    float wy = sy - (float)y0, wx = sx - (float)x0;
    int y0c = max(y0, 0), y1c = min(y0 + 1, Hin - 1);
    int x0c = max(x0, 0), x1c = min(x0 + 1, Win - 1);
    const float* p = in + ((long)b * C + c) * Hin * Win;
    float v00 = p[y0c * Win + x0c], v01 = p[y0c * Win + x1c];
    float v10 = p[y1c * Win + x0c], v11 = p[y1c * Win + x1c];
    out[i] = (1.f - wy) * ((1.f - wx) * v00 + wx * v01) + wy * ((1.f - wx) * v10 + wx * v11);
}

// ---------- demodulated conv weights (style=ones), layout [cblk][kk][8ci][68co], tf32 ----------
__global__ void weff_kernel(const float* __restrict__ w1, const float* __restrict__ w2) {
    int co = blockIdx.x;
    const float* w; float* wo; int len;
    if (co < 64) { w = w1 + (long)co * CIN1 * 9; wo = g_w1t; len = CIN1 * 9; }
    else { co -= 64; w = w2 + (long)co * FC * 9; wo = g_w2t; len = FC * 9; }
    __shared__ float red[256];
    float s = 0.f;
    for (int i = threadIdx.x; i < len; i += 256) { float v = w[i]; s += v * v; }
    red[threadIdx.x] = s; __syncthreads();
    for (int o = 128; o > 0; o >>= 1) { if (threadIdx.x < o) red[threadIdx.x] += red[threadIdx.x + o]; __syncthreads(); }
    float sc = 2.f * rsqrtf(4.f * red[0] + 1e-8f);
    for (int i = threadIdx.x; i < len; i += 256) {
        int ci = i / 9, kk = i % 9;
        wo[(((ci >> 3) * 9 + kk) * 8 + (ci & 7)) * 68 + co] = tf32f(w[i] * sc);
    }
}

// ---------- style -> modulated 1x1 rgb weights ----------
__global__ void style_kernel(const float* __restrict__ istyle, const float* __restrict__ sw,
                             const float* __restrict__ sb, const float* __restrict__ rgbw) {
    int f = threadIdx.x, b = blockIdx.x;
    float s = sb[f];
    for (int l = 0; l < 512; l++) s += istyle[b * 512 + l] * sw[f * 512 + l];
    s += 1.f;
    for (int co = 0; co < 3; co++) g_wmod[(b * 3 + co) * 64 + f] = rgbw[co * 64 + f] * s;
}

// ---------- QKV projection GEMM via tf32 mma: warp = n-quarter x all m ----------
__global__ void __launch_bounds__(128) proj_kernel(
    const float* __restrict__ noise, const float* __restrict__ qw,
    const float* __restrict__ kw, const float* __restrict__ vw) {
    __shared__ float Ws[64][72];      // [k][m], tf32
    __shared__ float Xs[64][136];     // [k][n], tf32
    int nt0 = blockIdx.x, rt = blockIdx.y, b = blockIdx.z;
    int t = threadIdx.x, n0 = nt0 * 128;
    int w = t >> 5, lane = t & 31, g = lane >> 2, tq = lane & 3;
    const float* wsrc; float* dst; float sc;
    const float SCALE = 0.42044820762685725f; // 32^-0.25
    if (rt < 4)      { wsrc = qw + rt * 64 * 64;       dst = g_q + ((long)b * DK + rt * 64) * NPIX;       sc = SCALE; }
    else if (rt < 8) { wsrc = kw + (rt - 4) * 64 * 64; dst = g_k + ((long)b * DK + (rt - 4) * 64) * NPIX; sc = SCALE; }
    else             { wsrc = vw + (rt - 8) * 64 * 64; dst = g_v + ((long)b * DV + (rt - 8) * 64) * NPIX; sc = 1.f; }
    {   // transpose-load weights, tf32 round
        int r = t >> 1, k0 = (t & 1) * 32;
        const float4* s4 = (const float4*)(wsrc + r * 64 + k0);
        #pragma unroll
        for (int i = 0; i < 8; i++) {
            float4 wv = s4[i]; int kk = k0 + i * 4;
            Ws[kk][r] = tf32f(wv.x); Ws[kk + 1][r] = tf32f(wv.y);
            Ws[kk + 2][r] = tf32f(wv.z); Ws[kk + 3][r] = tf32f(wv.w);
        }
    }
    #pragma unroll
    for (int i = 0; i < 16; i++) { int idx = t + i * 128; int c = idx >> 5, n4 = idx & 31;
      float4 xv = *(const float4*)(noise + ((long)b * FC + c) * NPIX + n0 + n4 * 4);
      *(float4*)&Xs[c][n4 * 4] = make_float4(tf32f(xv.x), tf32f(xv.y), tf32f(xv.z), tf32f(xv.w)); }
    __syncthreads();
    float acc[4][4][4];
    #pragma unroll
    for (int mt = 0; mt < 4; mt++)
      #pragma unroll
      for (int nt = 0; nt < 4; nt++)
        #pragma unroll
        for (int i = 0; i < 4; i++) acc[mt][nt][i] = 0.f;
    #pragma unroll
    for (int ks = 0; ks < 8; ks++) {
        uint bf[4][2];
        #pragma unroll
        for (int nt = 0; nt < 4; nt++) {
            bf[nt][0] = __float_as_uint(Xs[ks * 8 + tq][w * 32 + nt * 8 + g]);
            bf[nt][1] = __float_as_uint(Xs[ks * 8 + tq + 4][w * 32 + nt * 8 + g]);
        }
        #pragma unroll
        for (int mt = 0; mt < 4; mt++) {
            uint a[4];
            a[0] = __float_as_uint(Ws[ks * 8 + tq][mt * 16 + g]);
            a[1] = __float_as_uint(Ws[ks * 8 + tq][mt * 16 + g + 8]);
            a[2] = __float_as_uint(Ws[ks * 8 + tq + 4][mt * 16 + g]);
            a[3] = __float_as_uint(Ws[ks * 8 + tq + 4][mt * 16 + g + 8]);
            #pragma unroll
            for (int nt = 0; nt < 4; nt++) mma_tf32(acc[mt][nt], a, bf[nt]);
        }
    }
    #pragma unroll
    for (int mt = 0; mt < 4; mt++)
      #pragma unroll
      for (int nt = 0; nt < 4; nt++) {
        int n = n0 + w * 32 + nt * 8 + 2 * tq;
        long r0 = (long)(mt * 16 + g) * NPIX + n;
        long r1 = r0 + (long)8 * NPIX;
        *(float2*)(dst + r0) = make_float2(acc[mt][nt][0] * sc, acc[mt][nt][1] * sc);
        *(float2*)(dst + r1) = make_float2(acc[mt][nt][2] * sc, acc[mt][nt][3] * sc);
      }
}

// ---------- k softmax stats per row: (max, 1/sum(exp)) ----------
__global__ void __launch_bounds__(256) kstat_kernel() {
    __shared__ float red[256];
    int t = threadIdx.x;
    const float* p = g_k + (long)blockIdx.x * NPIX;
    float v[64]; float mx = -1e30f;
    #pragma unroll
    for (int i = 0; i < 64; i++) { v[i] = p[t + i * 256]; mx = fmaxf(mx, v[i]); }
    red[t] = mx; __syncthreads();
    for (int o = 128; o > 0; o >>= 1) { if (t < o) red[t] = fmaxf(red[t], red[t + o]); __syncthreads(); }
    mx = red[0]; __syncthreads();
    float s = 0.f;
    #pragma unroll
    for (int i = 0; i < 64; i++) s += __expf(v[i] - mx);
    red[t] = s; __syncthreads();
    for (int o = 128; o > 0; o >>= 1) { if (t < o) red[t] += red[t + o]; __syncthreads(); }
    if (t == 0) { g_kstat[blockIdx.x * 2] = mx; g_kstat[blockIdx.x * 2 + 1] = 1.f / red[0]; }
}

// ---------- ctx partial via tf32 mma, fused k-softmax ----------
__global__ void __launch_bounds__(128) ctx_kernel() {
    int ch = blockIdx.x, h = blockIdx.y, b = blockIdx.z;
    __shared__ float ksT[64][40];   // [px][d], tf32, exp-applied
    __shared__ float vs[64][72];    // [px][e], tf32
    int t = threadIdx.x;
    int w = t >> 5, lane = t & 31, g = lane >> 2, tq = lane & 3;
    int mt = w & 1, eh = w >> 1;
    const float* kbase = g_k + ((long)(b * DK + h * 32)) * NPIX + ch * 512;
    const float* vbase = g_v + ((long)(b * DV + h * 64)) * NPIX + ch * 512;
    int kd = t & 31, kpg = t >> 5;
    float kmx = g_kstat[(b * DK + h * 32 + kd) * 2];
    float kiv = g_kstat[(b * DK + h * 32 + kd) * 2 + 1];
    int ve = t & 63, vph = t >> 6;
    float acc[4][4];
    #pragma unroll
    for (int nt = 0; nt < 4; nt++)
      #pragma unroll
      for (int i = 0; i < 4; i++) acc[nt][i] = 0.f;
    for (int n0 = 0; n0 < 512; n0 += 64) {
        __syncthreads();
        #pragma unroll
        for (int i = 0; i < 4; i++) {
            float4 kk = *(const float4*)(kbase + (long)kd * NPIX + n0 + kpg * 16 + i * 4);
            int px = kpg * 16 + i * 4;
            ksT[px][kd]     = tf32f(__expf(kk.x - kmx) * kiv);
            ksT[px + 1][kd] = tf32f(__expf(kk.y - kmx) * kiv);
            ksT[px + 2][kd] = tf32f(__expf(kk.z - kmx) * kiv);
            ksT[px + 3][kd] = tf32f(__expf(kk.w - kmx) * kiv);
        }
        #pragma unroll
        for (int i = 0; i < 8; i++) {
            float4 vv = *(const float4*)(vbase + (long)ve * NPIX + n0 + vph * 32 + i * 4);
            int px = vph * 32 + i * 4;
            vs[px][ve] = tf32f(vv.x); vs[px + 1][ve] = tf32f(vv.y);
            vs[px + 2][ve] = tf32f(vv.z); vs[px + 3][ve] = tf32f(vv.w);
        }
        __syncthreads();
        #pragma unroll
        for (int sk = 0; sk < 8; sk++) {
            uint a[4];
            a[0] = __float_as_uint(ksT[sk * 8 + tq][mt * 16 + g]);
            a[1] = __float_as_uint(ksT[sk * 8 + tq][mt * 16 + g + 8]);
            a[2] = __float_as_uint(ksT[sk * 8 + tq + 4][mt * 16 + g]);
            a[3] = __float_as_uint(ksT[sk * 8 + tq + 4][mt * 16 + g + 8]);
            #pragma unroll
            for (int nt = 0; nt < 4; nt++) {
                uint bfr[2];
                bfr[0] = __float_as_uint(vs[sk * 8 + tq][eh * 32 + nt * 8 + g]);
                bfr[1] = __float_as_uint(vs[sk * 8 + tq + 4][eh * 32 + nt * 8 + g]);
                mma_tf32(acc[nt], a, bfr);
            }
        }
    }
    float* outp = g_ctxp + ((long)(b * 8 + h) * 32 + ch) * 2048;
    #pragma unroll
    for (int nt = 0; nt < 4; nt++) {
        int e = eh * 32 + nt * 8 + 2 * tq;
        int d0 = mt * 16 + g;
        outp[d0 * 64 + e] = acc[nt][0];       outp[d0 * 64 + e + 1] = acc[nt][1];
        outp[(d0 + 8) * 64 + e] = acc[nt][2]; outp[(d0 + 8) * 64 + e + 1] = acc[nt][3];
    }
}

// ---------- reduce ctx chunks, fold with ow ----------
__global__ void __launch_bounds__(256) m_kernel(const float* __restrict__ ow) {
    int h = blockIdx.x & 7, b = blockIdx.x >> 3;
    __shared__ float ctx_s[2048];
    __shared__ float ow_s[64][65];
    int t = threadIdx.x;
    const float* cp = g_ctxp + (long)(b * 8 + h) * 32 * 2048;
    #pragma unroll
    for (int i = 0; i < 8; i++) {
        int idx = t + i * 256;
        float s = 0.f;
        #pragma unroll 8
        for (int ch = 0; ch < 32; ch++) s += cp[(long)ch * 2048 + idx];
        ctx_s[idx] = s;
    }
    #pragma unroll
    for (int i = 0; i < 16; i++) {
        int idx = t + i * 256;
        int c = idx >> 6, e = idx & 63;
        ow_s[c][e] = ow[(long)c * DV + h * 64 + e];
    }
    __syncthreads();
    float* Mp = g_M + (long)(b * 8 + h) * 2048;
    #pragma unroll
    for (int i = 0; i < 8; i++) {
        int idx = t + i * 256;
        int d = idx >> 6, c = idx & 63;
        float s = 0.f;
        #pragma unroll 16
        for (int e = 0; e < 64; e++) s += ctx_s[d * 64 + e] * ow_s[c][e];
        Mp[idx] = s;
    }
}

// ---------- out projection via tf32 mma + fused q-softmax + residual ----------
__global__ void __launch_bounds__(256) outproj_kernel(
    const float* __restrict__ noise, const float* __restrict__ ob,
    const float* __restrict__ ga, float* __restrict__ nout) {
    int nt0 = blockIdx.x, b = blockIdx.y;
    __shared__ float qs[32][136];   // [d][px], softmaxed + tf32
    __shared__ float Ms[32][72];    // [d][c], tf32
    int t = threadIdx.x;
    int w = t >> 5, lane = t & 31, g = lane >> 2, tq = lane & 3;
    int mt = w & 3, nh = w >> 2;
    int n0 = nt0 * 128;
    float acc[8][4];
    #pragma unroll
    for (int nt = 0; nt < 8; nt++)
      #pragma unroll
      for (int i = 0; i < 4; i++) acc[nt][i] = 0.f;
    for (int h = 0; h < 8; h++) {
        __syncthreads();
        #pragma unroll
        for (int i = 0; i < 4; i++) { int idx = t + i * 256; int d = idx >> 5, n4 = idx & 31;
            *(float4*)&qs[d][n4 * 4] =
                *(const float4*)(g_q + ((long)(b * DK + h * 32 + d)) * NPIX + n0 + n4 * 4); }
        #pragma unroll
        for (int i = 0; i < 2; i++) { int idx = t + i * 256; int d = idx >> 4, c4 = idx & 15;
            float4 mv = *(const float4*)(g_M + ((long)(b * 8 + h)) * 2048 + d * 64 + c4 * 4);
            *(float4*)&Ms[d][c4 * 4] = make_float4(tf32f(mv.x), tf32f(mv.y), tf32f(mv.z), tf32f(mv.w)); }
        __syncthreads();
        if (t < 128) {
            float vv[32]; float mx = -1e30f;
            #pragma unroll
            for (int d = 0; d < 32; d++) { vv[d] = qs[d][t]; mx = fmaxf(mx, vv[d]); }
            float s = 0.f;
            #pragma unroll
            for (int d = 0; d < 32; d++) { vv[d] = __expf(vv[d] - mx); s += vv[d]; }
            float inv = 1.f / s;
            #pragma unroll
            for (int d = 0; d < 32; d++) qs[d][t] = tf32f(vv[d] * inv);
        }
        __syncthreads();
        #pragma unroll
        for (int sk = 0; sk < 4; sk++) {
            uint a[4];
            a[0] = __float_as_uint(Ms[sk * 8 + tq][mt * 16 + g]);
            a[1] = __float_as_uint(Ms[sk * 8 + tq][mt * 16 + g + 8]);
            a[2] = __float_as_uint(Ms[sk * 8 + tq + 4][mt * 16 + g]);
            a[3] = __float_as_uint(Ms[sk * 8 + tq + 4][mt * 16 + g + 8]);
            #pragma unroll
            for (int nt = 0; nt < 8; nt++) {
                uint bfr[2];
                bfr[0] = __float_as_uint(qs[sk * 8 + tq][nh * 64 + nt * 8 + g]);
                bfr[1] = __float_as_uint(qs[sk * 8 + tq + 4][nh * 64 + nt * 8 + g]);
                mma_tf32(acc[nt], a, bfr);
            }
        }
    }
    float gav = ga[0];
    #pragma unroll
    for (int nt = 0; nt < 8; nt++) {
        int n = n0 + nh * 64 + nt * 8 + 2 * tq;
        int c0 = mt * 16 + g, c1 = c0 + 8;
        float ob0 = ob[c0], ob1 = ob[c1];
        long off0 = ((long)(b * FC + c0)) * NPIX + n;
        long off1 = ((long)(b * FC + c1)) * NPIX + n;
        nout[off0] = noise[off0] + gav * (acc[nt][0] + ob0);
        nout[off0 + 1] = noise[off0 + 1] + gav * (acc[nt][1] + ob0);
        nout[off1] = noise[off1] + gav * (acc[nt][2] + ob1);
        nout[off1 + 1] = noise[off1 + 1] + gav * (acc[nt][3] + ob1);
    }
}

// ---------- per-pixel FF (f32x2) ----------
__global__ void __launch_bounds__(128) ff_kernel(
    const float* __restrict__ f1w, const float* __restrict__ f1b,
    const float* __restrict__ f2w, const float* __restrict__ f2b,
    const float* __restrict__ gf, float* __restrict__ xio) {
    __shared__ float f1s[128 * 64];
    __shared__ float f2s[128 * 68];
    __shared__ float b1s[128];
    __shared__ float b2s[64];
    int t = threadIdx.x;
    for (int i = t; i < 8192; i += 128) f1s[i] = f1w[i];
    for (int i = t; i < 8192; i += 128) { int c = i >> 7, j = i & 127; f2s[j * 68 + c] = f2w[i]; }
    b1s[t] = f1b[t];
    if (t < 64) b2s[t] = f2b[t];
    __syncthreads();
    long base = (long)blockIdx.y * FC * NPIX + blockIdx.x * 128 + t;
    ull xp[32], acc[32];
    #pragma unroll
    for (int c2 = 0; c2 < 32; c2++) {
        float a = xio[base + (long)(2 * c2) * NPIX];
        float bq = xio[base + (long)(2 * c2 + 1) * NPIX];
        xp[c2] = pk(a, bq); acc[c2] = 0ull;
    }
    #pragma unroll 2
    for (int j = 0; j < 128; j++) {
        ull d0 = 0ull, d1 = 0ull, d2 = 0ull, d3 = 0ull;
        const ulonglong2* w1p = (const ulonglong2*)(f1s + j * 64);
        #pragma unroll
        for (int i = 0; i < 16; i++) {
            ulonglong2 wv = w1p[i];
            if ((i & 1) == 0) { fma2(d0, wv.x, xp[2 * i]); fma2(d1, wv.y, xp[2 * i + 1]); }
            else              { fma2(d2, wv.x, xp[2 * i]); fma2(d3, wv.y, xp[2 * i + 1]); }
        }
        float2 s0 = upk(d0), s1 = upk(d1), s2 = upk(d2), s3 = upk(d3);
        float hv = b1s[j] + ((s0.x + s0.y) + (s1.x + s1.y)) + ((s2.x + s2.y) + (s3.x + s3.y));
        hv = hv > 0.f ? hv : 0.2f * hv;
        ull hb = pk(hv, hv);
        const ulonglong2* w2p = (const ulonglong2*)(f2s + j * 68);
        #pragma unroll
        for (int i = 0; i < 16; i++) {
            ulonglong2 wv = w2p[i];
            fma2(acc[2 * i], wv.x, hb); fma2(acc[2 * i + 1], wv.y, hb);
        }
    }
    float g = gf[0];
    #pragma unroll
    for (int c2 = 0; c2 < 32; c2++) {
        float2 f = upk(acc[c2]); float2 xv = upk(xp[c2]);
        xio[base + (long)(2 * c2) * NPIX] = xv.x + g * (f.x + b2s[2 * c2]);
        xio[base + (long)(2 * c2 + 1) * NPIX] = xv.y + g * (f.y + b2s[2 * c2 + 1]);
    }
}

// ---------- 3x3 conv via tf32 mma (implicit GEMM) + add + lrelu ----------
template<int CIN>
__global__ void __launch_bounds__(256) conv3_kernel(
    const float* __restrict__ in, const float* __restrict__ wt,
    const float* __restrict__ nadd, float* __restrict__ out) {
    __shared__ float ws[9 * 8 * 68];
    __shared__ float ins[8][18][20];
    int t = threadIdx.x;
    int w = t >> 5, lane = t & 31, g = lane >> 2, tq = lane & 3;
    int mt = w & 3, yh = w >> 2;
    int wb = mt * 16;
    int bx = blockIdx.x * 16, by = blockIdx.y * 16, b = blockIdx.z;
    float acc[16][4];
    #pragma unroll
    for (int j = 0; j < 16; j++)
      #pragma unroll
      for (int i = 0; i < 4; i++) acc[j][i] = 0.f;
    for (int c0 = 0; c0 < CIN; c0 += 8) {
        __syncthreads();
        {
            const float4* wsrc = (const float4*)(wt + (long)(c0 >> 3) * 9 * 544);
            float4* wdst = (float4*)ws;
            for (int i = t; i < 1224; i += 256) wdst[i] = wsrc[i];
        }
        for (int i = t; i < 2592; i += 256) {
            int ci = i / 324, r = i % 324, y = r / 18, xx = r % 18;
            int gy = by + y - 1, gx = bx + xx - 1;
            float v = 0.f;
            if (gy >= 0 && gy < 128 && gx >= 0 && gx < 128)
                v = in[((long)(b * CIN + c0 + ci)) * NPIX + gy * 128 + gx];
            ins[ci][y][xx] = tf32f(v);
        }
        __syncthreads();
        #pragma unroll
        for (int kk = 0; kk < 9; kk++) {
            int ky = kk / 3, kx = kk % 3;
            uint a[4];
            a[0] = __float_as_uint(ws[kk * 544 + tq * 68 + wb + g]);
            a[1] = __float_as_uint(ws[kk * 544 + tq * 68 + wb + g + 8]);
            a[2] = __float_as_uint(ws[kk * 544 + (tq + 4) * 68 + wb + g]);
            a[3] = __float_as_uint(ws[kk * 544 + (tq + 4) * 68 + wb + g + 8]);
            #pragma unroll
            for (int j = 0; j < 16; j++) {
                int y = (j >> 1) + yh * 8 + ky;
                int x = (j & 1) * 8 + g + kx;
                uint bfr[2];
                bfr[0] = __float_as_uint(ins[tq][y][x]);
                bfr[1] = __float_as_uint(ins[tq + 4][y][x]);
                mma_tf32(acc[j], a, bfr);
            }
        }
    }
    #pragma unroll
    for (int j = 0; j < 16; j++) {
        int y = (j >> 1) + yh * 8;
        int x = (j & 1) * 8 + 2 * tq;
        long poff = (long)(by + y) * 128 + bx + x;
        long off0 = ((long)(b * 64 + wb + g)) * NPIX + poff;
        long off1 = ((long)(b * 64 + wb + g + 8)) * NPIX + poff;
        float2 n0v = *(const float2*)(nadd + off0);
        float2 n1v = *(const float2*)(nadd + off1);
        float v0 = acc[j][0] + n0v.x, v1 = acc[j][1] + n0v.y;
        float v2 = acc[j][2] + n1v.x, v3 = acc[j][3] + n1v.y;
        v0 = v0 > 0.f ? v0 : 0.2f * v0; v1 = v1 > 0.f ? v1 : 0.2f * v1;
        v2 = v2 > 0.f ? v2 : 0.2f * v2; v3 = v3 > 0.f ? v3 : 0.2f * v3;
        *(float2*)(out + off0) = make_float2(v0, v1);
        *(float2*)(out + off1) = make_float2(v2, v3);
    }
}

// ---------- modulated 1x1 rgb conv + prev_rgb ----------
__global__ void rgb_kernel(const float* __restrict__ xin, const float* __restrict__ prev) {
    int n = blockIdx.x * 256 + threadIdx.x;
    int b = blockIdx.y;
    __shared__ float w[192];
    if (threadIdx.x < 192) w[threadIdx.x] = g_wmod[b * 192 + threadIdx.x];
    __syncthreads();
    float a0 = 0.f, a1 = 0.f, a2 = 0.f;
    for (int c = 0; c < 64; c++) {
        float xv = xin[((long)(b * 64 + c)) * NPIX + n];
        a0 += w[c] * xv; a1 += w[64 + c] * xv; a2 += w[128 + c] * xv;
    }
    g_rgbpre[((long)(b * 3 + 0)) * NPIX + n] = a0 + prev[((long)(b * 3 + 0)) * NPIX + n];
    g_rgbpre[((long)(b * 3 + 1)) * NPIX + n] = a1 + prev[((long)(b * 3 + 1)) * NPIX + n];
    g_rgbpre[((long)(b * 3 + 2)) * NPIX + n] = a2 + prev[((long)(b * 3 + 2)) * NPIX + n];
}

// ---------- normalized [1,2,1] depthwise blur, zero pad ----------
__global__ void blur_kernel(float* __restrict__ out) {
    long i = (long)blockIdx.x * 256 + threadIdx.x;
    int x = (int)(i & 255), y = (int)((i >> 8) & 255);
    long bc = i >> 16;
    const float* p = g_rgbup + bc * 65536;
    float s = 0.f;
    #pragma unroll
    for (int dy = -1; dy <= 1; dy++) {
        int yy = y + dy; if (yy < 0 || yy > 255) continue;
        float wy = (dy == 0) ? 2.f : 1.f;
        #pragma unroll
        for (int dx = -1; dx <= 1; dx++) {
            int xx = x + dx; if (xx < 0 || xx > 255) continue;
            float wx = (dx == 0) ? 2.f : 1.f;
            s += wy * wx * p[yy * 256 + xx];
        }
    }
    out[i] = s * 0.0625f;
}

extern "C" void kernel_launch(void* const* d_in, const int* in_sizes, int n_in,
                              void* d_out, int out_size) {
    const float* x      = (const float*)d_in[0];
    const float* prev   = (const float*)d_in[1];
    const float* istyle = (const float*)d_in[2];
    const float* noise1 = (const float*)d_in[3];
    const float* noise2 = (const float*)d_in[4];
    const float* c1w    = (const float*)d_in[5];
    const float* c2w    = (const float*)d_in[6];
    const float* sw     = (const float*)d_in[7];
    const float* sb     = (const float*)d_in[8];
    const float* rgbw   = (const float*)d_in[9];
    const float* qw     = (const float*)d_in[10];
    const float* kw     = (const float*)d_in[11];
    const float* vw     = (const float*)d_in[12];
    const float* ow     = (const float*)d_in[13];
    const float* ob     = (const float*)d_in[14];
    const float* ga     = (const float*)d_in[15];
    const float* f1w    = (const float*)d_in[16];
    const float* f1b    = (const float*)d_in[17];
    const float* f2w    = (const float*)d_in[18];
    const float* f2b    = (const float*)d_in[19];
    const float* gf     = (const float*)d_in[20];
    float* out = (float*)d_out;
    float* xout = out;
    float* rgbout = out + (long)BB * FC * NPIX;

    float *p_xup, *p_rgbpre, *p_rgbup, *p_n1, *p_n2, *p_xa, *p_w1t, *p_w2t;
    cudaGetSymbolAddress((void**)&p_xup, g_xup);
    cudaGetSymbolAddress((void**)&p_rgbpre, g_rgbpre);
    cudaGetSymbolAddress((void**)&p_rgbup, g_rgbup);
    cudaGetSymbolAddress((void**)&p_n1, g_n1);
    cudaGetSymbolAddress((void**)&p_n2, g_n2);
    cudaGetSymbolAddress((void**)&p_xa, g_xa);
    cudaGetSymbolAddress((void**)&p_w1t, g_w1t);
    cudaGetSymbolAddress((void**)&p_w2t, g_w2t);

    up2_kernel<<<(BB * CIN1 * NPIX) / 256, 256>>>(x, p_xup, CIN1, 64, 64);
    weff_kernel<<<128, 256>>>(c1w, c2w);
    style_kernel<<<BB, 64>>>(istyle, sw, sb, rgbw);

    for (int a = 0; a < 2; a++) {
        const float* noise = a ? noise2 : noise1;
        float* nout = a ? p_n2 : p_n1;
        proj_kernel<<<dim3(128, 16, BB), 128>>>(noise, qw + a * DK * 64, kw + a * DK * 64, vw + a * DV * 64);
        kstat_kernel<<<BB * DK, 256>>>();
        ctx_kernel<<<dim3(32, 8, BB), 128>>>();
        m_kernel<<<BB * 8, 256>>>(ow + a * 64 * DV);
        outproj_kernel<<<dim3(128, BB), 256>>>(noise, ob + a * 64, ga + a, nout);
        ff_kernel<<<dim3(128, BB), 128>>>(f1w + a * 128 * 64, f1b + a * 128,
                                          f2w + a * 64 * 128, f2b + a * 64, gf + a, nout);
    }

    conv3_kernel<CIN1><<<dim3(8, 8, BB), 256>>>(p_xup, p_w1t, p_n1, p_xa);
    conv3_kernel<FC><<<dim3(8, 8, BB), 256>>>(p_xa, p_w2t, p_n2, xout);
    rgb_kernel<<<dim3(NPIX / 256, BB), 256>>>(xout, prev);
    up2_kernel<<<(BB * 3 * 4 * NPIX) / 256, 256>>>(p_rgbpre, p_rgbup, 3, 128, 128);
    blur_kernel<<<(BB * 3 * 4 * NPIX) / 256, 256>>>(rgbout);
}

// round 14
// speedup vs baseline: 1.7672x; 1.1111x over previous
#include <cuda_runtime.h>
#include <cuda_bf16.h>

#define BB 4
#define FC 64
#define CIN1 128
#define NPIX 16384
#define DK 256
#define DV 512

typedef unsigned long long ull;
typedef unsigned int uint;

__device__ __forceinline__ ull pk(float a, float b) {
    ull r; asm("mov.b64 %0, {%1,%2};" : "=l"(r) : "f"(a), "f"(b)); return r;
}
__device__ __forceinline__ float2 upk(ull v) {
    float2 r; asm("mov.b64 {%0,%1}, %2;" : "=f"(r.x), "=f"(r.y) : "l"(v)); return r;
}
__device__ __forceinline__ void fma2(ull& d, ull a, ull b) {
    asm("fma.rn.f32x2 %0, %1, %2, %0;" : "+l"(d) : "l"(a), "l"(b));
}
__device__ __forceinline__ uint tf32r(float x) {
    uint r; asm("cvt.rna.tf32.f32 %0, %1;" : "=r"(r) : "f"(x)); return r;
}
__device__ __forceinline__ float tf32f(float x) { return __uint_as_float(tf32r(x)); }
__device__ __forceinline__ void mma_tf32(float* d, const uint* a, const uint* b) {
    asm volatile("mma.sync.aligned.m16n8k8.row.col.f32.tf32.tf32.f32 "
        "{%0,%1,%2,%3}, {%4,%5,%6,%7}, {%8,%9}, {%0,%1,%2,%3};"
        : "+f"(d[0]), "+f"(d[1]), "+f"(d[2]), "+f"(d[3])
        : "r"(a[0]), "r"(a[1]), "r"(a[2]), "r"(a[3]), "r"(b[0]), "r"(b[1]));
}

__device__ float g_xup[BB*CIN1*NPIX];
__device__ __nv_bfloat16 g_qb[BB*DK*NPIX];
__device__ __nv_bfloat16 g_kb[BB*DK*NPIX];
__device__ __nv_bfloat16 g_vb[BB*DV*NPIX];
__device__ float g_kstat[BB*DK*2];
__device__ float g_ctxp[BB*8*32*2048];
__device__ float g_M[BB*8*2048];
__device__ float g_n1[BB*FC*NPIX];
__device__ float g_n2[BB*FC*NPIX];
__device__ float g_xa[BB*FC*NPIX];
__device__ float g_w1t[(CIN1/8)*9*8*68];
__device__ float g_w2t[(FC/8)*9*8*68];
__device__ float g_wmod[BB*3*FC];
__device__ float g_rgbpre[BB*3*NPIX];
__device__ float g_rgbup[BB*3*4*NPIX];

// ---------- bilinear 2x upsample (half-pixel, edge clamp) ----------
__global__ void up2_kernel(const float* __restrict__ in, float* __restrict__ out,
                           int C, int Hin, int Win) {
    int Ho = Hin * 2, Wo = Win * 2;
    long total = (long)BB * C * Ho * Wo;
    long i = (long)blockIdx.x * blockDim.x + threadIdx.x;
    if (i >= total) return;
    int ox = (int)(i % Wo); long r = i / Wo;
    int oy = (int)(r % Ho); r /= Ho;
    int c = (int)(r % C); int b = (int)(r / C);
    float sy = oy * 0.5f - 0.25f, sx = ox * 0.5f - 0.25f;
    int y0 = (int)floorf(sy), x0 = (int)floorf(sx);
    float wy = sy - (float)y0, wx = sx - (float)x0;
    int y0c = max(y0, 0), y1c = min(y0 + 1, Hin - 1);
    int x0c = max(x0, 0), x1c = min(x0 + 1, Win - 1);
    const float* p = in + ((long)b * C + c) * Hin * Win;
    float v00 = p[y0c * Win + x0c], v01 = p[y0c * Win + x1c];
    float v10 = p[y1c * Win + x0c], v11 = p[y1c * Win + x1c];
    out[i] = (1.f - wy) * ((1.f - wx) * v00 + wx * v01) + wy * ((1.f - wx) * v10 + wx * v11);
}

// ---------- demodulated conv weights (style=ones), layout [cblk][kk][8ci][68co], tf32 ----------
__global__ void weff_kernel(const float* __restrict__ w1, const float* __restrict__ w2) {
    int co = blockIdx.x;
    const float* w; float* wo; int len;
    if (co < 64) { w = w1 + (long)co * CIN1 * 9; wo = g_w1t; len = CIN1 * 9; }
    else { co -= 64; w = w2 + (long)co * FC * 9; wo = g_w2t; len = FC * 9; }
    __shared__ float red[256];
    float s = 0.f;
    for (int i = threadIdx.x; i < len; i += 256) { float v = w[i]; s += v * v; }
    red[threadIdx.x] = s; __syncthreads();
    for (int o = 128; o > 0; o >>= 1) { if (threadIdx.x < o) red[threadIdx.x] += red[threadIdx.x + o]; __syncthreads(); }
    float sc = 2.f * rsqrtf(4.f * red[0] + 1e-8f);
    for (int i = threadIdx.x; i < len; i += 256) {
        int ci = i / 9, kk = i % 9;
        wo[(((ci >> 3) * 9 + kk) * 8 + (ci & 7)) * 68 + co] = tf32f(w[i] * sc);
    }
}

// ---------- style -> modulated 1x1 rgb weights ----------
__global__ void style_kernel(const float* __restrict__ istyle, const float* __restrict__ sw,
                             const float* __restrict__ sb, const float* __restrict__ rgbw) {
    int f = threadIdx.x, b = blockIdx.x;
    float s = sb[f];
    for (int l = 0; l < 512; l++) s += istyle[b * 512 + l] * sw[f * 512 + l];
    s += 1.f;
    for (int co = 0; co < 3; co++) g_wmod[(b * 3 + co) * 64 + f] = rgbw[co * 64 + f] * s;
}

// ---------- QKV projection GEMM via tf32 mma, bf16 outputs ----------
__global__ void __launch_bounds__(128) proj_kernel(
    const float* __restrict__ noise, const float* __restrict__ qw,
    const float* __restrict__ kw, const float* __restrict__ vw) {
    __shared__ float Ws[64][72];      // [k][m], tf32
    __shared__ float Xs[64][136];     // [k][n], tf32
    int nt0 = blockIdx.x, rt = blockIdx.y, b = blockIdx.z;
    int t = threadIdx.x, n0 = nt0 * 128;
    int w = t >> 5, lane = t & 31, g = lane >> 2, tq = lane & 3;
    const float* wsrc; __nv_bfloat16* dst; float sc;
    const float SCALE = 0.42044820762685725f; // 32^-0.25
    if (rt < 4)      { wsrc = qw + rt * 64 * 64;       dst = g_qb + ((long)b * DK + rt * 64) * NPIX;       sc = SCALE; }
    else if (rt < 8) { wsrc = kw + (rt - 4) * 64 * 64; dst = g_kb + ((long)b * DK + (rt - 4) * 64) * NPIX; sc = SCALE; }
    else             { wsrc = vw + (rt - 8) * 64 * 64; dst = g_vb + ((long)b * DV + (rt - 8) * 64) * NPIX; sc = 1.f; }
    {   // transpose-load weights, tf32 round
        int r = t >> 1, k0 = (t & 1) * 32;
        const float4* s4 = (const float4*)(wsrc + r * 64 + k0);
        #pragma unroll
        for (int i = 0; i < 8; i++) {
            float4 wv = s4[i]; int kk = k0 + i * 4;
            Ws[kk][r] = tf32f(wv.x); Ws[kk + 1][r] = tf32f(wv.y);
            Ws[kk + 2][r] = tf32f(wv.z); Ws[kk + 3][r] = tf32f(wv.w);
        }
    }
    #pragma unroll
    for (int i = 0; i < 16; i++) { int idx = t + i * 128; int c = idx >> 5, n4 = idx & 31;
      float4 xv = *(const float4*)(noise + ((long)b * FC + c) * NPIX + n0 + n4 * 4);
      *(float4*)&Xs[c][n4 * 4] = make_float4(tf32f(xv.x), tf32f(xv.y), tf32f(xv.z), tf32f(xv.w)); }
    __syncthreads();
    float acc[4][4][4];
    #pragma unroll
    for (int mt = 0; mt < 4; mt++)
      #pragma unroll
      for (int nt = 0; nt < 4; nt++)
        #pragma unroll
        for (int i = 0; i < 4; i++) acc[mt][nt][i] = 0.f;
    #pragma unroll
    for (int ks = 0; ks < 8; ks++) {
        uint bf[4][2];
        #pragma unroll
        for (int nt = 0; nt < 4; nt++) {
            bf[nt][0] = __float_as_uint(Xs[ks * 8 + tq][w * 32 + nt * 8 + g]);
            bf[nt][1] = __float_as_uint(Xs[ks * 8 + tq + 4][w * 32 + nt * 8 + g]);
        }
        #pragma unroll
        for (int mt = 0; mt < 4; mt++) {
            uint a[4];
            a[0] = __float_as_uint(Ws[ks * 8 + tq][mt * 16 + g]);
            a[1] = __float_as_uint(Ws[ks * 8 + tq][mt * 16 + g + 8]);
            a[2] = __float_as_uint(Ws[ks * 8 + tq + 4][mt * 16 + g]);
            a[3] = __float_as_uint(Ws[ks * 8 + tq + 4][mt * 16 + g + 8]);
            #pragma unroll
            for (int nt = 0; nt < 4; nt++) mma_tf32(acc[mt][nt], a, bf[nt]);
        }
    }
    #pragma unroll
    for (int mt = 0; mt < 4; mt++)
      #pragma unroll
      for (int nt = 0; nt < 4; nt++) {
        int n = n0 + w * 32 + nt * 8 + 2 * tq;
        long r0 = (long)(mt * 16 + g) * NPIX + n;
        long r1 = r0 + (long)8 * NPIX;
        *(__nv_bfloat162*)(dst + r0) = __floats2bfloat162_rn(acc[mt][nt][0] * sc, acc[mt][nt][1] * sc);
        *(__nv_bfloat162*)(dst + r1) = __floats2bfloat162_rn(acc[mt][nt][2] * sc, acc[mt][nt][3] * sc);
      }
}

// ---------- k softmax stats per row: (max, 1/sum(exp)), bf16 input ----------
__global__ void __launch_bounds__(256) kstat_kernel() {
    __shared__ float red[256];
    int t = threadIdx.x;
    const __nv_bfloat162* p = (const __nv_bfloat162*)(g_kb + (long)blockIdx.x * NPIX);
    float v[64]; float mx = -1e30f;
    #pragma unroll
    for (int i = 0; i < 32; i++) {
        float2 f = __bfloat1622float2(p[t + i * 256]);
        v[2 * i] = f.x; v[2 * i + 1] = f.y;
        mx = fmaxf(mx, fmaxf(f.x, f.y));
    }
    red[t] = mx; __syncthreads();
    for (int o = 128; o > 0; o >>= 1) { if (t < o) red[t] = fmaxf(red[t], red[t + o]); __syncthreads(); }
    mx = red[0]; __syncthreads();
    float s = 0.f;
    #pragma unroll
    for (int i = 0; i < 64; i++) s += __expf(v[i] - mx);
    red[t] = s; __syncthreads();
    for (int o = 128; o > 0; o >>= 1) { if (t < o) red[t] += red[t + o]; __syncthreads(); }
    if (t == 0) { g_kstat[blockIdx.x * 2] = mx; g_kstat[blockIdx.x * 2 + 1] = 1.f / red[0]; }
}

// ---------- ctx partial via tf32 mma, fused k-softmax, bf16 inputs ----------
__global__ void __launch_bounds__(128) ctx_kernel() {
    int ch = blockIdx.x, h = blockIdx.y, b = blockIdx.z;
    __shared__ float ksT[64][40];   // [px][d], tf32, exp-applied
    __shared__ float vs[64][72];    // [px][e], tf32
    int t = threadIdx.x;
    int w = t >> 5, lane = t & 31, g = lane >> 2, tq = lane & 3;
    int mt = w & 1, eh = w >> 1;
    const __nv_bfloat16* kbase = g_kb + ((long)(b * DK + h * 32)) * NPIX + ch * 512;
    const __nv_bfloat16* vbase = g_vb + ((long)(b * DV + h * 64)) * NPIX + ch * 512;
    int kd = t & 31, kpg = t >> 5;
    float kmx = g_kstat[(b * DK + h * 32 + kd) * 2];
    float kiv = g_kstat[(b * DK + h * 32 + kd) * 2 + 1];
    int ve = t & 63, vph = t >> 6;
    float acc[4][4];
    #pragma unroll
    for (int nt = 0; nt < 4; nt++)
      #pragma unroll
      for (int i = 0; i < 4; i++) acc[nt][i] = 0.f;
    for (int n0 = 0; n0 < 512; n0 += 64) {
        __syncthreads();
        #pragma unroll
        for (int i = 0; i < 4; i++) {
            uint2 kk2 = *(const uint2*)(kbase + (long)kd * NPIX + n0 + kpg * 16 + i * 4);
            float2 f0 = __bfloat1622float2(*reinterpret_cast<__nv_bfloat162*>(&kk2.x));
            float2 f1 = __bfloat1622float2(*reinterpret_cast<__nv_bfloat162*>(&kk2.y));
            int px = kpg * 16 + i * 4;
            ksT[px][kd]     = tf32f(__expf(f0.x - kmx) * kiv);
            ksT[px + 1][kd] = tf32f(__expf(f0.y - kmx) * kiv);
            ksT[px + 2][kd] = tf32f(__expf(f1.x - kmx) * kiv);
            ksT[px + 3][kd] = tf32f(__expf(f1.y - kmx) * kiv);
        }
        #pragma unroll
        for (int i = 0; i < 4; i++) {
            uint4 vv4 = *(const uint4*)(vbase + (long)ve * NPIX + n0 + vph * 32 + i * 8);
            float2 f0 = __bfloat1622float2(*reinterpret_cast<__nv_bfloat162*>(&vv4.x));
            float2 f1 = __bfloat1622float2(*reinterpret_cast<__nv_bfloat162*>(&vv4.y));
            float2 f2 = __bfloat1622float2(*reinterpret_cast<__nv_bfloat162*>(&vv4.z));
            float2 f3 = __bfloat1622float2(*reinterpret_cast<__nv_bfloat162*>(&vv4.w));
            int px = vph * 32 + i * 8;
            vs[px][ve] = tf32f(f0.x);     vs[px + 1][ve] = tf32f(f0.y);
            vs[px + 2][ve] = tf32f(f1.x); vs[px + 3][ve] = tf32f(f1.y);
            vs[px + 4][ve] = tf32f(f2.x); vs[px + 5][ve] = tf32f(f2.y);
            vs[px + 6][ve] = tf32f(f3.x); vs[px + 7][ve] = tf32f(f3.y);
        }
        __syncthreads();
        #pragma unroll
        for (int sk = 0; sk < 8; sk++) {
            uint a[4];
            a[0] = __float_as_uint(ksT[sk * 8 + tq][mt * 16 + g]);
            a[1] = __float_as_uint(ksT[sk * 8 + tq][mt * 16 + g + 8]);
            a[2] = __float_as_uint(ksT[sk * 8 + tq + 4][mt * 16 + g]);
            a[3] = __float_as_uint(ksT[sk * 8 + tq + 4][mt * 16 + g + 8]);
            #pragma unroll
            for (int nt = 0; nt < 4; nt++) {
                uint bfr[2];
                bfr[0] = __float_as_uint(vs[sk * 8 + tq][eh * 32 + nt * 8 + g]);
                bfr[1] = __float_as_uint(vs[sk * 8 + tq + 4][eh * 32 + nt * 8 + g]);
                mma_tf32(acc[nt], a, bfr);
            }
        }
    }
    float* outp = g_ctxp + ((long)(b * 8 + h) * 32 + ch) * 2048;
    #pragma unroll
    for (int nt = 0; nt < 4; nt++) {
        int e = eh * 32 + nt * 8 + 2 * tq;
        int d0 = mt * 16 + g;
        outp[d0 * 64 + e] = acc[nt][0];       outp[d0 * 64 + e + 1] = acc[nt][1];
        outp[(d0 + 8) * 64 + e] = acc[nt][2]; outp[(d0 + 8) * 64 + e + 1] = acc[nt][3];
    }
}

// ---------- reduce ctx chunks, fold with ow ----------
__global__ void __launch_bounds__(256) m_kernel(const float* __restrict__ ow) {
    int h = blockIdx.x & 7, b = blockIdx.x >> 3;
    __shared__ float ctx_s[2048];
    __shared__ float ow_s[64][65];
    int t = threadIdx.x;
    const float* cp = g_ctxp + (long)(b * 8 + h) * 32 * 2048;
    #pragma unroll
    for (int i = 0; i < 8; i++) {
        int idx = t + i * 256;
        float s = 0.f;
        #pragma unroll 8
        for (int ch = 0; ch < 32; ch++) s += cp[(long)ch * 2048 + idx];
        ctx_s[idx] = s;
    }
    #pragma unroll
    for (int i = 0; i < 16; i++) {
        int idx = t + i * 256;
        int c = idx >> 6, e = idx & 63;
        ow_s[c][e] = ow[(long)c * DV + h * 64 + e];
    }
    __syncthreads();
    float* Mp = g_M + (long)(b * 8 + h) * 2048;
    #pragma unroll
    for (int i = 0; i < 8; i++) {
        int idx = t + i * 256;
        int d = idx >> 6, c = idx & 63;
        float s = 0.f;
        #pragma unroll 16
        for (int e = 0; e < 64; e++) s += ctx_s[d * 64 + e] * ow_s[c][e];
        Mp[idx] = s;
    }
}

// ---------- out projection via tf32 mma + fused q-softmax + residual, bf16 q ----------
__global__ void __launch_bounds__(256) outproj_kernel(
    const float* __restrict__ noise, const float* __restrict__ ob,
    const float* __restrict__ ga, float* __restrict__ nout) {
    int nt0 = blockIdx.x, b = blockIdx.y;
    __shared__ float qs[32][136];   // [d][px], softmaxed + tf32
    __shared__ float Ms[32][72];    // [d][c], tf32
    int t = threadIdx.x;
    int w = t >> 5, lane = t & 31, g = lane >> 2, tq = lane & 3;
    int mt = w & 3, nh = w >> 2;
    int n0 = nt0 * 128;
    float acc[8][4];
    #pragma unroll
    for (int nt = 0; nt < 8; nt++)
      #pragma unroll
      for (int i = 0; i < 4; i++) acc[nt][i] = 0.f;
    for (int h = 0; h < 8; h++) {
        __syncthreads();
        #pragma unroll
        for (int i = 0; i < 4; i++) { int idx = t + i * 256; int d = idx >> 5, n4 = idx & 31;
            uint2 qq = *(const uint2*)(g_qb + ((long)(b * DK + h * 32 + d)) * NPIX + n0 + n4 * 4);
            float2 f0 = __bfloat1622float2(*reinterpret_cast<__nv_bfloat162*>(&qq.x));
            float2 f1 = __bfloat1622float2(*reinterpret_cast<__nv_bfloat162*>(&qq.y));
            *(float4*)&qs[d][n4 * 4] = make_float4(f0.x, f0.y, f1.x, f1.y); }
        #pragma unroll
        for (int i = 0; i < 2; i++) { int idx = t + i * 256; int d = idx >> 4, c4 = idx & 15;
            float4 mv = *(const float4*)(g_M + ((long)(b * 8 + h)) * 2048 + d * 64 + c4 * 4);
            *(float4*)&Ms[d][c4 * 4] = make_float4(tf32f(mv.x), tf32f(mv.y), tf32f(mv.z), tf32f(mv.w)); }
        __syncthreads();
        if (t < 128) {
            float vv[32]; float mx = -1e30f;
            #pragma unroll
            for (int d = 0; d < 32; d++) { vv[d] = qs[d][t]; mx = fmaxf(mx, vv[d]); }
            float s = 0.f;
            #pragma unroll
            for (int d = 0; d < 32; d++) { vv[d] = __expf(vv[d] - mx); s += vv[d]; }
            float inv = 1.f / s;
            #pragma unroll
            for (int d = 0; d < 32; d++) qs[d][t] = tf32f(vv[d] * inv);
        }
        __syncthreads();
        #pragma unroll
        for (int sk = 0; sk < 4; sk++) {
            uint a[4];
            a[0] = __float_as_uint(Ms[sk * 8 + tq][mt * 16 + g]);
            a[1] = __float_as_uint(Ms[sk * 8 + tq][mt * 16 + g + 8]);
            a[2] = __float_as_uint(Ms[sk * 8 + tq + 4][mt * 16 + g]);
            a[3] = __float_as_uint(Ms[sk * 8 + tq + 4][mt * 16 + g + 8]);
            #pragma unroll
            for (int nt = 0; nt < 8; nt++) {
                uint bfr[2];
                bfr[0] = __float_as_uint(qs[sk * 8 + tq][nh * 64 + nt * 8 + g]);
                bfr[1] = __float_as_uint(qs[sk * 8 + tq + 4][nh * 64 + nt * 8 + g]);
                mma_tf32(acc[nt], a, bfr);
            }
        }
    }
    float gav = ga[0];
    #pragma unroll
    for (int nt = 0; nt < 8; nt++) {
        int n = n0 + nh * 64 + nt * 8 + 2 * tq;
        int c0 = mt * 16 + g, c1 = c0 + 8;
        float ob0 = ob[c0], ob1 = ob[c1];
        long off0 = ((long)(b * FC + c0)) * NPIX + n;
        long off1 = ((long)(b * FC + c1)) * NPIX + n;
        nout[off0] = noise[off0] + gav * (acc[nt][0] + ob0);
        nout[off0 + 1] = noise[off0 + 1] + gav * (acc[nt][1] + ob0);
        nout[off1] = noise[off1] + gav * (acc[nt][2] + ob1);
        nout[off1 + 1] = noise[off1 + 1] + gav * (acc[nt][3] + ob1);
    }
}

// ---------- per-pixel FF (f32x2) ----------
__global__ void __launch_bounds__(128) ff_kernel(
    const float* __restrict__ f1w, const float* __restrict__ f1b,
    const float* __restrict__ f2w, const float* __restrict__ f2b,
    const float* __restrict__ gf, float* __restrict__ xio) {
    __shared__ float f1s[128 * 64];
    __shared__ float f2s[128 * 68];
    __shared__ float b1s[128];
    __shared__ float b2s[64];
    int t = threadIdx.x;
    for (int i = t; i < 8192; i += 128) f1s[i] = f1w[i];
    for (int i = t; i < 8192; i += 128) { int c = i >> 7, j = i & 127; f2s[j * 68 + c] = f2w[i]; }
    b1s[t] = f1b[t];
    if (t < 64) b2s[t] = f2b[t];
    __syncthreads();
    long base = (long)blockIdx.y * FC * NPIX + blockIdx.x * 128 + t;
    ull xp[32], acc[32];
    #pragma unroll
    for (int c2 = 0; c2 < 32; c2++) {
        float a = xio[base + (long)(2 * c2) * NPIX];
        float bq = xio[base + (long)(2 * c2 + 1) * NPIX];
        xp[c2] = pk(a, bq); acc[c2] = 0ull;
    }
    #pragma unroll 2
    for (int j = 0; j < 128; j++) {
        ull d0 = 0ull, d1 = 0ull, d2 = 0ull, d3 = 0ull;
        const ulonglong2* w1p = (const ulonglong2*)(f1s + j * 64);
        #pragma unroll
        for (int i = 0; i < 16; i++) {
            ulonglong2 wv = w1p[i];
            if ((i & 1) == 0) { fma2(d0, wv.x, xp[2 * i]); fma2(d1, wv.y, xp[2 * i + 1]); }
            else              { fma2(d2, wv.x, xp[2 * i]); fma2(d3, wv.y, xp[2 * i + 1]); }
        }
        float2 s0 = upk(d0), s1 = upk(d1), s2 = upk(d2), s3 = upk(d3);
        float hv = b1s[j] + ((s0.x + s0.y) + (s1.x + s1.y)) + ((s2.x + s2.y) + (s3.x + s3.y));
        hv = hv > 0.f ? hv : 0.2f * hv;
        ull hb = pk(hv, hv);
        const ulonglong2* w2p = (const ulonglong2*)(f2s + j * 68);
        #pragma unroll
        for (int i = 0; i < 16; i++) {
            ulonglong2 wv = w2p[i];
            fma2(acc[2 * i], wv.x, hb); fma2(acc[2 * i + 1], wv.y, hb);
        }
    }
    float g = gf[0];
    #pragma unroll
    for (int c2 = 0; c2 < 32; c2++) {
        float2 f = upk(acc[c2]); float2 xv = upk(xp[c2]);
        xio[base + (long)(2 * c2) * NPIX] = xv.x + g * (f.x + b2s[2 * c2]);
        xio[base + (long)(2 * c2 + 1) * NPIX] = xv.y + g * (f.y + b2s[2 * c2 + 1]);
    }
}

// ---------- 3x3 conv via tf32 mma (implicit GEMM) + add + lrelu ----------
template<int CIN>
__global__ void __launch_bounds__(256) conv3_kernel(
    const float* __restrict__ in, const float* __restrict__ wt,
    const float* __restrict__ nadd, float* __restrict__ out) {
    __shared__ float ws[9 * 8 * 68];
    __shared__ float ins[8][18][20];
    int t = threadIdx.x;
    int w = t >> 5, lane = t & 31, g = lane >> 2, tq = lane & 3;
    int mt = w & 3, yh = w >> 2;
    int wb = mt * 16;
    int bx = blockIdx.x * 16, by = blockIdx.y * 16, b = blockIdx.z;
    float acc[16][4];
    #pragma unroll
    for (int j = 0; j < 16; j++)
      #pragma unroll
      for (int i = 0; i < 4; i++) acc[j][i] = 0.f;
    for (int c0 = 0; c0 < CIN; c0 += 8) {
        __syncthreads();
        {
            const float4* wsrc = (const float4*)(wt + (long)(c0 >> 3) * 9 * 544);
            float4* wdst = (float4*)ws;
            for (int i = t; i < 1224; i += 256) wdst[i] = wsrc[i];
        }
        for (int i = t; i < 2592; i += 256) {
            int ci = i / 324, r = i % 324, y = r / 18, xx = r % 18;
            int gy = by + y - 1, gx = bx + xx - 1;
            float v = 0.f;
            if (gy >= 0 && gy < 128 && gx >= 0 && gx < 128)
                v = in[((long)(b * CIN + c0 + ci)) * NPIX + gy * 128 + gx];
            ins[ci][y][xx] = tf32f(v);
        }
        __syncthreads();
        #pragma unroll
        for (int kk = 0; kk < 9; kk++) {
            int ky = kk / 3, kx = kk % 3;
            uint a[4];
            a[0] = __float_as_uint(ws[kk * 544 + tq * 68 + wb + g]);
            a[1] = __float_as_uint(ws[kk * 544 + tq * 68 + wb + g + 8]);
            a[2] = __float_as_uint(ws[kk * 544 + (tq + 4) * 68 + wb + g]);
            a[3] = __float_as_uint(ws[kk * 544 + (tq + 4) * 68 + wb + g + 8]);
            #pragma unroll
            for (int j = 0; j < 16; j++) {
                int y = (j >> 1) + yh * 8 + ky;
                int x = (j & 1) * 8 + g + kx;
                uint bfr[2];
                bfr[0] = __float_as_uint(ins[tq][y][x]);
                bfr[1] = __float_as_uint(ins[tq + 4][y][x]);
                mma_tf32(acc[j], a, bfr);
            }
        }
    }
    #pragma unroll
    for (int j = 0; j < 16; j++) {
        int y = (j >> 1) + yh * 8;
        int x = (j & 1) * 8 + 2 * tq;
        long poff = (long)(by + y) * 128 + bx + x;
        long off0 = ((long)(b * 64 + wb + g)) * NPIX + poff;
        long off1 = ((long)(b * 64 + wb + g + 8)) * NPIX + poff;
        float2 n0v = *(const float2*)(nadd + off0);
        float2 n1v = *(const float2*)(nadd + off1);
        float v0 = acc[j][0] + n0v.x, v1 = acc[j][1] + n0v.y;
        float v2 = acc[j][2] + n1v.x, v3 = acc[j][3] + n1v.y;
        v0 = v0 > 0.f ? v0 : 0.2f * v0; v1 = v1 > 0.f ? v1 : 0.2f * v1;
        v2 = v2 > 0.f ? v2 : 0.2f * v2; v3 = v3 > 0.f ? v3 : 0.2f * v3;
        *(float2*)(out + off0) = make_float2(v0, v1);
        *(float2*)(out + off1) = make_float2(v2, v3);
    }
}

// ---------- modulated 1x1 rgb conv + prev_rgb ----------
__global__ void rgb_kernel(const float* __restrict__ xin, const float* __restrict__ prev) {
    int n = blockIdx.x * 256 + threadIdx.x;
    int b = blockIdx.y;
    __shared__ float w[192];
    if (threadIdx.x < 192) w[threadIdx.x] = g_wmod[b * 192 + threadIdx.x];
    __syncthreads();
    float a0 = 0.f, a1 = 0.f, a2 = 0.f;
    for (int c = 0; c < 64; c++) {
        float xv = xin[((long)(b * 64 + c)) * NPIX + n];
        a0 += w[c] * xv; a1 += w[64 + c] * xv; a2 += w[128 + c] * xv;
    }
    g_rgbpre[((long)(b * 3 + 0)) * NPIX + n] = a0 + prev[((long)(b * 3 + 0)) * NPIX + n];
    g_rgbpre[((long)(b * 3 + 1)) * NPIX + n] = a1 + prev[((long)(b * 3 + 1)) * NPIX + n];
    g_rgbpre[((long)(b * 3 + 2)) * NPIX + n] = a2 + prev[((long)(b * 3 + 2)) * NPIX + n];
}

// ---------- normalized [1,2,1] depthwise blur, zero pad ----------
__global__ void blur_kernel(float* __restrict__ out) {
    long i = (long)blockIdx.x * 256 + threadIdx.x;
    int x = (int)(i & 255), y = (int)((i >> 8) & 255);
    long bc = i >> 16;
    const float* p = g_rgbup + bc * 65536;
    float s = 0.f;
    #pragma unroll
    for (int dy = -1; dy <= 1; dy++) {
        int yy = y + dy; if (yy < 0 || yy > 255) continue;
        float wy = (dy == 0) ? 2.f : 1.f;
        #pragma unroll
        for (int dx = -1; dx <= 1; dx++) {
            int xx = x + dx; if (xx < 0 || xx > 255) continue;
            float wx = (dx == 0) ? 2.f : 1.f;
            s += wy * wx * p[yy * 256 + xx];
        }
    }
    out[i] = s * 0.0625f;
}

extern "C" void kernel_launch(void* const* d_in, const int* in_sizes, int n_in,
                              void* d_out, int out_size) {
    const float* x      = (const float*)d_in[0];
    const float* prev   = (const float*)d_in[1];
    const float* istyle = (const float*)d_in[2];
    const float* noise1 = (const float*)d_in[3];
    const float* noise2 = (const float*)d_in[4];
    const float* c1w    = (const float*)d_in[5];
    const float* c2w    = (const float*)d_in[6];
    const float* sw     = (const float*)d_in[7];
    const float* sb     = (const float*)d_in[8];
    const float* rgbw   = (const float*)d_in[9];
    const float* qw     = (const float*)d_in[10];
    const float* kw     = (const float*)d_in[11];
    const float* vw     = (const float*)d_in[12];
    const float* ow     = (const float*)d_in[13];
    const float* ob     = (const float*)d_in[14];
    const float* ga     = (const float*)d_in[15];
    const float* f1w    = (const float*)d_in[16];
    const float* f1b    = (const float*)d_in[17];
    const float* f2w    = (const float*)d_in[18];
    const float* f2b    = (const float*)d_in[19];
    const float* gf     = (const float*)d_in[20];
    float* out = (float*)d_out;
    float* xout = out;
    float* rgbout = out + (long)BB * FC * NPIX;

    float *p_xup, *p_rgbpre, *p_rgbup, *p_n1, *p_n2, *p_xa, *p_w1t, *p_w2t;
    cudaGetSymbolAddress((void**)&p_xup, g_xup);
    cudaGetSymbolAddress((void**)&p_rgbpre, g_rgbpre);
    cudaGetSymbolAddress((void**)&p_rgbup, g_rgbup);
    cudaGetSymbolAddress((void**)&p_n1, g_n1);
    cudaGetSymbolAddress((void**)&p_n2, g_n2);
    cudaGetSymbolAddress((void**)&p_xa, g_xa);
    cudaGetSymbolAddress((void**)&p_w1t, g_w1t);
    cudaGetSymbolAddress((void**)&p_w2t, g_w2t);

    up2_kernel<<<(BB * CIN1 * NPIX) / 256, 256>>>(x, p_xup, CIN1, 64, 64);
    weff_kernel<<<128, 256>>>(c1w, c2w);
    style_kernel<<<BB, 64>>>(istyle, sw, sb, rgbw);

    for (int a = 0; a < 2; a++) {
        const float* noise = a ? noise2 : noise1;
        float* nout = a ? p_n2 : p_n1;
        proj_kernel<<<dim3(128, 16, BB), 128>>>(noise, qw + a * DK * 64, kw + a * DK * 64, vw + a * DV * 64);
        kstat_kernel<<<BB * DK, 256>>>();
        ctx_kernel<<<dim3(32, 8, BB), 128>>>();
        m_kernel<<<BB * 8, 256>>>(ow + a * 64 * DV);
        outproj_kernel<<<dim3(128, BB), 256>>>(noise, ob + a * 64, ga + a, nout);
        ff_kernel<<<dim3(128, BB), 128>>>(f1w + a * 128 * 64, f1b + a * 128,
                                          f2w + a * 64 * 128, f2b + a * 64, gf + a, nout);
    }

    conv3_kernel<CIN1><<<dim3(8, 8, BB), 256>>>(p_xup, p_w1t, p_n1, p_xa);
    conv3_kernel<FC><<<dim3(8, 8, BB), 256>>>(p_xa, p_w2t, p_n2, xout);
    rgb_kernel<<<dim3(NPIX / 256, BB), 256>>>(xout, prev);
    up2_kernel<<<(BB * 3 * 4 * NPIX) / 256, 256>>>(p_rgbpre, p_rgbup, 3, 128, 128);
    blur_kernel<<<(BB * 3 * 4 * NPIX) / 256, 256>>>(rgbout);
}

// round 15
// speedup vs baseline: 1.9195x; 1.0862x over previous
#include <cuda_runtime.h>
#include <cuda_bf16.h>

#define BB 4
#define FC 64
#define CIN1 128
#define NPIX 16384
#define DK 256
#define DV 512

typedef unsigned long long ull;
typedef unsigned int uint;

__device__ __forceinline__ ull pk(float a, float b) {
    ull r; asm("mov.b64 %0, {%1,%2};" : "=l"(r) : "f"(a), "f"(b)); return r;
}
__device__ __forceinline__ float2 upk(ull v) {
    float2 r; asm("mov.b64 {%0,%1}, %2;" : "=f"(r.x), "=f"(r.y) : "l"(v)); return r;
}
__device__ __forceinline__ void fma2(ull& d, ull a, ull b) {
    asm("fma.rn.f32x2 %0, %1, %2, %0;" : "+l"(d) : "l"(a), "l"(b));
}
__device__ __forceinline__ uint tf32r(float x) {
    uint r; asm("cvt.rna.tf32.f32 %0, %1;" : "=r"(r) : "f"(x)); return r;
}
__device__ __forceinline__ float tf32f(float x) { return __uint_as_float(tf32r(x)); }
__device__ __forceinline__ void mma_tf32(float* d, const uint* a, const uint* b) {
    asm volatile("mma.sync.aligned.m16n8k8.row.col.f32.tf32.tf32.f32 "
        "{%0,%1,%2,%3}, {%4,%5,%6,%7}, {%8,%9}, {%0,%1,%2,%3};"
        : "+f"(d[0]), "+f"(d[1]), "+f"(d[2]), "+f"(d[3])
        : "r"(a[0]), "r"(a[1]), "r"(a[2]), "r"(a[3]), "r"(b[0]), "r"(b[1]));
}
__device__ __forceinline__ void mma_bf16(float* d, const uint* a, const uint* b) {
    asm volatile("mma.sync.aligned.m16n8k16.row.col.f32.bf16.bf16.f32 "
        "{%0,%1,%2,%3}, {%4,%5,%6,%7}, {%8,%9}, {%0,%1,%2,%3};"
        : "+f"(d[0]), "+f"(d[1]), "+f"(d[2]), "+f"(d[3])
        : "r"(a[0]), "r"(a[1]), "r"(a[2]), "r"(a[3]), "r"(b[0]), "r"(b[1]));
}

__device__ float g_xup[BB*CIN1*NPIX];
__device__ __nv_bfloat16 g_qb[BB*DK*NPIX];
__device__ __nv_bfloat16 g_kb[BB*DK*NPIX];
__device__ __nv_bfloat16 g_vb[BB*DV*NPIX];
__device__ float g_kstat[BB*DK*2];
__device__ float g_ctxp[BB*8*32*2048];
__device__ __nv_bfloat16 g_Mb[BB*8*64*32];   // [b][h][c][d] bf16
__device__ float g_n1[BB*FC*NPIX];
__device__ float g_n2[BB*FC*NPIX];
__device__ float g_xa[BB*FC*NPIX];
__device__ float g_w1t[(CIN1/8)*9*8*68];
__device__ float g_w2t[(FC/8)*9*8*68];
__device__ float g_wmod[BB*3*FC];
__device__ float g_rgbpre[BB*3*NPIX];
__device__ float g_rgbup[BB*3*4*NPIX];

// ---------- bilinear 2x upsample (half-pixel, edge clamp) ----------
__global__ void up2_kernel(const float* __restrict__ in, float* __restrict__ out,
                           int C, int Hin, int Win) {
    int Ho = Hin * 2, Wo = Win * 2;
    long total = (long)BB * C * Ho * Wo;
    long i = (long)blockIdx.x * blockDim.x + threadIdx.x;
    if (i >= total) return;
    int ox = (int)(i % Wo); long r = i / Wo;
    int oy = (int)(r % Ho); r /= Ho;
    int c = (int)(r % C); int b = (int)(r / C);
    float sy = oy * 0.5f - 0.25f, sx = ox * 0.5f - 0.25f;
    int y0 = (int)floorf(sy), x0 = (int)floorf(sx);
    float wy = sy - (float)y0, wx = sx - (float)x0;
    int y0c = max(y0, 0), y1c = min(y0 + 1, Hin - 1);
    int x0c = max(x0, 0), x1c = min(x0 + 1, Win - 1);
    const float* p = in + ((long)b * C + c) * Hin * Win;
    float v00 = p[y0c * Win + x0c], v01 = p[y0c * Win + x1c];
    float v10 = p[y1c * Win + x0c], v11 = p[y1c * Win + x1c];
    out[i] = (1.f - wy) * ((1.f - wx) * v00 + wx * v01) + wy * ((1.f - wx) * v10 + wx * v11);
}

// ---------- demodulated conv weights (style=ones), layout [cblk][kk][8ci][68co], tf32 ----------
__global__ void weff_kernel(const float* __restrict__ w1, const float* __restrict__ w2) {
    int co = blockIdx.x;
    const float* w; float* wo; int len;
    if (co < 64) { w = w1 + (long)co * CIN1 * 9; wo = g_w1t; len = CIN1 * 9; }
    else { co -= 64; w = w2 + (long)co * FC * 9; wo = g_w2t; len = FC * 9; }
    __shared__ float red[256];
    float s = 0.f;
    for (int i = threadIdx.x; i < len; i += 256) { float v = w[i]; s += v * v; }
    red[threadIdx.x] = s; __syncthreads();
    for (int o = 128; o > 0; o >>= 1) { if (threadIdx.x < o) red[threadIdx.x] += red[threadIdx.x + o]; __syncthreads(); }
    float sc = 2.f * rsqrtf(4.f * red[0] + 1e-8f);
    for (int i = threadIdx.x; i < len; i += 256) {
        int ci = i / 9, kk = i % 9;
        wo[(((ci >> 3) * 9 + kk) * 8 + (ci & 7)) * 68 + co] = tf32f(w[i] * sc);
    }
}

// ---------- style -> modulated 1x1 rgb weights ----------
__global__ void style_kernel(const float* __restrict__ istyle, const float* __restrict__ sw,
                             const float* __restrict__ sb, const float* __restrict__ rgbw) {
    int f = threadIdx.x, b = blockIdx.x;
    float s = sb[f];
    for (int l = 0; l < 512; l++) s += istyle[b * 512 + l] * sw[f * 512 + l];
    s += 1.f;
    for (int co = 0; co < 3; co++) g_wmod[(b * 3 + co) * 64 + f] = rgbw[co * 64 + f] * s;
}

// ---------- QKV projection GEMM via bf16 mma m16n8k16, bf16 outputs ----------
__global__ void __launch_bounds__(128) proj_kernel(
    const float* __restrict__ noise, const float* __restrict__ qw,
    const float* __restrict__ kw, const float* __restrict__ vw) {
    __shared__ __nv_bfloat162 Wp[64][36];    // [m][kpair], stride 36 (4g+tq banks)
    __shared__ __nv_bfloat162 Xp[32][136];   // [kpair][n], stride 136 (8tq+g banks)
    int nt0 = blockIdx.x, rt = blockIdx.y, b = blockIdx.z;
    int t = threadIdx.x, n0 = nt0 * 128;
    int w = t >> 5, lane = t & 31, g = lane >> 2, tq = lane & 3;
    const float* wsrc; __nv_bfloat16* dst; float sc;
    const float SCALE = 0.42044820762685725f; // 32^-0.25
    if (rt < 4)      { wsrc = qw + rt * 64 * 64;       dst = g_qb + ((long)b * DK + rt * 64) * NPIX;       sc = SCALE; }
    else if (rt < 8) { wsrc = kw + (rt - 4) * 64 * 64; dst = g_kb + ((long)b * DK + (rt - 4) * 64) * NPIX; sc = SCALE; }
    else             { wsrc = vw + (rt - 8) * 64 * 64; dst = g_vb + ((long)b * DV + (rt - 8) * 64) * NPIX; sc = 1.f; }
    {   // stage weights [m][k] -> bf16 pairs along k
        int r = t >> 1, k0 = (t & 1) * 32;
        const float4* s4 = (const float4*)(wsrc + r * 64 + k0);
        #pragma unroll
        for (int i = 0; i < 8; i++) {
            float4 wv = s4[i];
            Wp[r][(k0 >> 1) + 2 * i]     = __floats2bfloat162_rn(wv.x, wv.y);
            Wp[r][(k0 >> 1) + 2 * i + 1] = __floats2bfloat162_rn(wv.z, wv.w);
        }
    }
    // stage X: pair-interleave channels (k): Xp[cp][n] = {X[2cp][n], X[2cp+1][n]}
    #pragma unroll
    for (int i = 0; i < 8; i++) {
        int idx = t + i * 128;
        int cp = idx >> 5, n4 = idx & 31;
        const float* base0 = noise + ((long)b * FC + 2 * cp) * NPIX + n0 + n4 * 4;
        float4 xa = *(const float4*)(base0);
        float4 xb = *(const float4*)(base0 + NPIX);
        Xp[cp][n4 * 4 + 0] = __floats2bfloat162_rn(xa.x, xb.x);
        Xp[cp][n4 * 4 + 1] = __floats2bfloat162_rn(xa.y, xb.y);
        Xp[cp][n4 * 4 + 2] = __floats2bfloat162_rn(xa.z, xb.z);
        Xp[cp][n4 * 4 + 3] = __floats2bfloat162_rn(xa.w, xb.w);
    }
    __syncthreads();
    float acc[4][4][4];
    #pragma unroll
    for (int mt = 0; mt < 4; mt++)
      #pragma unroll
      for (int nt = 0; nt < 4; nt++)
        #pragma unroll
        for (int i = 0; i < 4; i++) acc[mt][nt][i] = 0.f;
    #pragma unroll
    for (int ks = 0; ks < 4; ks++) {     // k16 per step
        uint bf[4][2];
        #pragma unroll
        for (int nt = 0; nt < 4; nt++) {
            bf[nt][0] = *(const uint*)&Xp[ks * 8 + tq][w * 32 + nt * 8 + g];
            bf[nt][1] = *(const uint*)&Xp[ks * 8 + tq + 4][w * 32 + nt * 8 + g];
        }
        #pragma unroll
        for (int mt = 0; mt < 4; mt++) {
            uint a[4];
            a[0] = *(const uint*)&Wp[mt * 16 + g][ks * 8 + tq];
            a[1] = *(const uint*)&Wp[mt * 16 + g + 8][ks * 8 + tq];
            a[2] = *(const uint*)&Wp[mt * 16 + g][ks * 8 + tq + 4];
            a[3] = *(const uint*)&Wp[mt * 16 + g + 8][ks * 8 + tq + 4];
            #pragma unroll
            for (int nt = 0; nt < 4; nt++) mma_bf16(acc[mt][nt], a, bf[nt]);
        }
    }
    #pragma unroll
    for (int mt = 0; mt < 4; mt++)
      #pragma unroll
      for (int nt = 0; nt < 4; nt++) {
        int n = n0 + w * 32 + nt * 8 + 2 * tq;
        long r0 = (long)(mt * 16 + g) * NPIX + n;
        long r1 = r0 + (long)8 * NPIX;
        *(__nv_bfloat162*)(dst + r0) = __floats2bfloat162_rn(acc[mt][nt][0] * sc, acc[mt][nt][1] * sc);
        *(__nv_bfloat162*)(dst + r1) = __floats2bfloat162_rn(acc[mt][nt][2] * sc, acc[mt][nt][3] * sc);
      }
}

// ---------- k softmax stats per row: (max, 1/sum(exp)), bf16 input ----------
__global__ void __launch_bounds__(256) kstat_kernel() {
    __shared__ float red[256];
    int t = threadIdx.x;
    const __nv_bfloat162* p = (const __nv_bfloat162*)(g_kb + (long)blockIdx.x * NPIX);
    float v[64]; float mx = -1e30f;
    #pragma unroll
    for (int i = 0; i < 32; i++) {
        float2 f = __bfloat1622float2(p[t + i * 256]);
        v[2 * i] = f.x; v[2 * i + 1] = f.y;
        mx = fmaxf(mx, fmaxf(f.x, f.y));
    }
    red[t] = mx; __syncthreads();
    for (int o = 128; o > 0; o >>= 1) { if (t < o) red[t] = fmaxf(red[t], red[t + o]); __syncthreads(); }
    mx = red[0]; __syncthreads();
    float s = 0.f;
    #pragma unroll
    for (int i = 0; i < 64; i++) s += __expf(v[i] - mx);
    red[t] = s; __syncthreads();
    for (int o = 128; o > 0; o >>= 1) { if (t < o) red[t] += red[t + o]; __syncthreads(); }
    if (t == 0) { g_kstat[blockIdx.x * 2] = mx; g_kstat[blockIdx.x * 2 + 1] = 1.f / red[0]; }
}

// ---------- ctx partial via bf16 mma, fused k-softmax ----------
__global__ void __launch_bounds__(128) ctx_kernel() {
    int ch = blockIdx.x, h = blockIdx.y, b = blockIdx.z;
    __shared__ __nv_bfloat162 Ks2[32][37];   // [d][pxpair], stride 37
    __shared__ __nv_bfloat162 Vp[32][72];    // [pxpair][e], stride 72
    int t = threadIdx.x;
    int w = t >> 5, lane = t & 31, g = lane >> 2, tq = lane & 3;
    int mt = w & 1, eh = w >> 1;
    const __nv_bfloat16* kbase = g_kb + ((long)(b * DK + h * 32)) * NPIX + ch * 512;
    const __nv_bfloat16* vbase = g_vb + ((long)(b * DV + h * 64)) * NPIX + ch * 512;
    int kd = t & 31, kpg = t >> 5;
    float kmx = g_kstat[(b * DK + h * 32 + kd) * 2];
    float kiv = g_kstat[(b * DK + h * 32 + kd) * 2 + 1];
    int ve = t & 63, vph = t >> 6;
    float acc[4][4];
    #pragma unroll
    for (int nt = 0; nt < 4; nt++)
      #pragma unroll
      for (int i = 0; i < 4; i++) acc[nt][i] = 0.f;
    for (int n0 = 0; n0 < 512; n0 += 64) {
        __syncthreads();
        #pragma unroll
        for (int i = 0; i < 4; i++) {
            uint2 kk2 = *(const uint2*)(kbase + (long)kd * NPIX + n0 + kpg * 16 + i * 4);
            float2 f0 = __bfloat1622float2(*reinterpret_cast<__nv_bfloat162*>(&kk2.x));
            float2 f1 = __bfloat1622float2(*reinterpret_cast<__nv_bfloat162*>(&kk2.y));
            int pp = (kpg * 16 + i * 4) >> 1;
            Ks2[kd][pp]     = __floats2bfloat162_rn(__expf(f0.x - kmx) * kiv, __expf(f0.y - kmx) * kiv);
            Ks2[kd][pp + 1] = __floats2bfloat162_rn(__expf(f1.x - kmx) * kiv, __expf(f1.y - kmx) * kiv);
        }
        #pragma unroll
        for (int i = 0; i < 4; i++) {
            uint4 vv4 = *(const uint4*)(vbase + (long)ve * NPIX + n0 + vph * 32 + i * 8);
            int pp = (vph * 32 + i * 8) >> 1;
            *(uint*)&Vp[pp][ve]     = vv4.x;
            *(uint*)&Vp[pp + 1][ve] = vv4.y;
            *(uint*)&Vp[pp + 2][ve] = vv4.z;
            *(uint*)&Vp[pp + 3][ve] = vv4.w;
        }
        __syncthreads();
        #pragma unroll
        for (int ks = 0; ks < 4; ks++) {
            uint a[4];
            a[0] = *(const uint*)&Ks2[mt * 16 + g][ks * 8 + tq];
            a[1] = *(const uint*)&Ks2[mt * 16 + g + 8][ks * 8 + tq];
            a[2] = *(const uint*)&Ks2[mt * 16 + g][ks * 8 + tq + 4];
            a[3] = *(const uint*)&Ks2[mt * 16 + g + 8][ks * 8 + tq + 4];
            #pragma unroll
            for (int nt = 0; nt < 4; nt++) {
                uint bfr[2];
                bfr[0] = *(const uint*)&Vp[ks * 8 + tq][eh * 32 + nt * 8 + g];
                bfr[1] = *(const uint*)&Vp[ks * 8 + tq + 4][eh * 32 + nt * 8 + g];
                mma_bf16(acc[nt], a, bfr);
            }
        }
    }
    float* outp = g_ctxp + ((long)(b * 8 + h) * 32 + ch) * 2048;
    #pragma unroll
    for (int nt = 0; nt < 4; nt++) {
        int e = eh * 32 + nt * 8 + 2 * tq;
        int d0 = mt * 16 + g;
        outp[d0 * 64 + e] = acc[nt][0];       outp[d0 * 64 + e + 1] = acc[nt][1];
        outp[(d0 + 8) * 64 + e] = acc[nt][2]; outp[(d0 + 8) * 64 + e + 1] = acc[nt][3];
    }
}

// ---------- reduce ctx chunks, fold with ow -> bf16 M [c][d] ----------
__global__ void __launch_bounds__(256) m_kernel(const float* __restrict__ ow) {
    int h = blockIdx.x & 7, b = blockIdx.x >> 3;
    __shared__ float ctx_s[2048];
    __shared__ float ow_s[64][65];
    int t = threadIdx.x;
    const float* cp = g_ctxp + (long)(b * 8 + h) * 32 * 2048;
    #pragma unroll
    for (int i = 0; i < 8; i++) {
        int idx = t + i * 256;
        float s = 0.f;
        #pragma unroll 8
        for (int ch = 0; ch < 32; ch++) s += cp[(long)ch * 2048 + idx];
        ctx_s[idx] = s;
    }
    #pragma unroll
    for (int i = 0; i < 16; i++) {
        int idx = t + i * 256;
        int c = idx >> 6, e = idx & 63;
        ow_s[c][e] = ow[(long)c * DV + h * 64 + e];
    }
    __syncthreads();
    __nv_bfloat16* Mp = g_Mb + (long)(b * 8 + h) * 2048;
    #pragma unroll
    for (int i = 0; i < 8; i++) {
        int idx = t + i * 256;
        int d = idx >> 6, c = idx & 63;
        float s = 0.f;
        #pragma unroll 16
        for (int e = 0; e < 64; e++) s += ctx_s[d * 64 + e] * ow_s[c][e];
        Mp[c * 32 + d] = __float2bfloat16(s);
    }
}

// ---------- out projection via bf16 mma + fused q-softmax + residual ----------
__global__ void __launch_bounds__(256) outproj_kernel(
    const float* __restrict__ noise, const float* __restrict__ ob,
    const float* __restrict__ ga, float* __restrict__ nout) {
    int nt0 = blockIdx.x, b = blockIdx.y;
    __shared__ __nv_bfloat162 Qp[16][136];   // [dpair][px], stride 136
    __shared__ __nv_bfloat162 Ms2[64][20];   // [c][dpair], stride 20
    int t = threadIdx.x;
    int w = t >> 5, lane = t & 31, g = lane >> 2, tq = lane & 3;
    int mt = w & 3, nh = w >> 2;
    int n0 = nt0 * 128;
    float acc[8][4];
    #pragma unroll
    for (int nt = 0; nt < 8; nt++)
      #pragma unroll
      for (int i = 0; i < 4; i++) acc[nt][i] = 0.f;
    for (int h = 0; h < 8; h++) {
        __syncthreads();
        #pragma unroll
        for (int i = 0; i < 2; i++) {   // stage q, pair-interleaved along d
            int idx = t + i * 256;
            int dp = idx >> 5, n4 = idx & 31;
            const __nv_bfloat16* qb = g_qb + ((long)(b * DK + h * 32 + 2 * dp)) * NPIX + n0 + n4 * 4;
            uint2 qa = *(const uint2*)(qb);
            uint2 qc = *(const uint2*)(qb + NPIX);
            __nv_bfloat162 a0 = *reinterpret_cast<__nv_bfloat162*>(&qa.x);
            __nv_bfloat162 a1 = *reinterpret_cast<__nv_bfloat162*>(&qa.y);
            __nv_bfloat162 c0 = *reinterpret_cast<__nv_bfloat162*>(&qc.x);
            __nv_bfloat162 c1 = *reinterpret_cast<__nv_bfloat162*>(&qc.y);
            Qp[dp][n4 * 4 + 0] = __halves2bfloat162(a0.x, c0.x);
            Qp[dp][n4 * 4 + 1] = __halves2bfloat162(a0.y, c0.y);
            Qp[dp][n4 * 4 + 2] = __halves2bfloat162(a1.x, c1.x);
            Qp[dp][n4 * 4 + 3] = __halves2bfloat162(a1.y, c1.y);
        }
        #pragma unroll
        for (int i = 0; i < 4; i++) {   // stage M [c][dpair] (pairs native in g_Mb)
            int idx = t + i * 256;
            int c = idx >> 4, dp = idx & 15;
            *(uint*)&Ms2[c][dp] = *(const uint*)(g_Mb + (long)(b * 8 + h) * 2048 + c * 32 + 2 * dp);
        }
        __syncthreads();
        if (t < 128) {   // softmax over d=32 for pixel t
            float vv[32]; float mx = -1e30f;
            #pragma unroll
            for (int dp = 0; dp < 16; dp++) {
                float2 f = __bfloat1622float2(Qp[dp][t]);
                vv[2 * dp] = f.x; vv[2 * dp + 1] = f.y;
                mx = fmaxf(mx, fmaxf(f.x, f.y));
            }
            float s = 0.f;
            #pragma unroll
            for (int d = 0; d < 32; d++) { vv[d] = __expf(vv[d] - mx); s += vv[d]; }
            float inv = 1.f / s;
            #pragma unroll
            for (int dp = 0; dp < 16; dp++)
                Qp[dp][t] = __floats2bfloat162_rn(vv[2 * dp] * inv, vv[2 * dp + 1] * inv);
        }
        __syncthreads();
        #pragma unroll
        for (int ks = 0; ks < 2; ks++) {
            uint a[4];
            a[0] = *(const uint*)&Ms2[mt * 16 + g][ks * 8 + tq];
            a[1] = *(const uint*)&Ms2[mt * 16 + g + 8][ks * 8 + tq];
            a[2] = *(const uint*)&Ms2[mt * 16 + g][ks * 8 + tq + 4];
            a[3] = *(const uint*)&Ms2[mt * 16 + g + 8][ks * 8 + tq + 4];
            #pragma unroll
            for (int nt = 0; nt < 8; nt++) {
                uint bfr[2];
                bfr[0] = *(const uint*)&Qp[ks * 8 + tq][nh * 64 + nt * 8 + g];
                bfr[1] = *(const uint*)&Qp[ks * 8 + tq + 4][nh * 64 + nt * 8 + g];
                mma_bf16(acc[nt], a, bfr);
            }
        }
    }
    float gav = ga[0];
    #pragma unroll
    for (int nt = 0; nt < 8; nt++) {
        int n = n0 + nh * 64 + nt * 8 + 2 * tq;
        int c0 = mt * 16 + g, c1 = c0 + 8;
        float ob0 = ob[c0], ob1 = ob[c1];
        long off0 = ((long)(b * FC + c0)) * NPIX + n;
        long off1 = ((long)(b * FC + c1)) * NPIX + n;
        nout[off0] = noise[off0] + gav * (acc[nt][0] + ob0);
        nout[off0 + 1] = noise[off0 + 1] + gav * (acc[nt][1] + ob0);
        nout[off1] = noise[off1] + gav * (acc[nt][2] + ob1);
        nout[off1 + 1] = noise[off1 + 1] + gav * (acc[nt][3] + ob1);
    }
}

// ---------- per-pixel FF (f32x2) ----------
__global__ void __launch_bounds__(128) ff_kernel(
    const float* __restrict__ f1w, const float* __restrict__ f1b,
    const float* __restrict__ f2w, const float* __restrict__ f2b,
    const float* __restrict__ gf, float* __restrict__ xio) {
    __shared__ float f1s[128 * 64];
    __shared__ float f2s[128 * 68];
    __shared__ float b1s[128];
    __shared__ float b2s[64];
    int t = threadIdx.x;
    for (int i = t; i < 8192; i += 128) f1s[i] = f1w[i];
    for (int i = t; i < 8192; i += 128) { int c = i >> 7, j = i & 127; f2s[j * 68 + c] = f2w[i]; }
    b1s[t] = f1b[t];
    if (t < 64) b2s[t] = f2b[t];
    __syncthreads();
    long base = (long)blockIdx.y * FC * NPIX + blockIdx.x * 128 + t;
    ull xp[32], acc[32];
    #pragma unroll
    for (int c2 = 0; c2 < 32; c2++) {
        float a = xio[base + (long)(2 * c2) * NPIX];
        float bq = xio[base + (long)(2 * c2 + 1) * NPIX];
        xp[c2] = pk(a, bq); acc[c2] = 0ull;
    }
    #pragma unroll 2
    for (int j = 0; j < 128; j++) {
        ull d0 = 0ull, d1 = 0ull, d2 = 0ull, d3 = 0ull;
        const ulonglong2* w1p = (const ulonglong2*)(f1s + j * 64);
        #pragma unroll
        for (int i = 0; i < 16; i++) {
            ulonglong2 wv = w1p[i];
            if ((i & 1) == 0) { fma2(d0, wv.x, xp[2 * i]); fma2(d1, wv.y, xp[2 * i + 1]); }
            else              { fma2(d2, wv.x, xp[2 * i]); fma2(d3, wv.y, xp[2 * i + 1]); }
        }
        float2 s0 = upk(d0), s1 = upk(d1), s2 = upk(d2), s3 = upk(d3);
        float hv = b1s[j] + ((s0.x + s0.y) + (s1.x + s1.y)) + ((s2.x + s2.y) + (s3.x + s3.y));
        hv = hv > 0.f ? hv : 0.2f * hv;
        ull hb = pk(hv, hv);
        const ulonglong2* w2p = (const ulonglong2*)(f2s + j * 68);
        #pragma unroll
        for (int i = 0; i < 16; i++) {
            ulonglong2 wv = w2p[i];
            fma2(acc[2 * i], wv.x, hb); fma2(acc[2 * i + 1], wv.y, hb);
        }
    }
    float g = gf[0];
    #pragma unroll
    for (int c2 = 0; c2 < 32; c2++) {
        float2 f = upk(acc[c2]); float2 xv = upk(xp[c2]);
        xio[base + (long)(2 * c2) * NPIX] = xv.x + g * (f.x + b2s[2 * c2]);
        xio[base + (long)(2 * c2 + 1) * NPIX] = xv.y + g * (f.y + b2s[2 * c2 + 1]);
    }
}

// ---------- 3x3 conv via tf32 mma (implicit GEMM) + add + lrelu ----------
template<int CIN>
__global__ void __launch_bounds__(256) conv3_kernel(
    const float* __restrict__ in, const float* __restrict__ wt,
    const float* __restrict__ nadd, float* __restrict__ out) {
    __shared__ float ws[9 * 8 * 68];
    __shared__ float ins[8][18][20];
    int t = threadIdx.x;
    int w = t >> 5, lane = t & 31, g = lane >> 2, tq = lane & 3;
    int mt = w & 3, yh = w >> 2;
    int wb = mt * 16;
    int bx = blockIdx.x * 16, by = blockIdx.y * 16, b = blockIdx.z;
    float acc[16][4];
    #pragma unroll
    for (int j = 0; j < 16; j++)
      #pragma unroll
      for (int i = 0; i < 4; i++) acc[j][i] = 0.f;
    for (int c0 = 0; c0 < CIN; c0 += 8) {
        __syncthreads();
        {
            const float4* wsrc = (const float4*)(wt + (long)(c0 >> 3) * 9 * 544);
            float4* wdst = (float4*)ws;
            for (int i = t; i < 1224; i += 256) wdst[i] = wsrc[i];
        }
        for (int i = t; i < 2592; i += 256) {
            int ci = i / 324, r = i % 324, y = r / 18, xx = r % 18;
            int gy = by + y - 1, gx = bx + xx - 1;
            float v = 0.f;
            if (gy >= 0 && gy < 128 && gx >= 0 && gx < 128)
                v = in[((long)(b * CIN + c0 + ci)) * NPIX + gy * 128 + gx];
            ins[ci][y][xx] = tf32f(v);
        }
        __syncthreads();
        #pragma unroll
        for (int kk = 0; kk < 9; kk++) {
            int ky = kk / 3, kx = kk % 3;
            uint a[4];
            a[0] = __float_as_uint(ws[kk * 544 + tq * 68 + wb + g]);
            a[1] = __float_as_uint(ws[kk * 544 + tq * 68 + wb + g + 8]);
            a[2] = __float_as_uint(ws[kk * 544 + (tq + 4) * 68 + wb + g]);
            a[3] = __float_as_uint(ws[kk * 544 + (tq + 4) * 68 + wb + g + 8]);
            #pragma unroll
            for (int j = 0; j < 16; j++) {
                int y = (j >> 1) + yh * 8 + ky;
                int x = (j & 1) * 8 + g + kx;
                uint bfr[2];
                bfr[0] = __float_as_uint(ins[tq][y][x]);
                bfr[1] = __float_as_uint(ins[tq + 4][y][x]);
                mma_tf32(acc[j], a, bfr);
            }
        }
    }
    #pragma unroll
    for (int j = 0; j < 16; j++) {
        int y = (j >> 1) + yh * 8;
        int x = (j & 1) * 8 + 2 * tq;
        long poff = (long)(by + y) * 128 + bx + x;
        long off0 = ((long)(b * 64 + wb + g)) * NPIX + poff;
        long off1 = ((long)(b * 64 + wb + g + 8)) * NPIX + poff;
        float2 n0v = *(const float2*)(nadd + off0);
        float2 n1v = *(const float2*)(nadd + off1);
        float v0 = acc[j][0] + n0v.x, v1 = acc[j][1] + n0v.y;
        float v2 = acc[j][2] + n1v.x, v3 = acc[j][3] + n1v.y;
        v0 = v0 > 0.f ? v0 : 0.2f * v0; v1 = v1 > 0.f ? v1 : 0.2f * v1;
        v2 = v2 > 0.f ? v2 : 0.2f * v2; v3 = v3 > 0.f ? v3 : 0.2f * v3;
        *(float2*)(out + off0) = make_float2(v0, v1);
        *(float2*)(out + off1) = make_float2(v2, v3);
    }
}

// ---------- modulated 1x1 rgb conv + prev_rgb ----------
__global__ void rgb_kernel(const float* __restrict__ xin, const float* __restrict__ prev) {
    int n = blockIdx.x * 256 + threadIdx.x;
    int b = blockIdx.y;
    __shared__ float w[192];
    if (threadIdx.x < 192) w[threadIdx.x] = g_wmod[b * 192 + threadIdx.x];
    __syncthreads();
    float a0 = 0.f, a1 = 0.f, a2 = 0.f;
    for (int c = 0; c < 64; c++) {
        float xv = xin[((long)(b * 64 + c)) * NPIX + n];
        a0 += w[c] * xv; a1 += w[64 + c] * xv; a2 += w[128 + c] * xv;
    }
    g_rgbpre[((long)(b * 3 + 0)) * NPIX + n] = a0 + prev[((long)(b * 3 + 0)) * NPIX + n];
    g_rgbpre[((long)(b * 3 + 1)) * NPIX + n] = a1 + prev[((long)(b * 3 + 1)) * NPIX + n];
    g_rgbpre[((long)(b * 3 + 2)) * NPIX + n] = a2 + prev[((long)(b * 3 + 2)) * NPIX + n];
}

// ---------- normalized [1,2,1] depthwise blur, zero pad ----------
__global__ void blur_kernel(float* __restrict__ out) {
    long i = (long)blockIdx.x * 256 + threadIdx.x;
    int x = (int)(i & 255), y = (int)((i >> 8) & 255);
    long bc = i >> 16;
    const float* p = g_rgbup + bc * 65536;
    float s = 0.f;
    #pragma unroll
    for (int dy = -1; dy <= 1; dy++) {
        int yy = y + dy; if (yy < 0 || yy > 255) continue;
        float wy = (dy == 0) ? 2.f : 1.f;
        #pragma unroll
        for (int dx = -1; dx <= 1; dx++) {
            int xx = x + dx; if (xx < 0 || xx > 255) continue;
            float wx = (dx == 0) ? 2.f : 1.f;
            s += wy * wx * p[yy * 256 + xx];
        }
    }
    out[i] = s * 0.0625f;
}

extern "C" void kernel_launch(void* const* d_in, const int* in_sizes, int n_in,
                              void* d_out, int out_size) {
    const float* x      = (const float*)d_in[0];
    const float* prev   = (const float*)d_in[1];
    const float* istyle = (const float*)d_in[2];
    const float* noise1 = (const float*)d_in[3];
    const float* noise2 = (const float*)d_in[4];
    const float* c1w    = (const float*)d_in[5];
    const float* c2w    = (const float*)d_in[6];
    const float* sw     = (const float*)d_in[7];
    const float* sb     = (const float*)d_in[8];
    const float* rgbw   = (const float*)d_in[9];
    const float* qw     = (const float*)d_in[10];
    const float* kw     = (const float*)d_in[11];
    const float* vw     = (const float*)d_in[12];
    const float* ow     = (const float*)d_in[13];
    const float* ob     = (const float*)d_in[14];
    const float* ga     = (const float*)d_in[15];
    const float* f1w    = (const float*)d_in[16];
    const float* f1b    = (const float*)d_in[17];
    const float* f2w    = (const float*)d_in[18];
    const float* f2b    = (const float*)d_in[19];
    const float* gf     = (const float*)d_in[20];
    float* out = (float*)d_out;
    float* xout = out;
    float* rgbout = out + (long)BB * FC * NPIX;

    float *p_xup, *p_rgbpre, *p_rgbup, *p_n1, *p_n2, *p_xa, *p_w1t, *p_w2t;
    cudaGetSymbolAddress((void**)&p_xup, g_xup);
    cudaGetSymbolAddress((void**)&p_rgbpre, g_rgbpre);
    cudaGetSymbolAddress((void**)&p_rgbup, g_rgbup);
    cudaGetSymbolAddress((void**)&p_n1, g_n1);
    cudaGetSymbolAddress((void**)&p_n2, g_n2);
    cudaGetSymbolAddress((void**)&p_xa, g_xa);
    cudaGetSymbolAddress((void**)&p_w1t, g_w1t);
    cudaGetSymbolAddress((void**)&p_w2t, g_w2t);

    up2_kernel<<<(BB * CIN1 * NPIX) / 256, 256>>>(x, p_xup, CIN1, 64, 64);
    weff_kernel<<<128, 256>>>(c1w, c2w);
    style_kernel<<<BB, 64>>>(istyle, sw, sb, rgbw);

    for (int a = 0; a < 2; a++) {
        const float* noise = a ? noise2 : noise1;
        float* nout = a ? p_n2 : p_n1;
        proj_kernel<<<dim3(128, 16, BB), 128>>>(noise, qw + a * DK * 64, kw + a * DK * 64, vw + a * DV * 64);
        kstat_kernel<<<BB * DK, 256>>>();
        ctx_kernel<<<dim3(32, 8, BB), 128>>>();
        m_kernel<<<BB * 8, 256>>>(ow + a * 64 * DV);
        outproj_kernel<<<dim3(128, BB), 256>>>(noise, ob + a * 64, ga + a, nout);
        ff_kernel<<<dim3(128, BB), 128>>>(f1w + a * 128 * 64, f1b + a * 128,
                                          f2w + a * 64 * 128, f2b + a * 64, gf + a, nout);
    }

    conv3_kernel<CIN1><<<dim3(8, 8, BB), 256>>>(p_xup, p_w1t, p_n1, p_xa);
    conv3_kernel<FC><<<dim3(8, 8, BB), 256>>>(p_xa, p_w2t, p_n2, xout);
    rgb_kernel<<<dim3(NPIX / 256, BB), 256>>>(xout, prev);
    up2_kernel<<<(BB * 3 * 4 * NPIX) / 256, 256>>>(p_rgbpre, p_rgbup, 3, 128, 128);
    blur_kernel<<<(BB * 3 * 4 * NPIX) / 256, 256>>>(rgbout);
}

// round 16
// speedup vs baseline: 2.1754x; 1.1333x over previous
#include <cuda_runtime.h>
#include <cuda_bf16.h>
#include <cuda_fp16.h>

#define BB 4
#define FC 64
#define CIN1 128
#define NPIX 16384
#define DK 256
#define DV 512

typedef unsigned long long ull;
typedef unsigned int uint;

__device__ __forceinline__ ull pk(float a, float b) {
    ull r; asm("mov.b64 %0, {%1,%2};" : "=l"(r) : "f"(a), "f"(b)); return r;
}
__device__ __forceinline__ float2 upk(ull v) {
    float2 r; asm("mov.b64 {%0,%1}, %2;" : "=f"(r.x), "=f"(r.y) : "l"(v)); return r;
}
__device__ __forceinline__ void fma2(ull& d, ull a, ull b) {
    asm("fma.rn.f32x2 %0, %1, %2, %0;" : "+l"(d) : "l"(a), "l"(b));
}
__device__ __forceinline__ void mma_bf16(float* d, const uint* a, const uint* b) {
    asm volatile("mma.sync.aligned.m16n8k16.row.col.f32.bf16.bf16.f32 "
        "{%0,%1,%2,%3}, {%4,%5,%6,%7}, {%8,%9}, {%0,%1,%2,%3};"
        : "+f"(d[0]), "+f"(d[1]), "+f"(d[2]), "+f"(d[3])
        : "r"(a[0]), "r"(a[1]), "r"(a[2]), "r"(a[3]), "r"(b[0]), "r"(b[1]));
}
__device__ __forceinline__ void mma_f16(float* d, const uint* a, const uint* b) {
    asm volatile("mma.sync.aligned.m16n8k16.row.col.f32.f16.f16.f32 "
        "{%0,%1,%2,%3}, {%4,%5,%6,%7}, {%8,%9}, {%0,%1,%2,%3};"
        : "+f"(d[0]), "+f"(d[1]), "+f"(d[2]), "+f"(d[3])
        : "r"(a[0]), "r"(a[1]), "r"(a[2]), "r"(a[3]), "r"(b[0]), "r"(b[1]));
}

__device__ float g_xup[BB*CIN1*NPIX];
__device__ __nv_bfloat16 g_qb[BB*DK*NPIX];
__device__ __nv_bfloat16 g_kb[BB*DK*NPIX];
__device__ __nv_bfloat16 g_vb[BB*DV*NPIX];
__device__ float g_kstat[BB*DK*2];
__device__ float g_ctxp[BB*8*32*2048];
__device__ __nv_bfloat16 g_Mb[BB*8*64*32];   // [b][h][c][d] bf16
__device__ float g_n1[BB*FC*NPIX];
__device__ float g_n2[BB*FC*NPIX];
__device__ float g_xa[BB*FC*NPIX];
__device__ __half g_w1h[(CIN1/16)*9*64*18];  // [blk][kk][co][9 cipair x2]
__device__ __half g_w2h[(FC/16)*9*64*18];
__device__ float g_wmod[BB*3*FC];
__device__ float g_rgbpre[BB*3*NPIX];
__device__ float g_rgbup[BB*3*4*NPIX];

// ---------- bilinear 2x upsample (half-pixel, edge clamp) ----------
__global__ void up2_kernel(const float* __restrict__ in, float* __restrict__ out,
                           int C, int Hin, int Win) {
    int Ho = Hin * 2, Wo = Win * 2;
    long total = (long)BB * C * Ho * Wo;
    long i = (long)blockIdx.x * blockDim.x + threadIdx.x;
    if (i >= total) return;
    int ox = (int)(i % Wo); long r = i / Wo;
    int oy = (int)(r % Ho); r /= Ho;
    int c = (int)(r % C); int b = (int)(r / C);
    float sy = oy * 0.5f - 0.25f, sx = ox * 0.5f - 0.25f;
    int y0 = (int)floorf(sy), x0 = (int)floorf(sx);
    float wy = sy - (float)y0, wx = sx - (float)x0;
    int y0c = max(y0, 0), y1c = min(y0 + 1, Hin - 1);
    int x0c = max(x0, 0), x1c = min(x0 + 1, Win - 1);
    const float* p = in + ((long)b * C + c) * Hin * Win;
    float v00 = p[y0c * Win + x0c], v01 = p[y0c * Win + x1c];
    float v10 = p[y1c * Win + x0c], v11 = p[y1c * Win + x1c];
    out[i] = (1.f - wy) * ((1.f - wx) * v00 + wx * v01) + wy * ((1.f - wx) * v10 + wx * v11);
}

// ---------- demodulated conv weights (style=ones) -> fp16, [blk][kk][co][cipair*2] ----------
__global__ void weff_kernel(const float* __restrict__ w1, const float* __restrict__ w2) {
    int co = blockIdx.x;
    const float* w; __half* wo; int len;
    if (co < 64) { w = w1 + (long)co * CIN1 * 9; wo = g_w1h; len = CIN1 * 9; }
    else { co -= 64; w = w2 + (long)co * FC * 9; wo = g_w2h; len = FC * 9; }
    __shared__ float red[256];
    float s = 0.f;
    for (int i = threadIdx.x; i < len; i += 256) { float v = w[i]; s += v * v; }
    red[threadIdx.x] = s; __syncthreads();
    for (int o = 128; o > 0; o >>= 1) { if (threadIdx.x < o) red[threadIdx.x] += red[threadIdx.x + o]; __syncthreads(); }
    float sc = 2.f * rsqrtf(4.f * red[0] + 1e-8f);
    for (int i = threadIdx.x; i < len; i += 256) {
        int ci = i / 9, kk = i % 9;
        int blk = ci >> 4, cp = (ci & 15) >> 1, par = ci & 1;
        wo[(((long)(blk * 9 + kk) * 64 + co)) * 18 + cp * 2 + par] = __float2half(w[i] * sc);
    }
}

// ---------- style -> modulated 1x1 rgb weights ----------
__global__ void style_kernel(const float* __restrict__ istyle, const float* __restrict__ sw,
                             const float* __restrict__ sb, const float* __restrict__ rgbw) {
    int f = threadIdx.x, b = blockIdx.x;
    float s = sb[f];
    for (int l = 0; l < 512; l++) s += istyle[b * 512 + l] * sw[f * 512 + l];
    s += 1.f;
    for (int co = 0; co < 3; co++) g_wmod[(b * 3 + co) * 64 + f] = rgbw[co * 64 + f] * s;
}

// ---------- QKV projection GEMM via bf16 mma m16n8k16, bf16 outputs ----------
__global__ void __launch_bounds__(128) proj_kernel(
    const float* __restrict__ noise, const float* __restrict__ qw,
    const float* __restrict__ kw, const float* __restrict__ vw) {
    __shared__ __nv_bfloat162 Wp[64][36];
    __shared__ __nv_bfloat162 Xp[32][136];
    int nt0 = blockIdx.x, rt = blockIdx.y, b = blockIdx.z;
    int t = threadIdx.x, n0 = nt0 * 128;
    int w = t >> 5, lane = t & 31, g = lane >> 2, tq = lane & 3;
    const float* wsrc; __nv_bfloat16* dst; float sc;
    const float SCALE = 0.42044820762685725f; // 32^-0.25
    if (rt < 4)      { wsrc = qw + rt * 64 * 64;       dst = g_qb + ((long)b * DK + rt * 64) * NPIX;       sc = SCALE; }
    else if (rt < 8) { wsrc = kw + (rt - 4) * 64 * 64; dst = g_kb + ((long)b * DK + (rt - 4) * 64) * NPIX; sc = SCALE; }
    else             { wsrc = vw + (rt - 8) * 64 * 64; dst = g_vb + ((long)b * DV + (rt - 8) * 64) * NPIX; sc = 1.f; }
    {
        int r = t >> 1, k0 = (t & 1) * 32;
        const float4* s4 = (const float4*)(wsrc + r * 64 + k0);
        #pragma unroll
        for (int i = 0; i < 8; i++) {
            float4 wv = s4[i];
            Wp[r][(k0 >> 1) + 2 * i]     = __floats2bfloat162_rn(wv.x, wv.y);
            Wp[r][(k0 >> 1) + 2 * i + 1] = __floats2bfloat162_rn(wv.z, wv.w);
        }
    }
    #pragma unroll
    for (int i = 0; i < 8; i++) {
        int idx = t + i * 128;
        int cp = idx >> 5, n4 = idx & 31;
        const float* base0 = noise + ((long)b * FC + 2 * cp) * NPIX + n0 + n4 * 4;
        float4 xa = *(const float4*)(base0);
        float4 xb = *(const float4*)(base0 + NPIX);
        Xp[cp][n4 * 4 + 0] = __floats2bfloat162_rn(xa.x, xb.x);
        Xp[cp][n4 * 4 + 1] = __floats2bfloat162_rn(xa.y, xb.y);
        Xp[cp][n4 * 4 + 2] = __floats2bfloat162_rn(xa.z, xb.z);
        Xp[cp][n4 * 4 + 3] = __floats2bfloat162_rn(xa.w, xb.w);
    }
    __syncthreads();
    float acc[4][4][4];
    #pragma unroll
    for (int mt = 0; mt < 4; mt++)
      #pragma unroll
      for (int nt = 0; nt < 4; nt++)
        #pragma unroll
        for (int i = 0; i < 4; i++) acc[mt][nt][i] = 0.f;
    #pragma unroll
    for (int ks = 0; ks < 4; ks++) {
        uint bf[4][2];
        #pragma unroll
        for (int nt = 0; nt < 4; nt++) {
            bf[nt][0] = *(const uint*)&Xp[ks * 8 + tq][w * 32 + nt * 8 + g];
            bf[nt][1] = *(const uint*)&Xp[ks * 8 + tq + 4][w * 32 + nt * 8 + g];
        }
        #pragma unroll
        for (int mt = 0; mt < 4; mt++) {
            uint a[4];
            a[0] = *(const uint*)&Wp[mt * 16 + g][ks * 8 + tq];
            a[1] = *(const uint*)&Wp[mt * 16 + g + 8][ks * 8 + tq];
            a[2] = *(const uint*)&Wp[mt * 16 + g][ks * 8 + tq + 4];
            a[3] = *(const uint*)&Wp[mt * 16 + g + 8][ks * 8 + tq + 4];
            #pragma unroll
            for (int nt = 0; nt < 4; nt++) mma_bf16(acc[mt][nt], a, bf[nt]);
        }
    }
    #pragma unroll
    for (int mt = 0; mt < 4; mt++)
      #pragma unroll
      for (int nt = 0; nt < 4; nt++) {
        int n = n0 + w * 32 + nt * 8 + 2 * tq;
        long r0 = (long)(mt * 16 + g) * NPIX + n;
        long r1 = r0 + (long)8 * NPIX;
        *(__nv_bfloat162*)(dst + r0) = __floats2bfloat162_rn(acc[mt][nt][0] * sc, acc[mt][nt][1] * sc);
        *(__nv_bfloat162*)(dst + r1) = __floats2bfloat162_rn(acc[mt][nt][2] * sc, acc[mt][nt][3] * sc);
      }
}

// ---------- k softmax stats per row: (max, 1/sum(exp)), bf16 input ----------
__global__ void __launch_bounds__(256) kstat_kernel() {
    __shared__ float red[256];
    int t = threadIdx.x;
    const __nv_bfloat162* p = (const __nv_bfloat162*)(g_kb + (long)blockIdx.x * NPIX);
    float v[64]; float mx = -1e30f;
    #pragma unroll
    for (int i = 0; i < 32; i++) {
        float2 f = __bfloat1622float2(p[t + i * 256]);
        v[2 * i] = f.x; v[2 * i + 1] = f.y;
        mx = fmaxf(mx, fmaxf(f.x, f.y));
    }
    red[t] = mx; __syncthreads();
    for (int o = 128; o > 0; o >>= 1) { if (t < o) red[t] = fmaxf(red[t], red[t + o]); __syncthreads(); }
    mx = red[0]; __syncthreads();
    float s = 0.f;
    #pragma unroll
    for (int i = 0; i < 64; i++) s += __expf(v[i] - mx);
    red[t] = s; __syncthreads();
    for (int o = 128; o > 0; o >>= 1) { if (t < o) red[t] += red[t + o]; __syncthreads(); }
    if (t == 0) { g_kstat[blockIdx.x * 2] = mx; g_kstat[blockIdx.x * 2 + 1] = 1.f / red[0]; }
}

// ---------- ctx partial via bf16 mma, fused k-softmax ----------
__global__ void __launch_bounds__(128) ctx_kernel() {
    int ch = blockIdx.x, h = blockIdx.y, b = blockIdx.z;
    __shared__ __nv_bfloat162 Ks2[32][37];
    __shared__ __nv_bfloat162 Vp[32][72];
    int t = threadIdx.x;
    int w = t >> 5, lane = t & 31, g = lane >> 2, tq = lane & 3;
    int mt = w & 1, eh = w >> 1;
    const __nv_bfloat16* kbase = g_kb + ((long)(b * DK + h * 32)) * NPIX + ch * 512;
    const __nv_bfloat16* vbase = g_vb + ((long)(b * DV + h * 64)) * NPIX + ch * 512;
    int kd = t & 31, kpg = t >> 5;
    float kmx = g_kstat[(b * DK + h * 32 + kd) * 2];
    float kiv = g_kstat[(b * DK + h * 32 + kd) * 2 + 1];
    int ve = t & 63, vph = t >> 6;
    float acc[4][4];
    #pragma unroll
    for (int nt = 0; nt < 4; nt++)
      #pragma unroll
      for (int i = 0; i < 4; i++) acc[nt][i] = 0.f;
    for (int n0 = 0; n0 < 512; n0 += 64) {
        __syncthreads();
        #pragma unroll
        for (int i = 0; i < 4; i++) {
            uint2 kk2 = *(const uint2*)(kbase + (long)kd * NPIX + n0 + kpg * 16 + i * 4);
            float2 f0 = __bfloat1622float2(*reinterpret_cast<__nv_bfloat162*>(&kk2.x));
            float2 f1 = __bfloat1622float2(*reinterpret_cast<__nv_bfloat162*>(&kk2.y));
            int pp = (kpg * 16 + i * 4) >> 1;
            Ks2[kd][pp]     = __floats2bfloat162_rn(__expf(f0.x - kmx) * kiv, __expf(f0.y - kmx) * kiv);
            Ks2[kd][pp + 1] = __floats2bfloat162_rn(__expf(f1.x - kmx) * kiv, __expf(f1.y - kmx) * kiv);
        }
        #pragma unroll
        for (int i = 0; i < 4; i++) {
            uint4 vv4 = *(const uint4*)(vbase + (long)ve * NPIX + n0 + vph * 32 + i * 8);
            int pp = (vph * 32 + i * 8) >> 1;
            *(uint*)&Vp[pp][ve]     = vv4.x;
            *(uint*)&Vp[pp + 1][ve] = vv4.y;
            *(uint*)&Vp[pp + 2][ve] = vv4.z;
            *(uint*)&Vp[pp + 3][ve] = vv4.w;
        }
        __syncthreads();
        #pragma unroll
        for (int ks = 0; ks < 4; ks++) {
            uint a[4];
            a[0] = *(const uint*)&Ks2[mt * 16 + g][ks * 8 + tq];
            a[1] = *(const uint*)&Ks2[mt * 16 + g + 8][ks * 8 + tq];
            a[2] = *(const uint*)&Ks2[mt * 16 + g][ks * 8 + tq + 4];
            a[3] = *(const uint*)&Ks2[mt * 16 + g + 8][ks * 8 + tq + 4];
            #pragma unroll
            for (int nt = 0; nt < 4; nt++) {
                uint bfr[2];
                bfr[0] = *(const uint*)&Vp[ks * 8 + tq][eh * 32 + nt * 8 + g];
                bfr[1] = *(const uint*)&Vp[ks * 8 + tq + 4][eh * 32 + nt * 8 + g];
                mma_bf16(acc[nt], a, bfr);
            }
        }
    }
    float* outp = g_ctxp + ((long)(b * 8 + h) * 32 + ch) * 2048;
    #pragma unroll
    for (int nt = 0; nt < 4; nt++) {
        int e = eh * 32 + nt * 8 + 2 * tq;
        int d0 = mt * 16 + g;
        outp[d0 * 64 + e] = acc[nt][0];       outp[d0 * 64 + e + 1] = acc[nt][1];
        outp[(d0 + 8) * 64 + e] = acc[nt][2]; outp[(d0 + 8) * 64 + e + 1] = acc[nt][3];
    }
}

// ---------- reduce ctx chunks, fold with ow -> bf16 M [c][d] ----------
__global__ void __launch_bounds__(256) m_kernel(const float* __restrict__ ow) {
    int h = blockIdx.x & 7, b = blockIdx.x >> 3;
    __shared__ float ctx_s[2048];
    __shared__ float ow_s[64][65];
    int t = threadIdx.x;
    const float* cp = g_ctxp + (long)(b * 8 + h) * 32 * 2048;
    #pragma unroll
    for (int i = 0; i < 8; i++) {
        int idx = t + i * 256;
        float s = 0.f;
        #pragma unroll 8
        for (int ch = 0; ch < 32; ch++) s += cp[(long)ch * 2048 + idx];
        ctx_s[idx] = s;
    }
    #pragma unroll
    for (int i = 0; i < 16; i++) {
        int idx = t + i * 256;
        int c = idx >> 6, e = idx & 63;
        ow_s[c][e] = ow[(long)c * DV + h * 64 + e];
    }
    __syncthreads();
    __nv_bfloat16* Mp = g_Mb + (long)(b * 8 + h) * 2048;
    #pragma unroll
    for (int i = 0; i < 8; i++) {
        int idx = t + i * 256;
        int d = idx >> 6, c = idx & 63;
        float s = 0.f;
        #pragma unroll 16
        for (int e = 0; e < 64; e++) s += ctx_s[d * 64 + e] * ow_s[c][e];
        Mp[c * 32 + d] = __float2bfloat16(s);
    }
}

// ---------- out projection via bf16 mma + fused q-softmax + residual ----------
__global__ void __launch_bounds__(256) outproj_kernel(
    const float* __restrict__ noise, const float* __restrict__ ob,
    const float* __restrict__ ga, float* __restrict__ nout) {
    int nt0 = blockIdx.x, b = blockIdx.y;
    __shared__ __nv_bfloat162 Qp[16][136];
    __shared__ __nv_bfloat162 Ms2[64][20];
    int t = threadIdx.x;
    int w = t >> 5, lane = t & 31, g = lane >> 2, tq = lane & 3;
    int mt = w & 3, nh = w >> 2;
    int n0 = nt0 * 128;
    float acc[8][4];
    #pragma unroll
    for (int nt = 0; nt < 8; nt++)
      #pragma unroll
      for (int i = 0; i < 4; i++) acc[nt][i] = 0.f;
    for (int h = 0; h < 8; h++) {
        __syncthreads();
        #pragma unroll
        for (int i = 0; i < 2; i++) {
            int idx = t + i * 256;
            int dp = idx >> 5, n4 = idx & 31;
            const __nv_bfloat16* qb = g_qb + ((long)(b * DK + h * 32 + 2 * dp)) * NPIX + n0 + n4 * 4;
            uint2 qa = *(const uint2*)(qb);
            uint2 qc = *(const uint2*)(qb + NPIX);
            __nv_bfloat162 a0 = *reinterpret_cast<__nv_bfloat162*>(&qa.x);
            __nv_bfloat162 a1 = *reinterpret_cast<__nv_bfloat162*>(&qa.y);
            __nv_bfloat162 c0 = *reinterpret_cast<__nv_bfloat162*>(&qc.x);
            __nv_bfloat162 c1 = *reinterpret_cast<__nv_bfloat162*>(&qc.y);
            Qp[dp][n4 * 4 + 0] = __halves2bfloat162(a0.x, c0.x);
            Qp[dp][n4 * 4 + 1] = __halves2bfloat162(a0.y, c0.y);
            Qp[dp][n4 * 4 + 2] = __halves2bfloat162(a1.x, c1.x);
            Qp[dp][n4 * 4 + 3] = __halves2bfloat162(a1.y, c1.y);
        }
        #pragma unroll
        for (int i = 0; i < 4; i++) {
            int idx = t + i * 256;
            int c = idx >> 4, dp = idx & 15;
            *(uint*)&Ms2[c][dp] = *(const uint*)(g_Mb + (long)(b * 8 + h) * 2048 + c * 32 + 2 * dp);
        }
        __syncthreads();
        if (t < 128) {
            float vv[32]; float mx = -1e30f;
            #pragma unroll
            for (int dp = 0; dp < 16; dp++) {
                float2 f = __bfloat1622float2(Qp[dp][t]);
                vv[2 * dp] = f.x; vv[2 * dp + 1] = f.y;
                mx = fmaxf(mx, fmaxf(f.x, f.y));
            }
            float s = 0.f;
            #pragma unroll
            for (int d = 0; d < 32; d++) { vv[d] = __expf(vv[d] - mx); s += vv[d]; }
            float inv = 1.f / s;
            #pragma unroll
            for (int dp = 0; dp < 16; dp++)
                Qp[dp][t] = __floats2bfloat162_rn(vv[2 * dp] * inv, vv[2 * dp + 1] * inv);
        }
        __syncthreads();
        #pragma unroll
        for (int ks = 0; ks < 2; ks++) {
            uint a[4];
            a[0] = *(const uint*)&Ms2[mt * 16 + g][ks * 8 + tq];
            a[1] = *(const uint*)&Ms2[mt * 16 + g + 8][ks * 8 + tq];
            a[2] = *(const uint*)&Ms2[mt * 16 + g][ks * 8 + tq + 4];
            a[3] = *(const uint*)&Ms2[mt * 16 + g + 8][ks * 8 + tq + 4];
            #pragma unroll
            for (int nt = 0; nt < 8; nt++) {
                uint bfr[2];
                bfr[0] = *(const uint*)&Qp[ks * 8 + tq][nh * 64 + nt * 8 + g];
                bfr[1] = *(const uint*)&Qp[ks * 8 + tq + 4][nh * 64 + nt * 8 + g];
                mma_bf16(acc[nt], a, bfr);
            }
        }
    }
    float gav = ga[0];
    #pragma unroll
    for (int nt = 0; nt < 8; nt++) {
        int n = n0 + nh * 64 + nt * 8 + 2 * tq;
        int c0 = mt * 16 + g, c1 = c0 + 8;
        float ob0 = ob[c0], ob1 = ob[c1];
        long off0 = ((long)(b * FC + c0)) * NPIX + n;
        long off1 = ((long)(b * FC + c1)) * NPIX + n;
        nout[off0] = noise[off0] + gav * (acc[nt][0] + ob0);
        nout[off0 + 1] = noise[off0 + 1] + gav * (acc[nt][1] + ob0);
        nout[off1] = noise[off1] + gav * (acc[nt][2] + ob1);
        nout[off1 + 1] = noise[off1 + 1] + gav * (acc[nt][3] + ob1);
    }
}

// ---------- per-pixel FF (f32x2) ----------
__global__ void __launch_bounds__(128) ff_kernel(
    const float* __restrict__ f1w, const float* __restrict__ f1b,
    const float* __restrict__ f2w, const float* __restrict__ f2b,
    const float* __restrict__ gf, float* __restrict__ xio) {
    __shared__ float f1s[128 * 64];
    __shared__ float f2s[128 * 68];
    __shared__ float b1s[128];
    __shared__ float b2s[64];
    int t = threadIdx.x;
    for (int i = t; i < 8192; i += 128) f1s[i] = f1w[i];
    for (int i = t; i < 8192; i += 128) { int c = i >> 7, j = i & 127; f2s[j * 68 + c] = f2w[i]; }
    b1s[t] = f1b[t];
    if (t < 64) b2s[t] = f2b[t];
    __syncthreads();
    long base = (long)blockIdx.y * FC * NPIX + blockIdx.x * 128 + t;
    ull xp[32], acc[32];
    #pragma unroll
    for (int c2 = 0; c2 < 32; c2++) {
        float a = xio[base + (long)(2 * c2) * NPIX];
        float bq = xio[base + (long)(2 * c2 + 1) * NPIX];
        xp[c2] = pk(a, bq); acc[c2] = 0ull;
    }
    #pragma unroll 2
    for (int j = 0; j < 128; j++) {
        ull d0 = 0ull, d1 = 0ull, d2 = 0ull, d3 = 0ull;
        const ulonglong2* w1p = (const ulonglong2*)(f1s + j * 64);
        #pragma unroll
        for (int i = 0; i < 16; i++) {
            ulonglong2 wv = w1p[i];
            if ((i & 1) == 0) { fma2(d0, wv.x, xp[2 * i]); fma2(d1, wv.y, xp[2 * i + 1]); }
            else              { fma2(d2, wv.x, xp[2 * i]); fma2(d3, wv.y, xp[2 * i + 1]); }
        }
        float2 s0 = upk(d0), s1 = upk(d1), s2 = upk(d2), s3 = upk(d3);
        float hv = b1s[j] + ((s0.x + s0.y) + (s1.x + s1.y)) + ((s2.x + s2.y) + (s3.x + s3.y));
        hv = hv > 0.f ? hv : 0.2f * hv;
        ull hb = pk(hv, hv);
        const ulonglong2* w2p = (const ulonglong2*)(f2s + j * 68);
        #pragma unroll
        for (int i = 0; i < 16; i++) {
            ulonglong2 wv = w2p[i];
            fma2(acc[2 * i], wv.x, hb); fma2(acc[2 * i + 1], wv.y, hb);
        }
    }
    float g = gf[0];
    #pragma unroll
    for (int c2 = 0; c2 < 32; c2++) {
        float2 f = upk(acc[c2]); float2 xv = upk(xp[c2]);
        xio[base + (long)(2 * c2) * NPIX] = xv.x + g * (f.x + b2s[2 * c2]);
        xio[base + (long)(2 * c2 + 1) * NPIX] = xv.y + g * (f.y + b2s[2 * c2 + 1]);
    }
}

// ---------- 3x3 conv via fp16 mma m16n8k16 (implicit GEMM) + add + lrelu ----------
template<int CIN>
__global__ void __launch_bounds__(256) conv3_kernel(
    const float* __restrict__ in, const __half* __restrict__ wt,
    const float* __restrict__ nadd, float* __restrict__ out) {
    __shared__ __half2 ws2[9 * 64 * 9];      // [kk][co][9 cipair]
    __shared__ __half2 insp[8][18][20];      // [cipair][y][x] haloed
    int t = threadIdx.x;
    int w = t >> 5, lane = t & 31, g = lane >> 2, tq = lane & 3;
    int mt = w & 3, yh = w >> 2;
    int wb = mt * 16;
    int bx = blockIdx.x * 16, by = blockIdx.y * 16, b = blockIdx.z;
    float acc[16][4];
    #pragma unroll
    for (int j = 0; j < 16; j++)
      #pragma unroll
      for (int i = 0; i < 4; i++) acc[j][i] = 0.f;
    for (int c0 = 0; c0 < CIN; c0 += 16) {
        __syncthreads();
        {   // copy weight block: 9*64*9 half2 = 5184 uint = 1296 uint4
            const uint4* wsrc = (const uint4*)(wt + (long)(c0 >> 4) * 9 * 64 * 18);
            uint4* wdst = (uint4*)ws2;
            for (int i = t; i < 1296; i += 256) wdst[i] = wsrc[i];
        }
        for (int i = t; i < 2592; i += 256) {
            int cp = i / 324, r = i % 324, y = r / 18, xx = r % 18;
            int gy = by + y - 1, gx = bx + xx - 1;
            float v0 = 0.f, v1 = 0.f;
            if (gy >= 0 && gy < 128 && gx >= 0 && gx < 128) {
                const float* p = in + ((long)(b * CIN + c0 + 2 * cp)) * NPIX + gy * 128 + gx;
                v0 = p[0]; v1 = p[NPIX];
            }
            insp[cp][y][xx] = __floats2half2_rn(v0, v1);
        }
        __syncthreads();
        #pragma unroll
        for (int kk = 0; kk < 9; kk++) {
            int ky = kk / 3, kx = kk % 3;
            const __half2* wrow = ws2 + kk * 576;
            uint a[4];
            a[0] = *(const uint*)&wrow[(wb + g) * 9 + tq];
            a[1] = *(const uint*)&wrow[(wb + g + 8) * 9 + tq];
            a[2] = *(const uint*)&wrow[(wb + g) * 9 + tq + 4];
            a[3] = *(const uint*)&wrow[(wb + g + 8) * 9 + tq + 4];
            #pragma unroll
            for (int j = 0; j < 16; j++) {
                int y = (j >> 1) + yh * 8 + ky;
                int x = (j & 1) * 8 + g + kx;
                uint bfr[2];
                bfr[0] = *(const uint*)&insp[tq][y][x];
                bfr[1] = *(const uint*)&insp[tq + 4][y][x];
                mma_f16(acc[j], a, bfr);
            }
        }
    }
    #pragma unroll
    for (int j = 0; j < 16; j++) {
        int y = (j >> 1) + yh * 8;
        int x = (j & 1) * 8 + 2 * tq;
        long poff = (long)(by + y) * 128 + bx + x;
        long off0 = ((long)(b * 64 + wb + g)) * NPIX + poff;
        long off1 = ((long)(b * 64 + wb + g + 8)) * NPIX + poff;
        float2 n0v = *(const float2*)(nadd + off0);
        float2 n1v = *(const float2*)(nadd + off1);
        float v0 = acc[j][0] + n0v.x, v1 = acc[j][1] + n0v.y;
        float v2 = acc[j][2] + n1v.x, v3 = acc[j][3] + n1v.y;
        v0 = v0 > 0.f ? v0 : 0.2f * v0; v1 = v1 > 0.f ? v1 : 0.2f * v1;
        v2 = v2 > 0.f ? v2 : 0.2f * v2; v3 = v3 > 0.f ? v3 : 0.2f * v3;
        *(float2*)(out + off0) = make_float2(v0, v1);
        *(float2*)(out + off1) = make_float2(v2, v3);
    }
}

// ---------- modulated 1x1 rgb conv + prev_rgb ----------
__global__ void rgb_kernel(const float* __restrict__ xin, const float* __restrict__ prev) {
    int n = blockIdx.x * 256 + threadIdx.x;
    int b = blockIdx.y;
    __shared__ float w[192];
    if (threadIdx.x < 192) w[threadIdx.x] = g_wmod[b * 192 + threadIdx.x];
    __syncthreads();
    float a0 = 0.f, a1 = 0.f, a2 = 0.f;
    for (int c = 0; c < 64; c++) {
        float xv = xin[((long)(b * 64 + c)) * NPIX + n];
        a0 += w[c] * xv; a1 += w[64 + c] * xv; a2 += w[128 + c] * xv;
    }
    g_rgbpre[((long)(b * 3 + 0)) * NPIX + n] = a0 + prev[((long)(b * 3 + 0)) * NPIX + n];
    g_rgbpre[((long)(b * 3 + 1)) * NPIX + n] = a1 + prev[((long)(b * 3 + 1)) * NPIX + n];
    g_rgbpre[((long)(b * 3 + 2)) * NPIX + n] = a2 + prev[((long)(b * 3 + 2)) * NPIX + n];
}

// ---------- normalized [1,2,1] depthwise blur, zero pad ----------
__global__ void blur_kernel(float* __restrict__ out) {
    long i = (long)blockIdx.x * 256 + threadIdx.x;
    int x = (int)(i & 255), y = (int)((i >> 8) & 255);
    long bc = i >> 16;
    const float* p = g_rgbup + bc * 65536;
    float s = 0.f;
    #pragma unroll
    for (int dy = -1; dy <= 1; dy++) {
        int yy = y + dy; if (yy < 0 || yy > 255) continue;
        float wy = (dy == 0) ? 2.f : 1.f;
        #pragma unroll
        for (int dx = -1; dx <= 1; dx++) {
            int xx = x + dx; if (xx < 0 || xx > 255) continue;
            float wx = (dx == 0) ? 2.f : 1.f;
            s += wy * wx * p[yy * 256 + xx];
        }
    }
    out[i] = s * 0.0625f;
}

extern "C" void kernel_launch(void* const* d_in, const int* in_sizes, int n_in,
                              void* d_out, int out_size) {
    const float* x      = (const float*)d_in[0];
    const float* prev   = (const float*)d_in[1];
    const float* istyle = (const float*)d_in[2];
    const float* noise1 = (const float*)d_in[3];
    const float* noise2 = (const float*)d_in[4];
    const float* c1w    = (const float*)d_in[5];
    const float* c2w    = (const float*)d_in[6];
    const float* sw     = (const float*)d_in[7];
    const float* sb     = (const float*)d_in[8];
    const float* rgbw   = (const float*)d_in[9];
    const float* qw     = (const float*)d_in[10];
    const float* kw     = (const float*)d_in[11];
    const float* vw     = (const float*)d_in[12];
    const float* ow     = (const float*)d_in[13];
    const float* ob     = (const float*)d_in[14];
    const float* ga     = (const float*)d_in[15];
    const float* f1w    = (const float*)d_in[16];
    const float* f1b    = (const float*)d_in[17];
    const float* f2w    = (const float*)d_in[18];
    const float* f2b    = (const float*)d_in[19];
    const float* gf     = (const float*)d_in[20];
    float* out = (float*)d_out;
    float* xout = out;
    float* rgbout = out + (long)BB * FC * NPIX;

    float *p_xup, *p_rgbpre, *p_rgbup, *p_n1, *p_n2, *p_xa;
    __half *p_w1h, *p_w2h;
    cudaGetSymbolAddress((void**)&p_xup, g_xup);
    cudaGetSymbolAddress((void**)&p_rgbpre, g_rgbpre);
    cudaGetSymbolAddress((void**)&p_rgbup, g_rgbup);
    cudaGetSymbolAddress((void**)&p_n1, g_n1);
    cudaGetSymbolAddress((void**)&p_n2, g_n2);
    cudaGetSymbolAddress((void**)&p_xa, g_xa);
    cudaGetSymbolAddress((void**)&p_w1h, g_w1h);
    cudaGetSymbolAddress((void**)&p_w2h, g_w2h);

    // zero pad lanes (cp==8) of fp16 weight buffers, then fill
    cudaMemsetAsync(p_w1h, 0, sizeof(__half) * (CIN1/16)*9*64*18);
    cudaMemsetAsync(p_w2h, 0, sizeof(__half) * (FC/16)*9*64*18);

    up2_kernel<<<(BB * CIN1 * NPIX) / 256, 256>>>(x, p_xup, CIN1, 64, 64);
    weff_kernel<<<128, 256>>>(c1w, c2w);
    style_kernel<<<BB, 64>>>(istyle, sw, sb, rgbw);

    for (int a = 0; a < 2; a++) {
        const float* noise = a ? noise2 : noise1;
        float* nout = a ? p_n2 : p_n1;
        proj_kernel<<<dim3(128, 16, BB), 128>>>(noise, qw + a * DK * 64, kw + a * DK * 64, vw + a * DV * 64);
        kstat_kernel<<<BB * DK, 256>>>();
        ctx_kernel<<<dim3(32, 8, BB), 128>>>();
        m_kernel<<<BB * 8, 256>>>(ow + a * 64 * DV);
        outproj_kernel<<<dim3(128, BB), 256>>>(noise, ob + a * 64, ga + a, nout);
        ff_kernel<<<dim3(128, BB), 128>>>(f1w + a * 128 * 64, f1b + a * 128,
                                          f2w + a * 64 * 128, f2b + a * 64, gf + a, nout);
    }

    conv3_kernel<CIN1><<<dim3(8, 8, BB), 256>>>(p_xup, p_w1h, p_n1, p_xa);
    conv3_kernel<FC><<<dim3(8, 8, BB), 256>>>(p_xa, p_w2h, p_n2, xout);
    rgb_kernel<<<dim3(NPIX / 256, BB), 256>>>(xout, prev);
    up2_kernel<<<(BB * 3 * 4 * NPIX) / 256, 256>>>(p_rgbpre, p_rgbup, 3, 128, 128);
    blur_kernel<<<(BB * 3 * 4 * NPIX) / 256, 256>>>(rgbout);
}